// round 10
// baseline (speedup 1.0000x reference)
#include <cuda_runtime.h>
#include <cuda_bf16.h>
#include <math.h>
#include <stdint.h>

#define B_    4
#define T_    2048
#define H_    16
#define D_    128
#define ATTN_ 2048
#define BT_   (B_*T_)

// ---------------------------------------------------------------------------
// Scratch (__device__ globals).
// int8 two-plane quantized operands + per-row scales for the projections;
// bf16 hi/lo Q,K,V for flash; fp32 y between flash and out-projection.
// Weight concat slots: 0=wq 1=wk 2=wv 3=wo.
// ---------------------------------------------------------------------------
__device__ int8_t g_xqh[(size_t)BT_ * ATTN_];
__device__ int8_t g_xql[(size_t)BT_ * ATTN_];
__device__ int8_t g_wqh[(size_t)4 * ATTN_ * ATTN_];
__device__ int8_t g_wql[(size_t)4 * ATTN_ * ATTN_];
__device__ int8_t g_yqh[(size_t)BT_ * ATTN_];
__device__ int8_t g_yql[(size_t)BT_ * ATTN_];
__device__ float  g_sx[BT_];
__device__ float  g_sw[4 * ATTN_];
__device__ float  g_sy[BT_];
__device__ float  g_y[(size_t)BT_ * ATTN_];
__device__ __nv_bfloat16 g_qh[(size_t)BT_ * ATTN_];
__device__ __nv_bfloat16 g_ql[(size_t)BT_ * ATTN_];
__device__ __nv_bfloat16 g_kh[(size_t)BT_ * ATTN_];
__device__ __nv_bfloat16 g_kl[(size_t)BT_ * ATTN_];
__device__ __nv_bfloat16 g_vh[(size_t)BT_ * ATTN_];
__device__ __nv_bfloat16 g_vl[(size_t)BT_ * ATTN_];
__device__ float g_cosT[T_ * 64];
__device__ float g_sinT[T_ * 64];

// ---------------------------------------------------------------------------
// PTX helpers
// ---------------------------------------------------------------------------
__device__ __forceinline__ uint32_t smem_u32(const void* p) {
    uint32_t a;
    asm("{ .reg .u64 t; cvta.to.shared.u64 t, %1; cvt.u32.u64 %0, t; }" : "=r"(a) : "l"(p));
    return a;
}

#define CP_ASYNC16(dst, src) \
    asm volatile("cp.async.cg.shared.global [%0], [%1], 16;" :: "r"(dst), "l"(src))
#define CP_COMMIT() asm volatile("cp.async.commit_group;" ::: "memory")
#define CP_WAIT(n)  asm volatile("cp.async.wait_group %0;" :: "n"(n) : "memory")

__device__ __forceinline__ void ldsm4(uint32_t* r, uint32_t addr) {
    asm volatile("ldmatrix.sync.aligned.m8n8.x4.shared.b16 {%0,%1,%2,%3}, [%4];"
                 : "=r"(r[0]), "=r"(r[1]), "=r"(r[2]), "=r"(r[3]) : "r"(addr));
}
__device__ __forceinline__ void ldsm4t(uint32_t* r, uint32_t addr) {
    asm volatile("ldmatrix.sync.aligned.m8n8.x4.trans.shared.b16 {%0,%1,%2,%3}, [%4];"
                 : "=r"(r[0]), "=r"(r[1]), "=r"(r[2]), "=r"(r[3]) : "r"(addr));
}

__device__ __forceinline__ void mma16816(float* c, const uint32_t* a,
                                         uint32_t b0, uint32_t b1) {
    asm volatile(
        "mma.sync.aligned.m16n8k16.row.col.f32.bf16.bf16.f32 "
        "{%0,%1,%2,%3}, {%4,%5,%6,%7}, {%8,%9}, {%0,%1,%2,%3};"
        : "+f"(c[0]), "+f"(c[1]), "+f"(c[2]), "+f"(c[3])
        : "r"(a[0]), "r"(a[1]), "r"(a[2]), "r"(a[3]), "r"(b0), "r"(b1));
}

__device__ __forceinline__ void mmai8(int* c, const uint32_t* a,
                                      uint32_t b0, uint32_t b1) {
    asm volatile(
        "mma.sync.aligned.m16n8k32.row.col.s32.s8.s8.s32 "
        "{%0,%1,%2,%3}, {%4,%5,%6,%7}, {%8,%9}, {%0,%1,%2,%3};"
        : "+r"(c[0]), "+r"(c[1]), "+r"(c[2]), "+r"(c[3])
        : "r"(a[0]), "r"(a[1]), "r"(a[2]), "r"(a[3]), "r"(b0), "r"(b1));
}

__device__ __forceinline__ uint32_t packbf2(float a, float b) {
    __nv_bfloat162 t = __halves2bfloat162(__float2bfloat16(a), __float2bfloat16(b));
    return *(uint32_t*)&t;
}

// ---------------------------------------------------------------------------
// RoPE table
// ---------------------------------------------------------------------------
__global__ void rope_table_kernel(float* __restrict__ cosT, float* __restrict__ sinT) {
    const int t = blockIdx.x;
    const int i = threadIdx.x;
    const float kFreq = 0.07195578415606394f;  // ln(10000)/128
    const float inv = expf((float)(2 * i) * -kFreq);
    const float ang = (float)t * inv;
    float s, c;
    sincosf(ang, &s, &c);
    cosT[t * 64 + i] = c;
    sinT[t * 64 + i] = s;
}

// ---------------------------------------------------------------------------
// Row quantizer: one block per 2048-wide row. v = s*(hi*128 + lo), lo in [-64,63].
// s = rowmax/16256 so hi fits in [-127,127].
// ---------------------------------------------------------------------------
__device__ __forceinline__ void quant_row_body(
    const float* __restrict__ srcRow, int8_t* __restrict__ qh,
    int8_t* __restrict__ ql, float* __restrict__ scales, int outRow)
{
    const int tid = threadIdx.x;
    const float4* s4 = (const float4*)srcRow;
    const float4 v0 = s4[tid];
    const float4 v1 = s4[tid + 256];
    float mx = fmaxf(fmaxf(fabsf(v0.x), fabsf(v0.y)), fmaxf(fabsf(v0.z), fabsf(v0.w)));
    mx = fmaxf(mx, fmaxf(fmaxf(fabsf(v1.x), fabsf(v1.y)), fmaxf(fabsf(v1.z), fabsf(v1.w))));
#pragma unroll
    for (int o = 16; o; o >>= 1) mx = fmaxf(mx, __shfl_xor_sync(0xffffffffu, mx, o));
    __shared__ float red[8];
    __shared__ float sInv;
    if ((tid & 31) == 0) red[tid >> 5] = mx;
    __syncthreads();
    if (tid == 0) {
        float m = red[0];
#pragma unroll
        for (int i = 1; i < 8; i++) m = fmaxf(m, red[i]);
        scales[outRow] = m * (1.f / 16256.f);
        sInv = (m > 0.f) ? (16256.f / m) : 0.f;
    }
    __syncthreads();
    const float inv = sInv;
    char4* qh4 = (char4*)(qh + (size_t)outRow * ATTN_);
    char4* ql4 = (char4*)(ql + (size_t)outRow * ATTN_);

    {
        const int q0 = __float2int_rn(v0.x * inv), q1 = __float2int_rn(v0.y * inv);
        const int q2 = __float2int_rn(v0.z * inv), q3 = __float2int_rn(v0.w * inv);
        const int h0 = (q0 + 64) >> 7, h1 = (q1 + 64) >> 7;
        const int h2 = (q2 + 64) >> 7, h3 = (q3 + 64) >> 7;
        qh4[tid] = make_char4((char)h0, (char)h1, (char)h2, (char)h3);
        ql4[tid] = make_char4((char)(q0 - (h0 << 7)), (char)(q1 - (h1 << 7)),
                              (char)(q2 - (h2 << 7)), (char)(q3 - (h3 << 7)));
    }
    {
        const int q0 = __float2int_rn(v1.x * inv), q1 = __float2int_rn(v1.y * inv);
        const int q2 = __float2int_rn(v1.z * inv), q3 = __float2int_rn(v1.w * inv);
        const int h0 = (q0 + 64) >> 7, h1 = (q1 + 64) >> 7;
        const int h2 = (q2 + 64) >> 7, h3 = (q3 + 64) >> 7;
        qh4[tid + 256] = make_char4((char)h0, (char)h1, (char)h2, (char)h3);
        ql4[tid + 256] = make_char4((char)(q0 - (h0 << 7)), (char)(q1 - (h1 << 7)),
                                    (char)(q2 - (h2 << 7)), (char)(q3 - (h3 << 7)));
    }
}

__global__ void quant_kernel(const float* __restrict__ src, int8_t* __restrict__ qh,
                             int8_t* __restrict__ ql, float* __restrict__ scales) {
    const int row = blockIdx.x;
    quant_row_body(src + (size_t)row * ATTN_, qh, ql, scales, row);
}

__global__ void quant_w_kernel(const float* __restrict__ w0, const float* __restrict__ w1,
                               const float* __restrict__ w2, const float* __restrict__ w3,
                               int8_t* __restrict__ qh, int8_t* __restrict__ ql,
                               float* __restrict__ scales) {
    const int z = blockIdx.z;
    const float* src = (z == 0) ? w0 : (z == 1) ? w1 : (z == 2) ? w2 : w3;
    const int outRow = z * ATTN_ + blockIdx.x;
    quant_row_body(src + (size_t)blockIdx.x * ATTN_, qh, ql, scales, outRow);
}

// ---------------------------------------------------------------------------
// int8 two-plane GEMM core. CTA 128x128, BK=64 int8, 8 warps (2Mx4N, 64x32),
// 2-stage cp.async. smem pitch 80 B/row (64 data + 16 pad, conflict-free).
// acc_hh = hi*hi; acc_mid = hi*lo + lo*hi (weight 128). ll dropped (zero-mean).
// ---------------------------------------------------------------------------
static constexpr int GBM = 128, GBN = 128, GBK = 64;
static constexpr int LDSE = 40;                 // pitch in b16 units = 80 bytes
static constexpr int ARRB = 128 * 80;           // 10240 B per array
static constexpr int STB  = 4 * ARRB;           // 40960 B per stage
static constexpr int GSMEM = 2 * STB;           // 81920 B
static constexpr int GTH = 256;

struct GemmCoreI8 {
    __device__ static __forceinline__ void run(
        uint32_t sBase, int (&acch)[4][4][4], int (&accm)[4][4][4],
        const int8_t* gAh, const int8_t* gAl,
        const int8_t* gWh, const int8_t* gWl,
        int tid, int wm, int wn, int lr, int lc)
    {
        const int cc = tid & 3;        // 16B chunk within 64B row
        const int rb = tid >> 2;       // 0..63
        const int NIT = ATTN_ / GBK;   // 32

        auto load_stage = [&](uint32_t st, int k0) {
#pragma unroll
            for (int bb = 0; bb < 2; bb++) {
                const int r = bb * 64 + rb;
                const uint32_t so = r * 80 + cc * 16;
                const size_t go = (size_t)r * ATTN_ + k0 + cc * 16;
                CP_ASYNC16(st + so,            gAh + go);
                CP_ASYNC16(st + ARRB + so,     gAl + go);
                CP_ASYNC16(st + 2 * ARRB + so, gWh + go);
                CP_ASYNC16(st + 3 * ARRB + so, gWl + go);
            }
            CP_COMMIT();
        };

        load_stage(sBase, 0);

        for (int kt = 0; kt < NIT; kt++) {
            if (kt + 1 < NIT) {
                load_stage(sBase + ((kt + 1) & 1) * STB, (kt + 1) * GBK);
                CP_WAIT(1);
            } else {
                CP_WAIT(0);
            }
            __syncthreads();

            const uint32_t st  = sBase + (kt & 1) * STB;
            const uint32_t sAh = st;
            const uint32_t sAl = st + ARRB;
            const uint32_t sWh = st + 2 * ARRB;
            const uint32_t sWl = st + 3 * ARRB;

#pragma unroll
            for (int ks = 0; ks < 2; ks++) {
                const int kc = ks * 16 + lc;   // b16 units: 16 b16 = 32 int8 K
                uint32_t ah[4][4], whf[2][4], wlf[2][4];
#pragma unroll
                for (int mt = 0; mt < 4; mt++)
                    ldsm4(ah[mt], sAh + ((wm + mt * 16 + lr) * LDSE + kc) * 2);
#pragma unroll
                for (int g = 0; g < 2; g++)
                    ldsm4(whf[g], sWh + ((wn + g * 16 + lr) * LDSE + kc) * 2);
#pragma unroll
                for (int g = 0; g < 2; g++)
                    ldsm4(wlf[g], sWl + ((wn + g * 16 + lr) * LDSE + kc) * 2);

                // hi*hi -> acc_hh
#pragma unroll
                for (int mt = 0; mt < 4; mt++)
#pragma unroll
                    for (int nt = 0; nt < 4; nt++)
                        mmai8(acch[mt][nt], ah[mt], whf[nt >> 1][nt & 1], whf[nt >> 1][(nt & 1) + 2]);
                // hi*lo -> acc_mid
#pragma unroll
                for (int mt = 0; mt < 4; mt++)
#pragma unroll
                    for (int nt = 0; nt < 4; nt++)
                        mmai8(accm[mt][nt], ah[mt], wlf[nt >> 1][nt & 1], wlf[nt >> 1][(nt & 1) + 2]);
                // lo*hi -> acc_mid (reload A frags from lo plane)
#pragma unroll
                for (int mt = 0; mt < 4; mt++)
                    ldsm4(ah[mt], sAl + ((wm + mt * 16 + lr) * LDSE + kc) * 2);
#pragma unroll
                for (int mt = 0; mt < 4; mt++)
#pragma unroll
                    for (int nt = 0; nt < 4; nt++)
                        mmai8(accm[mt][nt], ah[mt], whf[nt >> 1][nt & 1], whf[nt >> 1][(nt & 1) + 2]);
            }
            __syncthreads();
        }
    }
};

__device__ __forceinline__ float combine_i8(int hh, int mid, float sasw) {
    return fmaf(16384.f, (float)hh, 128.f * (float)mid) * sasw;
}

// ---------------------------------------------------------------------------
// Fused QKV projection GEMM (int8). grid (48, 64). blockIdx.x>>4 : 0=Q,1=K,2=V.
// Epilogue: bias, RoPE (Q,K), 1/sqrt(D) (Q), bf16 hi/lo split output.
// ---------------------------------------------------------------------------
__global__ void __launch_bounds__(GTH, 1) qkv_gemm(
    const int8_t* __restrict__ Xh, const int8_t* __restrict__ Xl,
    const int8_t* __restrict__ Wh, const int8_t* __restrict__ Wl,
    const float* __restrict__ sA, const float* __restrict__ sW,
    const float* __restrict__ bq, const float* __restrict__ bk, const float* __restrict__ bv,
    __nv_bfloat16* __restrict__ QH, __nv_bfloat16* __restrict__ QL,
    __nv_bfloat16* __restrict__ KH, __nv_bfloat16* __restrict__ KL,
    __nv_bfloat16* __restrict__ VH, __nv_bfloat16* __restrict__ VL,
    const float* __restrict__ cosT, const float* __restrict__ sinT)
{
    extern __shared__ char dsm[];
    const uint32_t sBase = smem_u32(dsm);

    const int tid  = threadIdx.x;
    const int wid  = tid >> 5;
    const int lane = tid & 31;
    const int wm   = (wid >> 2) * 64;
    const int wn   = (wid & 3) * 32;
    const int bm   = blockIdx.y * GBM;
    const int qkv  = blockIdx.x >> 4;
    const int bnl  = (blockIdx.x & 15) * GBN;
    const int bng  = blockIdx.x * GBN;

    int acch[4][4][4], accm[4][4][4];
#pragma unroll
    for (int mt = 0; mt < 4; mt++)
#pragma unroll
        for (int nt = 0; nt < 4; nt++)
#pragma unroll
            for (int e = 0; e < 4; e++) { acch[mt][nt][e] = 0; accm[mt][nt][e] = 0; }

    GemmCoreI8::run(sBase, acch, accm,
                    Xh + (size_t)bm * ATTN_, Xl + (size_t)bm * ATTN_,
                    Wh + (size_t)bng * ATTN_, Wl + (size_t)bng * ATTN_,
                    tid, wm, wn, lane & 15, (lane >> 4) << 3);

    const float* bias = (qkv == 0) ? bq : (qkv == 1) ? bk : bv;
    __nv_bfloat16* CH = (qkv == 0) ? QH : (qkv == 1) ? KH : VH;
    __nv_bfloat16* CL = (qkv == 0) ? QL : (qkv == 1) ? KL : VL;
    const bool rope  = (qkv != 2);
    const bool scale = (qkv == 0);
    const float qscale = 0.08838834764831843f;

    const int rr = lane >> 2;
    const int nn = (lane & 3) * 2;
#pragma unroll
    for (int mt = 0; mt < 4; mt++) {
#pragma unroll
        for (int half = 0; half < 2; half++) {
            const int m = bm + wm + mt * 16 + rr + half * 8;
            const int pos = m & (T_ - 1);
            const float sa = __ldg(&sA[m]);
#pragma unroll
            for (int nt = 0; nt < 4; nt++) {
                const int n0 = bnl + wn + nt * 8 + nn;           // local output col
                const int ng = bng + wn + nt * 8 + nn;           // global W row
                const float sw0 = __ldg(&sW[ng]);
                const float sw1 = __ldg(&sW[ng + 1]);
                const int e = half * 2;
                float v0 = combine_i8(acch[mt][nt][e],     accm[mt][nt][e],     sa * sw0)
                           + __ldg(&bias[n0]);
                float v1 = combine_i8(acch[mt][nt][e + 1], accm[mt][nt][e + 1], sa * sw1)
                           + __ldg(&bias[n0 + 1]);
                if (rope) {
                    const int pi = (n0 & (D_ - 1)) >> 1;
                    const float cv = __ldg(&cosT[pos * 64 + pi]);
                    const float sv = __ldg(&sinT[pos * 64 + pi]);
                    const float t1 = v0, t2 = v1;
                    v0 = t1 * cv - t2 * sv;
                    v1 = t1 * sv + t2 * cv;
                }
                if (scale) { v0 *= qscale; v1 *= qscale; }
                const __nv_bfloat16 h0 = __float2bfloat16(v0);
                const __nv_bfloat16 h1 = __float2bfloat16(v1);
                *(__nv_bfloat162*)(CH + (size_t)m * ATTN_ + n0) = __halves2bfloat162(h0, h1);
                *(__nv_bfloat162*)(CL + (size_t)m * ATTN_ + n0) = __halves2bfloat162(
                    __float2bfloat16(v0 - __bfloat162float(h0)),
                    __float2bfloat16(v1 - __bfloat162float(h1)));
            }
        }
    }
}

// ---------------------------------------------------------------------------
// Output projection GEMM (int8): fp32 out + bias. grid (16, 64).
// ---------------------------------------------------------------------------
__global__ void __launch_bounds__(GTH, 1) out_gemm(
    const int8_t* __restrict__ Ah, const int8_t* __restrict__ Al,
    const int8_t* __restrict__ Wh, const int8_t* __restrict__ Wl,
    const float* __restrict__ sA, const float* __restrict__ sW,
    const float* __restrict__ bias, float* __restrict__ Cf)
{
    extern __shared__ char dsm[];
    const uint32_t sBase = smem_u32(dsm);

    const int tid  = threadIdx.x;
    const int wid  = tid >> 5;
    const int lane = tid & 31;
    const int wm   = (wid >> 2) * 64;
    const int wn   = (wid & 3) * 32;
    const int bm   = blockIdx.y * GBM;
    const int bn   = blockIdx.x * GBN;

    int acch[4][4][4], accm[4][4][4];
#pragma unroll
    for (int mt = 0; mt < 4; mt++)
#pragma unroll
        for (int nt = 0; nt < 4; nt++)
#pragma unroll
            for (int e = 0; e < 4; e++) { acch[mt][nt][e] = 0; accm[mt][nt][e] = 0; }

    GemmCoreI8::run(sBase, acch, accm,
                    Ah + (size_t)bm * ATTN_, Al + (size_t)bm * ATTN_,
                    Wh + (size_t)bn * ATTN_, Wl + (size_t)bn * ATTN_,
                    tid, wm, wn, lane & 15, (lane >> 4) << 3);

    const int rr = lane >> 2;
    const int nn = (lane & 3) * 2;
#pragma unroll
    for (int mt = 0; mt < 4; mt++) {
#pragma unroll
        for (int half = 0; half < 2; half++) {
            const int m = bm + wm + mt * 16 + rr + half * 8;
            const float sa = __ldg(&sA[m]);
#pragma unroll
            for (int nt = 0; nt < 4; nt++) {
                const int n0 = bn + wn + nt * 8 + nn;
                const float sw0 = __ldg(&sW[n0]);
                const float sw1 = __ldg(&sW[n0 + 1]);
                const int e = half * 2;
                const float v0 = combine_i8(acch[mt][nt][e],     accm[mt][nt][e],     sa * sw0)
                                 + __ldg(&bias[n0]);
                const float v1 = combine_i8(acch[mt][nt][e + 1], accm[mt][nt][e + 1], sa * sw1)
                                 + __ldg(&bias[n0 + 1]);
                *(float2*)(Cf + (size_t)m * ATTN_ + n0) = make_float2(v0, v1);
            }
        }
    }
}

// ---------------------------------------------------------------------------
// Tensor-core causal flash attention, bf16x3 (unchanged math; writes fp32 Y).
// ---------------------------------------------------------------------------
static constexpr int FLD = 136;
static constexpr int FQB = 128 * FLD * 2;
static constexpr int FKB = 64 * FLD * 2;
static constexpr int FSTG = 4 * FKB;
static constexpr int FSMEM = 2 * FQB + 2 * FSTG;

__global__ void __launch_bounds__(256, 1) flash_mma(
    const __nv_bfloat16* __restrict__ Qh, const __nv_bfloat16* __restrict__ Ql,
    const __nv_bfloat16* __restrict__ Kh, const __nv_bfloat16* __restrict__ Kl,
    const __nv_bfloat16* __restrict__ Vh, const __nv_bfloat16* __restrict__ Vl,
    float* __restrict__ Y)
{
    extern __shared__ char fsm[];
    const uint32_t sb  = smem_u32(fsm);
    const uint32_t sQH = sb;
    const uint32_t sQL = sb + FQB;
    const uint32_t sKV = sb + 2 * FQB;

    const int qt = blockIdx.x, h = blockIdx.y, b = blockIdx.z;
    const int tid = threadIdx.x, wid = tid >> 5, lane = tid & 31;
    const int wm = wid * 16;
    const int lr = lane & 15;
    const int lcg = (lane >> 4) << 3;

    const int ccf = tid & 15;
    const int r0f = tid >> 4;

    {
        const __nv_bfloat16* qh_g = Qh + ((size_t)(b * T_ + qt * 128)) * ATTN_ + h * D_;
        const __nv_bfloat16* ql_g = Ql + ((size_t)(b * T_ + qt * 128)) * ATTN_ + h * D_;
#pragma unroll
        for (int bb = 0; bb < 8; bb++) {
            const int r = bb * 16 + r0f;
            const uint32_t so = r * (FLD * 2) + ccf * 16;
            const size_t go = (size_t)r * ATTN_ + ccf * 8;
            CP_ASYNC16(sQH + so, qh_g + go);
            CP_ASYNC16(sQL + so, ql_g + go);
        }
        CP_COMMIT();
    }

    const int nkv = 2 * qt + 2;

    auto issue_kv = [&](int j) {
        const uint32_t st = sKV + (j & 1) * FSTG;
        const size_t base = ((size_t)(b * T_ + j * 64)) * ATTN_ + h * D_;
#pragma unroll
        for (int bb = 0; bb < 4; bb++) {
            const int r = bb * 16 + r0f;
            const uint32_t so = r * (FLD * 2) + ccf * 16;
            const size_t go = base + (size_t)r * ATTN_ + ccf * 8;
            CP_ASYNC16(st + so, Kh + go);
            CP_ASYNC16(st + FKB + so, Kl + go);
            CP_ASYNC16(st + 2 * FKB + so, Vh + go);
            CP_ASYNC16(st + 3 * FKB + so, Vl + go);
        }
        CP_COMMIT();
    };

    issue_kv(0);

    float Oacc[16][4];
#pragma unroll
    for (int nt = 0; nt < 16; nt++)
#pragma unroll
        for (int e = 0; e < 4; e++) Oacc[nt][e] = 0.f;
    float m0 = -1e30f, m1 = -1e30f, l0 = 0.f, l1 = 0.f;

    const int grow0 = qt * 128 + wm + (lane >> 2);
    const int grow1 = grow0 + 8;

    for (int j = 0; j < nkv; j++) {
        if (j + 1 < nkv) {
            issue_kv(j + 1);
            CP_WAIT(1);
        } else {
            CP_WAIT(0);
        }
        __syncthreads();

        const uint32_t st  = sKV + (j & 1) * FSTG;
        const uint32_t cKH = st;
        const uint32_t cKL = st + FKB;
        const uint32_t cVH = st + 2 * FKB;
        const uint32_t cVL = st + 3 * FKB;

        float sc[8][4];
#pragma unroll
        for (int nt = 0; nt < 8; nt++)
#pragma unroll
            for (int e = 0; e < 4; e++) sc[nt][e] = 0.f;

#pragma unroll 2
        for (int ks = 0; ks < 8; ks++) {
            const int kc = ks * 16 + lcg;
            uint32_t aQh[4], aQl[4], kh[4][4], kl[4][4];
            ldsm4(aQh, sQH + ((wm + lr) * FLD + kc) * 2);
            ldsm4(aQl, sQL + ((wm + lr) * FLD + kc) * 2);
#pragma unroll
            for (int g = 0; g < 4; g++) {
                ldsm4(kh[g], cKH + ((g * 16 + lr) * FLD + kc) * 2);
                ldsm4(kl[g], cKL + ((g * 16 + lr) * FLD + kc) * 2);
            }
#pragma unroll
            for (int nt = 0; nt < 8; nt++) {
                const uint32_t b0h = kh[nt >> 1][nt & 1], b1h = kh[nt >> 1][(nt & 1) + 2];
                mma16816(sc[nt], aQh, b0h, b1h);
                mma16816(sc[nt], aQh, kl[nt >> 1][nt & 1], kl[nt >> 1][(nt & 1) + 2]);
                mma16816(sc[nt], aQl, b0h, b1h);
            }
        }

        if (j >= 2 * qt) {
            const int c0 = j * 64 + ((lane & 3) << 1);
#pragma unroll
            for (int nt = 0; nt < 8; nt++) {
                const int gc = c0 + nt * 8;
                if (gc > grow0)     sc[nt][0] = -1e30f;
                if (gc + 1 > grow0) sc[nt][1] = -1e30f;
                if (gc > grow1)     sc[nt][2] = -1e30f;
                if (gc + 1 > grow1) sc[nt][3] = -1e30f;
            }
        }
        float mx0 = -1e30f, mx1 = -1e30f;
#pragma unroll
        for (int nt = 0; nt < 8; nt++) {
            mx0 = fmaxf(mx0, fmaxf(sc[nt][0], sc[nt][1]));
            mx1 = fmaxf(mx1, fmaxf(sc[nt][2], sc[nt][3]));
        }
        mx0 = fmaxf(mx0, __shfl_xor_sync(0xffffffffu, mx0, 1));
        mx0 = fmaxf(mx0, __shfl_xor_sync(0xffffffffu, mx0, 2));
        mx1 = fmaxf(mx1, __shfl_xor_sync(0xffffffffu, mx1, 1));
        mx1 = fmaxf(mx1, __shfl_xor_sync(0xffffffffu, mx1, 2));
        const float mn0 = fmaxf(m0, mx0), mn1 = fmaxf(m1, mx1);
        const float al0 = __expf(m0 - mn0), al1 = __expf(m1 - mn1);
        float ls0 = 0.f, ls1 = 0.f;
#pragma unroll
        for (int nt = 0; nt < 8; nt++) {
            sc[nt][0] = __expf(sc[nt][0] - mn0);
            sc[nt][1] = __expf(sc[nt][1] - mn0);
            sc[nt][2] = __expf(sc[nt][2] - mn1);
            sc[nt][3] = __expf(sc[nt][3] - mn1);
            ls0 += sc[nt][0] + sc[nt][1];
            ls1 += sc[nt][2] + sc[nt][3];
        }
        ls0 += __shfl_xor_sync(0xffffffffu, ls0, 1);
        ls0 += __shfl_xor_sync(0xffffffffu, ls0, 2);
        ls1 += __shfl_xor_sync(0xffffffffu, ls1, 1);
        ls1 += __shfl_xor_sync(0xffffffffu, ls1, 2);
        l0 = l0 * al0 + ls0; m0 = mn0;
        l1 = l1 * al1 + ls1; m1 = mn1;
#pragma unroll
        for (int nt = 0; nt < 16; nt++) {
            Oacc[nt][0] *= al0; Oacc[nt][1] *= al0;
            Oacc[nt][2] *= al1; Oacc[nt][3] *= al1;
        }

#pragma unroll
        for (int ks = 0; ks < 4; ks++) {
            uint32_t aPh[4], aPl[4];
            {
                const float p0 = sc[2 * ks][0],     p1 = sc[2 * ks][1];
                const float p2 = sc[2 * ks][2],     p3 = sc[2 * ks][3];
                const float p4 = sc[2 * ks + 1][0], p5 = sc[2 * ks + 1][1];
                const float p6 = sc[2 * ks + 1][2], p7 = sc[2 * ks + 1][3];
                aPh[0] = packbf2(p0, p1);
                aPh[1] = packbf2(p2, p3);
                aPh[2] = packbf2(p4, p5);
                aPh[3] = packbf2(p6, p7);
                aPl[0] = packbf2(p0 - __bfloat162float(__float2bfloat16(p0)),
                                 p1 - __bfloat162float(__float2bfloat16(p1)));
                aPl[1] = packbf2(p2 - __bfloat162float(__float2bfloat16(p2)),
                                 p3 - __bfloat162float(__float2bfloat16(p3)));
                aPl[2] = packbf2(p4 - __bfloat162float(__float2bfloat16(p4)),
                                 p5 - __bfloat162float(__float2bfloat16(p5)));
                aPl[3] = packbf2(p6 - __bfloat162float(__float2bfloat16(p6)),
                                 p7 - __bfloat162float(__float2bfloat16(p7)));
            }
#pragma unroll
            for (int ng = 0; ng < 8; ng++) {
                uint32_t bh[4], bl[4];
                const uint32_t va = ((ks * 16 + lr) * FLD + ng * 16 + lcg) * 2;
                ldsm4t(bh, cVH + va);
                ldsm4t(bl, cVL + va);
                mma16816(Oacc[2 * ng], aPh, bh[0], bh[1]);
                mma16816(Oacc[2 * ng], aPh, bl[0], bl[1]);
                mma16816(Oacc[2 * ng], aPl, bh[0], bh[1]);
                mma16816(Oacc[2 * ng + 1], aPh, bh[2], bh[3]);
                mma16816(Oacc[2 * ng + 1], aPh, bl[2], bl[3]);
                mma16816(Oacc[2 * ng + 1], aPl, bh[2], bh[3]);
            }
        }
        __syncthreads();
    }

    const float inv0 = 1.0f / l0, inv1 = 1.0f / l1;
    const size_t rb0 = ((size_t)(b * T_) + grow0) * ATTN_ + h * D_;
    const size_t rb1 = ((size_t)(b * T_) + grow1) * ATTN_ + h * D_;
    const int nn = (lane & 3) << 1;
#pragma unroll
    for (int nt = 0; nt < 16; nt++) {
        const int col = nt * 8 + nn;
        *(float2*)(Y + rb0 + col) = make_float2(Oacc[nt][0] * inv0, Oacc[nt][1] * inv0);
        *(float2*)(Y + rb1 + col) = make_float2(Oacc[nt][2] * inv1, Oacc[nt][3] * inv1);
    }
}

// ---------------------------------------------------------------------------
// Host side. Order: 0 rope, 1 quant_x, 2 quant_w, 3 qkv, 4 flash, 5 quant_y, 6 out.
// ---------------------------------------------------------------------------
extern "C" void kernel_launch(void* const* d_in, const int* in_sizes, int n_in,
                              void* d_out, int out_size)
{
    const float* x    = (const float*)d_in[0];
    const float* wq_w = (const float*)d_in[3];
    const float* wq_b = (const float*)d_in[4];
    const float* wk_w = (const float*)d_in[5];
    const float* wk_b = (const float*)d_in[6];
    const float* wv_w = (const float*)d_in[7];
    const float* wv_b = (const float*)d_in[8];
    const float* wo_w = (const float*)d_in[9];
    const float* wo_b = (const float*)d_in[10];
    float* out = (float*)d_out;

    float *cosp, *sinp, *sx, *sw, *sy, *yp;
    int8_t *xqh, *xql, *wqh, *wql, *yqh, *yql;
    __nv_bfloat16 *qh, *ql, *kh, *kl, *vh, *vl;
    cudaGetSymbolAddress((void**)&cosp, g_cosT);
    cudaGetSymbolAddress((void**)&sinp, g_sinT);
    cudaGetSymbolAddress((void**)&sx, g_sx);
    cudaGetSymbolAddress((void**)&sw, g_sw);
    cudaGetSymbolAddress((void**)&sy, g_sy);
    cudaGetSymbolAddress((void**)&yp, g_y);
    cudaGetSymbolAddress((void**)&xqh, g_xqh);
    cudaGetSymbolAddress((void**)&xql, g_xql);
    cudaGetSymbolAddress((void**)&wqh, g_wqh);
    cudaGetSymbolAddress((void**)&wql, g_wql);
    cudaGetSymbolAddress((void**)&yqh, g_yqh);
    cudaGetSymbolAddress((void**)&yql, g_yql);
    cudaGetSymbolAddress((void**)&qh, g_qh);
    cudaGetSymbolAddress((void**)&ql, g_ql);
    cudaGetSymbolAddress((void**)&kh, g_kh);
    cudaGetSymbolAddress((void**)&kl, g_kl);
    cudaGetSymbolAddress((void**)&vh, g_vh);
    cudaGetSymbolAddress((void**)&vl, g_vl);

    const size_t WSZ = (size_t)ATTN_ * ATTN_;

    rope_table_kernel<<<T_, 64>>>(cosp, sinp);
    quant_kernel<<<BT_, 256>>>(x, xqh, xql, sx);
    quant_w_kernel<<<dim3(ATTN_, 1, 4), 256>>>(wq_w, wk_w, wv_w, wo_w, wqh, wql, sw);

    cudaFuncSetAttribute(qkv_gemm, cudaFuncAttributeMaxDynamicSharedMemorySize, GSMEM);
    cudaFuncSetAttribute(out_gemm, cudaFuncAttributeMaxDynamicSharedMemorySize, GSMEM);
    cudaFuncSetAttribute(flash_mma, cudaFuncAttributeMaxDynamicSharedMemorySize, FSMEM);

    qkv_gemm<<<dim3(48, BT_ / GBM), GTH, GSMEM>>>(xqh, xql, wqh, wql, sx, sw,
                                                  wq_b, wk_b, wv_b,
                                                  qh, ql, kh, kl, vh, vl,
                                                  cosp, sinp);
    flash_mma<<<dim3(T_ / 128, H_, B_), 256, FSMEM>>>(qh, ql, kh, kl, vh, vl, yp);
    quant_kernel<<<BT_, 256>>>(yp, yqh, yql, sy);
    out_gemm<<<dim3(ATTN_ / GBN, BT_ / GBM), GTH, GSMEM>>>(yqh, yql,
                                                           wqh + 3 * WSZ, wql + 3 * WSZ,
                                                           sy, sw + 3 * ATTN_,
                                                           wo_b, out);
}

// round 11
// speedup vs baseline: 2.8581x; 2.8581x over previous
#include <cuda_runtime.h>
#include <cuda_bf16.h>
#include <cuda_fp16.h>
#include <math.h>
#include <stdint.h>

#define B_    4
#define T_    2048
#define H_    16
#define D_    128
#define ATTN_ 2048
#define BT_   (B_*T_)

// ---------------------------------------------------------------------------
// Scratch. GEMM operands: A in fp16 hi/lo planes, W single fp16 plane
// (concat slots 0=wq 1=wk 2=wv 3=wo). Q/K/V bf16 hi/lo for flash; y fp16 hi/lo.
// ---------------------------------------------------------------------------
__device__ __half g_xh[(size_t)BT_ * ATTN_];
__device__ __half g_xl[(size_t)BT_ * ATTN_];
__device__ __half g_w[(size_t)4 * ATTN_ * ATTN_];
__device__ __half g_yh[(size_t)BT_ * ATTN_];
__device__ __half g_yl[(size_t)BT_ * ATTN_];
__device__ __nv_bfloat16 g_qh[(size_t)BT_ * ATTN_];
__device__ __nv_bfloat16 g_ql[(size_t)BT_ * ATTN_];
__device__ __nv_bfloat16 g_kh[(size_t)BT_ * ATTN_];
__device__ __nv_bfloat16 g_kl[(size_t)BT_ * ATTN_];
__device__ __nv_bfloat16 g_vh[(size_t)BT_ * ATTN_];
__device__ __nv_bfloat16 g_vl[(size_t)BT_ * ATTN_];
__device__ float g_cosT[T_ * 64];
__device__ float g_sinT[T_ * 64];

// ---------------------------------------------------------------------------
// PTX helpers
// ---------------------------------------------------------------------------
__device__ __forceinline__ uint32_t smem_u32(const void* p) {
    uint32_t a;
    asm("{ .reg .u64 t; cvta.to.shared.u64 t, %1; cvt.u32.u64 %0, t; }" : "=r"(a) : "l"(p));
    return a;
}

#define CP_ASYNC16(dst, src) \
    asm volatile("cp.async.cg.shared.global [%0], [%1], 16;" :: "r"(dst), "l"(src))
#define CP_COMMIT() asm volatile("cp.async.commit_group;" ::: "memory")
#define CP_WAIT(n)  asm volatile("cp.async.wait_group %0;" :: "n"(n) : "memory")

__device__ __forceinline__ void ldsm4(uint32_t* r, uint32_t addr) {
    asm volatile("ldmatrix.sync.aligned.m8n8.x4.shared.b16 {%0,%1,%2,%3}, [%4];"
                 : "=r"(r[0]), "=r"(r[1]), "=r"(r[2]), "=r"(r[3]) : "r"(addr));
}
__device__ __forceinline__ void ldsm4t(uint32_t* r, uint32_t addr) {
    asm volatile("ldmatrix.sync.aligned.m8n8.x4.trans.shared.b16 {%0,%1,%2,%3}, [%4];"
                 : "=r"(r[0]), "=r"(r[1]), "=r"(r[2]), "=r"(r[3]) : "r"(addr));
}

// bf16 mma (flash)
__device__ __forceinline__ void mma16816(float* c, const uint32_t* a,
                                         uint32_t b0, uint32_t b1) {
    asm volatile(
        "mma.sync.aligned.m16n8k16.row.col.f32.bf16.bf16.f32 "
        "{%0,%1,%2,%3}, {%4,%5,%6,%7}, {%8,%9}, {%0,%1,%2,%3};"
        : "+f"(c[0]), "+f"(c[1]), "+f"(c[2]), "+f"(c[3])
        : "r"(a[0]), "r"(a[1]), "r"(a[2]), "r"(a[3]), "r"(b0), "r"(b1));
}
// fp16 mma (projections)
__device__ __forceinline__ void mmah(float* c, const uint32_t* a,
                                     uint32_t b0, uint32_t b1) {
    asm volatile(
        "mma.sync.aligned.m16n8k16.row.col.f32.f16.f16.f32 "
        "{%0,%1,%2,%3}, {%4,%5,%6,%7}, {%8,%9}, {%0,%1,%2,%3};"
        : "+f"(c[0]), "+f"(c[1]), "+f"(c[2]), "+f"(c[3])
        : "r"(a[0]), "r"(a[1]), "r"(a[2]), "r"(a[3]), "r"(b0), "r"(b1));
}

__device__ __forceinline__ uint32_t packbf2(float a, float b) {
    __nv_bfloat162 t = __halves2bfloat162(__float2bfloat16(a), __float2bfloat16(b));
    return *(uint32_t*)&t;
}

// ---------------------------------------------------------------------------
// Elementwise kernels
// ---------------------------------------------------------------------------
__global__ void rope_table_kernel(float* __restrict__ cosT, float* __restrict__ sinT) {
    const int t = blockIdx.x;
    const int i = threadIdx.x;
    const float kFreq = 0.07195578415606394f;  // ln(10000)/128
    const float inv = expf((float)(2 * i) * -kFreq);
    const float ang = (float)t * inv;
    float s, c;
    sincosf(ang, &s, &c);
    cosT[t * 64 + i] = c;
    sinT[t * 64 + i] = s;
}

// fp16 hi/lo split of x
__global__ void split_x_kernel(const float4* __restrict__ src,
                               __half2* __restrict__ hi, __half2* __restrict__ lo, int n4) {
    int i = blockIdx.x * blockDim.x + threadIdx.x;
    if (i >= n4) return;
    float4 v = src[i];
    const __half h0 = __float2half_rn(v.x), h1 = __float2half_rn(v.y);
    const __half h2 = __float2half_rn(v.z), h3 = __float2half_rn(v.w);
    hi[2 * i]     = __halves2half2(h0, h1);
    hi[2 * i + 1] = __halves2half2(h2, h3);
    lo[2 * i]     = __halves2half2(__float2half_rn(v.x - __half2float(h0)),
                                   __float2half_rn(v.y - __half2float(h1)));
    lo[2 * i + 1] = __halves2half2(__float2half_rn(v.z - __half2float(h2)),
                                   __float2half_rn(v.w - __half2float(h3)));
}

// single-plane fp16 conversion of all 4 weight matrices (grid.z selects source)
__global__ void conv_w_kernel(const float* __restrict__ w0, const float* __restrict__ w1,
                              const float* __restrict__ w2, const float* __restrict__ w3,
                              __half2* __restrict__ dst, int n4) {
    int i = blockIdx.x * blockDim.x + threadIdx.x;
    if (i >= n4) return;
    const int z = blockIdx.z;
    const float* src = (z == 0) ? w0 : (z == 1) ? w1 : (z == 2) ? w2 : w3;
    float4 v = ((const float4*)src)[i];
    const size_t off = (size_t)z * n4 * 2;
    dst[off + 2 * i]     = __halves2half2(__float2half_rn(v.x), __float2half_rn(v.y));
    dst[off + 2 * i + 1] = __halves2half2(__float2half_rn(v.z), __float2half_rn(v.w));
}

// ---------------------------------------------------------------------------
// fp16 2-term GEMM core. CTA 128x128, BK=64, 8 warps (2Mx4N, warp 64x32),
// 2-stage cp.async. Arrays per stage: Ah, Al, W (each 128 x 144B). 108 KB total
// -> 2 CTAs/SM. acc (fp32) += Ah*W + Al*W.
// ---------------------------------------------------------------------------
static constexpr int GBM = 128, GBN = 128, GBK = 64;
static constexpr int LDSE = 72;                 // pitch in b16 elems = 144 B
static constexpr int ARRB = 128 * 144;          // 18432 B per array
static constexpr int STB  = 3 * ARRB;           // 55296 B per stage
static constexpr int GSMEM = 2 * STB;           // 110592 B
static constexpr int GTH = 256;

struct GemmCoreF16 {
    __device__ static __forceinline__ void run(
        uint32_t sBase, float (&acc)[4][4][4],
        const __half* gAh, const __half* gAl, const __half* gW,
        int tid, int wm, int wn, int lr, int lc)
    {
        const int cc = tid & 7;        // 16B chunk within 128B row
        const int rb = tid >> 3;       // 0..31
        const int NIT = ATTN_ / GBK;   // 32

        auto load_stage = [&](uint32_t st, int k0) {
#pragma unroll
            for (int bb = 0; bb < 4; bb++) {
                const int r = bb * 32 + rb;
                const uint32_t so = r * 144 + cc * 16;
                const size_t go = (size_t)r * ATTN_ + k0 + cc * 8;
                CP_ASYNC16(st + so,            gAh + go);
                CP_ASYNC16(st + ARRB + so,     gAl + go);
                CP_ASYNC16(st + 2 * ARRB + so, gW + go);
            }
            CP_COMMIT();
        };

        load_stage(sBase, 0);

        for (int kt = 0; kt < NIT; kt++) {
            if (kt + 1 < NIT) {
                load_stage(sBase + ((kt + 1) & 1) * STB, (kt + 1) * GBK);
                CP_WAIT(1);
            } else {
                CP_WAIT(0);
            }
            __syncthreads();

            const uint32_t st  = sBase + (kt & 1) * STB;
            const uint32_t sAh = st;
            const uint32_t sAl = st + ARRB;
            const uint32_t sW  = st + 2 * ARRB;

#pragma unroll
            for (int ks = 0; ks < 4; ks++) {
                const int kc = ks * 16 + lc;
                uint32_t ah[4][4], al[4][4], wf[2][4];
#pragma unroll
                for (int mt = 0; mt < 4; mt++)
                    ldsm4(ah[mt], sAh + ((wm + mt * 16 + lr) * LDSE + kc) * 2);
#pragma unroll
                for (int mt = 0; mt < 4; mt++)
                    ldsm4(al[mt], sAl + ((wm + mt * 16 + lr) * LDSE + kc) * 2);
#pragma unroll
                for (int g = 0; g < 2; g++)
                    ldsm4(wf[g], sW + ((wn + g * 16 + lr) * LDSE + kc) * 2);

#pragma unroll
                for (int mt = 0; mt < 4; mt++)
#pragma unroll
                    for (int nt = 0; nt < 4; nt++) {
                        const uint32_t b0 = wf[nt >> 1][nt & 1];
                        const uint32_t b1 = wf[nt >> 1][(nt & 1) + 2];
                        mmah(acc[mt][nt], ah[mt], b0, b1);
                        mmah(acc[mt][nt], al[mt], b0, b1);
                    }
            }
            __syncthreads();
        }
    }
};

// ---------------------------------------------------------------------------
// Fused QKV projection GEMM. grid (48, 64). blockIdx.x>>4 : 0=Q,1=K,2=V.
// Epilogue: bias, RoPE (Q,K), 1/sqrt(D) (Q), bf16 hi/lo split output (for flash).
// ---------------------------------------------------------------------------
__global__ void __launch_bounds__(GTH, 2) qkv_gemm(
    const __half* __restrict__ Xh, const __half* __restrict__ Xl,
    const __half* __restrict__ W,
    const float* __restrict__ bq, const float* __restrict__ bk, const float* __restrict__ bv,
    __nv_bfloat16* __restrict__ QH, __nv_bfloat16* __restrict__ QL,
    __nv_bfloat16* __restrict__ KH, __nv_bfloat16* __restrict__ KL,
    __nv_bfloat16* __restrict__ VH, __nv_bfloat16* __restrict__ VL,
    const float* __restrict__ cosT, const float* __restrict__ sinT)
{
    extern __shared__ char dsm[];
    const uint32_t sBase = smem_u32(dsm);

    const int tid  = threadIdx.x;
    const int wid  = tid >> 5;
    const int lane = tid & 31;
    const int wm   = (wid >> 2) * 64;
    const int wn   = (wid & 3) * 32;
    const int bm   = blockIdx.y * GBM;
    const int qkv  = blockIdx.x >> 4;
    const int bnl  = (blockIdx.x & 15) * GBN;
    const int bng  = blockIdx.x * GBN;

    float acc[4][4][4];
#pragma unroll
    for (int mt = 0; mt < 4; mt++)
#pragma unroll
        for (int nt = 0; nt < 4; nt++)
#pragma unroll
            for (int e = 0; e < 4; e++) acc[mt][nt][e] = 0.f;

    GemmCoreF16::run(sBase, acc,
                     Xh + (size_t)bm * ATTN_, Xl + (size_t)bm * ATTN_,
                     W + (size_t)bng * ATTN_,
                     tid, wm, wn, lane & 15, (lane >> 4) << 3);

    const float* bias = (qkv == 0) ? bq : (qkv == 1) ? bk : bv;
    __nv_bfloat16* CH = (qkv == 0) ? QH : (qkv == 1) ? KH : VH;
    __nv_bfloat16* CL = (qkv == 0) ? QL : (qkv == 1) ? KL : VL;
    const bool rope  = (qkv != 2);
    const bool scale = (qkv == 0);
    const float qscale = 0.08838834764831843f;

    const int rr = lane >> 2;
    const int nn = (lane & 3) * 2;
#pragma unroll
    for (int mt = 0; mt < 4; mt++) {
#pragma unroll
        for (int half_ = 0; half_ < 2; half_++) {
            const int m = bm + wm + mt * 16 + rr + half_ * 8;
            const int pos = m & (T_ - 1);
#pragma unroll
            for (int nt = 0; nt < 4; nt++) {
                const int n0 = bnl + wn + nt * 8 + nn;
                float v0 = acc[mt][nt][half_ * 2 + 0] + __ldg(&bias[n0]);
                float v1 = acc[mt][nt][half_ * 2 + 1] + __ldg(&bias[n0 + 1]);
                if (rope) {
                    const int pi = (n0 & (D_ - 1)) >> 1;
                    const float cv = __ldg(&cosT[pos * 64 + pi]);
                    const float sv = __ldg(&sinT[pos * 64 + pi]);
                    const float t1 = v0, t2 = v1;
                    v0 = t1 * cv - t2 * sv;
                    v1 = t1 * sv + t2 * cv;
                }
                if (scale) { v0 *= qscale; v1 *= qscale; }
                const __nv_bfloat16 h0 = __float2bfloat16(v0);
                const __nv_bfloat16 h1 = __float2bfloat16(v1);
                *(__nv_bfloat162*)(CH + (size_t)m * ATTN_ + n0) = __halves2bfloat162(h0, h1);
                *(__nv_bfloat162*)(CL + (size_t)m * ATTN_ + n0) = __halves2bfloat162(
                    __float2bfloat16(v0 - __bfloat162float(h0)),
                    __float2bfloat16(v1 - __bfloat162float(h1)));
            }
        }
    }
}

// ---------------------------------------------------------------------------
// Output projection GEMM: fp32 out + bias. grid (16, 64).
// ---------------------------------------------------------------------------
__global__ void __launch_bounds__(GTH, 2) out_gemm(
    const __half* __restrict__ Ah, const __half* __restrict__ Al,
    const __half* __restrict__ W,
    const float* __restrict__ bias, float* __restrict__ Cf)
{
    extern __shared__ char dsm[];
    const uint32_t sBase = smem_u32(dsm);

    const int tid  = threadIdx.x;
    const int wid  = tid >> 5;
    const int lane = tid & 31;
    const int wm   = (wid >> 2) * 64;
    const int wn   = (wid & 3) * 32;
    const int bm   = blockIdx.y * GBM;
    const int bn   = blockIdx.x * GBN;

    float acc[4][4][4];
#pragma unroll
    for (int mt = 0; mt < 4; mt++)
#pragma unroll
        for (int nt = 0; nt < 4; nt++)
#pragma unroll
            for (int e = 0; e < 4; e++) acc[mt][nt][e] = 0.f;

    GemmCoreF16::run(sBase, acc,
                     Ah + (size_t)bm * ATTN_, Al + (size_t)bm * ATTN_,
                     W + (size_t)bn * ATTN_,
                     tid, wm, wn, lane & 15, (lane >> 4) << 3);

    const int rr = lane >> 2;
    const int nn = (lane & 3) * 2;
#pragma unroll
    for (int mt = 0; mt < 4; mt++) {
#pragma unroll
        for (int half_ = 0; half_ < 2; half_++) {
            const int m = bm + wm + mt * 16 + rr + half_ * 8;
#pragma unroll
            for (int nt = 0; nt < 4; nt++) {
                const int n0 = bn + wn + nt * 8 + nn;
                const float v0 = acc[mt][nt][half_ * 2 + 0] + __ldg(&bias[n0]);
                const float v1 = acc[mt][nt][half_ * 2 + 1] + __ldg(&bias[n0 + 1]);
                *(float2*)(Cf + (size_t)m * ATTN_ + n0) = make_float2(v0, v1);
            }
        }
    }
}

// ---------------------------------------------------------------------------
// Tensor-core causal flash attention, bf16x3 (unchanged math). Outputs y as
// fp16 hi/lo planes for the fp16 out-projection.
// ---------------------------------------------------------------------------
static constexpr int FLD = 136;
static constexpr int FQB = 128 * FLD * 2;
static constexpr int FKB = 64 * FLD * 2;
static constexpr int FSTG = 4 * FKB;
static constexpr int FSMEM = 2 * FQB + 2 * FSTG;

__global__ void __launch_bounds__(256, 1) flash_mma(
    const __nv_bfloat16* __restrict__ Qh, const __nv_bfloat16* __restrict__ Ql,
    const __nv_bfloat16* __restrict__ Kh, const __nv_bfloat16* __restrict__ Kl,
    const __nv_bfloat16* __restrict__ Vh, const __nv_bfloat16* __restrict__ Vl,
    __half* __restrict__ Yh, __half* __restrict__ Yl)
{
    extern __shared__ char fsm[];
    const uint32_t sb  = smem_u32(fsm);
    const uint32_t sQH = sb;
    const uint32_t sQL = sb + FQB;
    const uint32_t sKV = sb + 2 * FQB;

    const int qt = blockIdx.x, h = blockIdx.y, b = blockIdx.z;
    const int tid = threadIdx.x, wid = tid >> 5, lane = tid & 31;
    const int wm = wid * 16;
    const int lr = lane & 15;
    const int lcg = (lane >> 4) << 3;

    const int ccf = tid & 15;
    const int r0f = tid >> 4;

    {
        const __nv_bfloat16* qh_g = Qh + ((size_t)(b * T_ + qt * 128)) * ATTN_ + h * D_;
        const __nv_bfloat16* ql_g = Ql + ((size_t)(b * T_ + qt * 128)) * ATTN_ + h * D_;
#pragma unroll
        for (int bb = 0; bb < 8; bb++) {
            const int r = bb * 16 + r0f;
            const uint32_t so = r * (FLD * 2) + ccf * 16;
            const size_t go = (size_t)r * ATTN_ + ccf * 8;
            CP_ASYNC16(sQH + so, qh_g + go);
            CP_ASYNC16(sQL + so, ql_g + go);
        }
        CP_COMMIT();
    }

    const int nkv = 2 * qt + 2;

    auto issue_kv = [&](int j) {
        const uint32_t st = sKV + (j & 1) * FSTG;
        const size_t base = ((size_t)(b * T_ + j * 64)) * ATTN_ + h * D_;
#pragma unroll
        for (int bb = 0; bb < 4; bb++) {
            const int r = bb * 16 + r0f;
            const uint32_t so = r * (FLD * 2) + ccf * 16;
            const size_t go = base + (size_t)r * ATTN_ + ccf * 8;
            CP_ASYNC16(st + so, Kh + go);
            CP_ASYNC16(st + FKB + so, Kl + go);
            CP_ASYNC16(st + 2 * FKB + so, Vh + go);
            CP_ASYNC16(st + 3 * FKB + so, Vl + go);
        }
        CP_COMMIT();
    };

    issue_kv(0);

    float Oacc[16][4];
#pragma unroll
    for (int nt = 0; nt < 16; nt++)
#pragma unroll
        for (int e = 0; e < 4; e++) Oacc[nt][e] = 0.f;
    float m0 = -1e30f, m1 = -1e30f, l0 = 0.f, l1 = 0.f;

    const int grow0 = qt * 128 + wm + (lane >> 2);
    const int grow1 = grow0 + 8;

    for (int j = 0; j < nkv; j++) {
        if (j + 1 < nkv) {
            issue_kv(j + 1);
            CP_WAIT(1);
        } else {
            CP_WAIT(0);
        }
        __syncthreads();

        const uint32_t st  = sKV + (j & 1) * FSTG;
        const uint32_t cKH = st;
        const uint32_t cKL = st + FKB;
        const uint32_t cVH = st + 2 * FKB;
        const uint32_t cVL = st + 3 * FKB;

        float sc[8][4];
#pragma unroll
        for (int nt = 0; nt < 8; nt++)
#pragma unroll
            for (int e = 0; e < 4; e++) sc[nt][e] = 0.f;

#pragma unroll 2
        for (int ks = 0; ks < 8; ks++) {
            const int kc = ks * 16 + lcg;
            uint32_t aQh[4], aQl[4], kh[4][4], kl[4][4];
            ldsm4(aQh, sQH + ((wm + lr) * FLD + kc) * 2);
            ldsm4(aQl, sQL + ((wm + lr) * FLD + kc) * 2);
#pragma unroll
            for (int g = 0; g < 4; g++) {
                ldsm4(kh[g], cKH + ((g * 16 + lr) * FLD + kc) * 2);
                ldsm4(kl[g], cKL + ((g * 16 + lr) * FLD + kc) * 2);
            }
#pragma unroll
            for (int nt = 0; nt < 8; nt++) {
                const uint32_t b0h = kh[nt >> 1][nt & 1], b1h = kh[nt >> 1][(nt & 1) + 2];
                mma16816(sc[nt], aQh, b0h, b1h);
                mma16816(sc[nt], aQh, kl[nt >> 1][nt & 1], kl[nt >> 1][(nt & 1) + 2]);
                mma16816(sc[nt], aQl, b0h, b1h);
            }
        }

        if (j >= 2 * qt) {
            const int c0 = j * 64 + ((lane & 3) << 1);
#pragma unroll
            for (int nt = 0; nt < 8; nt++) {
                const int gc = c0 + nt * 8;
                if (gc > grow0)     sc[nt][0] = -1e30f;
                if (gc + 1 > grow0) sc[nt][1] = -1e30f;
                if (gc > grow1)     sc[nt][2] = -1e30f;
                if (gc + 1 > grow1) sc[nt][3] = -1e30f;
            }
        }
        float mx0 = -1e30f, mx1 = -1e30f;
#pragma unroll
        for (int nt = 0; nt < 8; nt++) {
            mx0 = fmaxf(mx0, fmaxf(sc[nt][0], sc[nt][1]));
            mx1 = fmaxf(mx1, fmaxf(sc[nt][2], sc[nt][3]));
        }
        mx0 = fmaxf(mx0, __shfl_xor_sync(0xffffffffu, mx0, 1));
        mx0 = fmaxf(mx0, __shfl_xor_sync(0xffffffffu, mx0, 2));
        mx1 = fmaxf(mx1, __shfl_xor_sync(0xffffffffu, mx1, 1));
        mx1 = fmaxf(mx1, __shfl_xor_sync(0xffffffffu, mx1, 2));
        const float mn0 = fmaxf(m0, mx0), mn1 = fmaxf(m1, mx1);
        const float al0 = __expf(m0 - mn0), al1 = __expf(m1 - mn1);
        float ls0 = 0.f, ls1 = 0.f;
#pragma unroll
        for (int nt = 0; nt < 8; nt++) {
            sc[nt][0] = __expf(sc[nt][0] - mn0);
            sc[nt][1] = __expf(sc[nt][1] - mn0);
            sc[nt][2] = __expf(sc[nt][2] - mn1);
            sc[nt][3] = __expf(sc[nt][3] - mn1);
            ls0 += sc[nt][0] + sc[nt][1];
            ls1 += sc[nt][2] + sc[nt][3];
        }
        ls0 += __shfl_xor_sync(0xffffffffu, ls0, 1);
        ls0 += __shfl_xor_sync(0xffffffffu, ls0, 2);
        ls1 += __shfl_xor_sync(0xffffffffu, ls1, 1);
        ls1 += __shfl_xor_sync(0xffffffffu, ls1, 2);
        l0 = l0 * al0 + ls0; m0 = mn0;
        l1 = l1 * al1 + ls1; m1 = mn1;
#pragma unroll
        for (int nt = 0; nt < 16; nt++) {
            Oacc[nt][0] *= al0; Oacc[nt][1] *= al0;
            Oacc[nt][2] *= al1; Oacc[nt][3] *= al1;
        }

#pragma unroll
        for (int ks = 0; ks < 4; ks++) {
            uint32_t aPh[4], aPl[4];
            {
                const float p0 = sc[2 * ks][0],     p1 = sc[2 * ks][1];
                const float p2 = sc[2 * ks][2],     p3 = sc[2 * ks][3];
                const float p4 = sc[2 * ks + 1][0], p5 = sc[2 * ks + 1][1];
                const float p6 = sc[2 * ks + 1][2], p7 = sc[2 * ks + 1][3];
                aPh[0] = packbf2(p0, p1);
                aPh[1] = packbf2(p2, p3);
                aPh[2] = packbf2(p4, p5);
                aPh[3] = packbf2(p6, p7);
                aPl[0] = packbf2(p0 - __bfloat162float(__float2bfloat16(p0)),
                                 p1 - __bfloat162float(__float2bfloat16(p1)));
                aPl[1] = packbf2(p2 - __bfloat162float(__float2bfloat16(p2)),
                                 p3 - __bfloat162float(__float2bfloat16(p3)));
                aPl[2] = packbf2(p4 - __bfloat162float(__float2bfloat16(p4)),
                                 p5 - __bfloat162float(__float2bfloat16(p5)));
                aPl[3] = packbf2(p6 - __bfloat162float(__float2bfloat16(p6)),
                                 p7 - __bfloat162float(__float2bfloat16(p7)));
            }
#pragma unroll
            for (int ng = 0; ng < 8; ng++) {
                uint32_t bh[4], bl[4];
                const uint32_t va = ((ks * 16 + lr) * FLD + ng * 16 + lcg) * 2;
                ldsm4t(bh, cVH + va);
                ldsm4t(bl, cVL + va);
                mma16816(Oacc[2 * ng], aPh, bh[0], bh[1]);
                mma16816(Oacc[2 * ng], aPh, bl[0], bl[1]);
                mma16816(Oacc[2 * ng], aPl, bh[0], bh[1]);
                mma16816(Oacc[2 * ng + 1], aPh, bh[2], bh[3]);
                mma16816(Oacc[2 * ng + 1], aPh, bl[2], bl[3]);
                mma16816(Oacc[2 * ng + 1], aPl, bh[2], bh[3]);
            }
        }
        __syncthreads();
    }

    // finalize: /l, split into fp16 hi/lo for the fp16 out-projection
    const float inv0 = 1.0f / l0, inv1 = 1.0f / l1;
    const size_t rb0 = ((size_t)(b * T_) + grow0) * ATTN_ + h * D_;
    const size_t rb1 = ((size_t)(b * T_) + grow1) * ATTN_ + h * D_;
    const int nn = (lane & 3) << 1;
#pragma unroll
    for (int nt = 0; nt < 16; nt++) {
        const int col = nt * 8 + nn;
        {
            const float v0 = Oacc[nt][0] * inv0, v1 = Oacc[nt][1] * inv0;
            const __half h0 = __float2half_rn(v0), h1 = __float2half_rn(v1);
            *(__half2*)(Yh + rb0 + col) = __halves2half2(h0, h1);
            *(__half2*)(Yl + rb0 + col) = __halves2half2(
                __float2half_rn(v0 - __half2float(h0)),
                __float2half_rn(v1 - __half2float(h1)));
        }
        {
            const float v0 = Oacc[nt][2] * inv1, v1 = Oacc[nt][3] * inv1;
            const __half h0 = __float2half_rn(v0), h1 = __float2half_rn(v1);
            *(__half2*)(Yh + rb1 + col) = __halves2half2(h0, h1);
            *(__half2*)(Yl + rb1 + col) = __halves2half2(
                __float2half_rn(v0 - __half2float(h0)),
                __float2half_rn(v1 - __half2float(h1)));
        }
    }
}

// ---------------------------------------------------------------------------
// Host side. Order: 0 rope, 1 split_x, 2 conv_w, 3 qkv, 4 flash, 5 out.
// ---------------------------------------------------------------------------
extern "C" void kernel_launch(void* const* d_in, const int* in_sizes, int n_in,
                              void* d_out, int out_size)
{
    const float* x    = (const float*)d_in[0];
    const float* wq_w = (const float*)d_in[3];
    const float* wq_b = (const float*)d_in[4];
    const float* wk_w = (const float*)d_in[5];
    const float* wk_b = (const float*)d_in[6];
    const float* wv_w = (const float*)d_in[7];
    const float* wv_b = (const float*)d_in[8];
    const float* wo_w = (const float*)d_in[9];
    const float* wo_b = (const float*)d_in[10];
    float* out = (float*)d_out;

    float *cosp, *sinp;
    __half *xh, *xl, *wp, *yh, *yl;
    __nv_bfloat16 *qh, *ql, *kh, *kl, *vh, *vl;
    cudaGetSymbolAddress((void**)&cosp, g_cosT);
    cudaGetSymbolAddress((void**)&sinp, g_sinT);
    cudaGetSymbolAddress((void**)&xh, g_xh);
    cudaGetSymbolAddress((void**)&xl, g_xl);
    cudaGetSymbolAddress((void**)&wp, g_w);
    cudaGetSymbolAddress((void**)&yh, g_yh);
    cudaGetSymbolAddress((void**)&yl, g_yl);
    cudaGetSymbolAddress((void**)&qh, g_qh);
    cudaGetSymbolAddress((void**)&ql, g_ql);
    cudaGetSymbolAddress((void**)&kh, g_kh);
    cudaGetSymbolAddress((void**)&kl, g_kl);
    cudaGetSymbolAddress((void**)&vh, g_vh);
    cudaGetSymbolAddress((void**)&vl, g_vl);

    const size_t WSZ = (size_t)ATTN_ * ATTN_;

    rope_table_kernel<<<T_, 64>>>(cosp, sinp);
    const int n4x = BT_ * ATTN_ / 4;
    split_x_kernel<<<n4x / 256, 256>>>((const float4*)x, (__half2*)xh, (__half2*)xl, n4x);
    const int n4w = ATTN_ * ATTN_ / 4;
    conv_w_kernel<<<dim3(n4w / 256, 1, 4), 256>>>(wq_w, wk_w, wv_w, wo_w,
                                                  (__half2*)wp, n4w);

    cudaFuncSetAttribute(qkv_gemm, cudaFuncAttributeMaxDynamicSharedMemorySize, GSMEM);
    cudaFuncSetAttribute(out_gemm, cudaFuncAttributeMaxDynamicSharedMemorySize, GSMEM);
    cudaFuncSetAttribute(flash_mma, cudaFuncAttributeMaxDynamicSharedMemorySize, FSMEM);

    qkv_gemm<<<dim3(48, BT_ / GBM), GTH, GSMEM>>>(xh, xl, wp,
                                                  wq_b, wk_b, wv_b,
                                                  qh, ql, kh, kl, vh, vl,
                                                  cosp, sinp);
    flash_mma<<<dim3(T_ / 128, H_, B_), 256, FSMEM>>>(qh, ql, kh, kl, vh, vl, yh, yl);

    out_gemm<<<dim3(ATTN_ / GBN, BT_ / GBM), GTH, GSMEM>>>(yh, yl, wp + 3 * WSZ,
                                                           wo_b, out);
}

// round 12
// speedup vs baseline: 3.1473x; 1.1012x over previous
#include <cuda_runtime.h>
#include <cuda_fp16.h>
#include <math.h>
#include <stdint.h>

#define B_    4
#define T_    2048
#define H_    16
#define D_    128
#define ATTN_ 2048
#define BT_   (B_*T_)

// ---------------------------------------------------------------------------
// Scratch. All fp16: x hi/lo planes, W single plane (concat 0=wq 1=wk 2=wv 3=wo),
// Q hi/lo, K single, V single, y hi/lo.
// ---------------------------------------------------------------------------
__device__ __half g_xh[(size_t)BT_ * ATTN_];
__device__ __half g_xl[(size_t)BT_ * ATTN_];
__device__ __half g_w[(size_t)4 * ATTN_ * ATTN_];
__device__ __half g_qh[(size_t)BT_ * ATTN_];
__device__ __half g_ql[(size_t)BT_ * ATTN_];
__device__ __half g_k[(size_t)BT_ * ATTN_];
__device__ __half g_v[(size_t)BT_ * ATTN_];
__device__ __half g_yh[(size_t)BT_ * ATTN_];
__device__ __half g_yl[(size_t)BT_ * ATTN_];
__device__ float g_cosT[T_ * 64];
__device__ float g_sinT[T_ * 64];

// ---------------------------------------------------------------------------
// PTX helpers
// ---------------------------------------------------------------------------
__device__ __forceinline__ uint32_t smem_u32(const void* p) {
    uint32_t a;
    asm("{ .reg .u64 t; cvta.to.shared.u64 t, %1; cvt.u32.u64 %0, t; }" : "=r"(a) : "l"(p));
    return a;
}

#define CP_ASYNC16(dst, src) \
    asm volatile("cp.async.cg.shared.global [%0], [%1], 16;" :: "r"(dst), "l"(src))
#define CP_COMMIT() asm volatile("cp.async.commit_group;" ::: "memory")
#define CP_WAIT(n)  asm volatile("cp.async.wait_group %0;" :: "n"(n) : "memory")

__device__ __forceinline__ void ldsm4(uint32_t* r, uint32_t addr) {
    asm volatile("ldmatrix.sync.aligned.m8n8.x4.shared.b16 {%0,%1,%2,%3}, [%4];"
                 : "=r"(r[0]), "=r"(r[1]), "=r"(r[2]), "=r"(r[3]) : "r"(addr));
}
__device__ __forceinline__ void ldsm4t(uint32_t* r, uint32_t addr) {
    asm volatile("ldmatrix.sync.aligned.m8n8.x4.trans.shared.b16 {%0,%1,%2,%3}, [%4];"
                 : "=r"(r[0]), "=r"(r[1]), "=r"(r[2]), "=r"(r[3]) : "r"(addr));
}

__device__ __forceinline__ void mmah(float* c, const uint32_t* a,
                                     uint32_t b0, uint32_t b1) {
    asm volatile(
        "mma.sync.aligned.m16n8k16.row.col.f32.f16.f16.f32 "
        "{%0,%1,%2,%3}, {%4,%5,%6,%7}, {%8,%9}, {%0,%1,%2,%3};"
        : "+f"(c[0]), "+f"(c[1]), "+f"(c[2]), "+f"(c[3])
        : "r"(a[0]), "r"(a[1]), "r"(a[2]), "r"(a[3]), "r"(b0), "r"(b1));
}

__device__ __forceinline__ uint32_t packh2(float a, float b) {
    __half2 t = __halves2half2(__float2half_rn(a), __float2half_rn(b));
    return *(uint32_t*)&t;
}

// ---------------------------------------------------------------------------
// Elementwise kernels
// ---------------------------------------------------------------------------
__global__ void rope_table_kernel(float* __restrict__ cosT, float* __restrict__ sinT) {
    const int t = blockIdx.x;
    const int i = threadIdx.x;
    const float kFreq = 0.07195578415606394f;  // ln(10000)/128
    const float inv = expf((float)(2 * i) * -kFreq);
    const float ang = (float)t * inv;
    float s, c;
    sincosf(ang, &s, &c);
    cosT[t * 64 + i] = c;
    sinT[t * 64 + i] = s;
}

__global__ void split_x_kernel(const float4* __restrict__ src,
                               __half2* __restrict__ hi, __half2* __restrict__ lo, int n4) {
    int i = blockIdx.x * blockDim.x + threadIdx.x;
    if (i >= n4) return;
    float4 v = src[i];
    const __half h0 = __float2half_rn(v.x), h1 = __float2half_rn(v.y);
    const __half h2 = __float2half_rn(v.z), h3 = __float2half_rn(v.w);
    hi[2 * i]     = __halves2half2(h0, h1);
    hi[2 * i + 1] = __halves2half2(h2, h3);
    lo[2 * i]     = __halves2half2(__float2half_rn(v.x - __half2float(h0)),
                                   __float2half_rn(v.y - __half2float(h1)));
    lo[2 * i + 1] = __halves2half2(__float2half_rn(v.z - __half2float(h2)),
                                   __float2half_rn(v.w - __half2float(h3)));
}

__global__ void conv_w_kernel(const float* __restrict__ w0, const float* __restrict__ w1,
                              const float* __restrict__ w2, const float* __restrict__ w3,
                              __half2* __restrict__ dst, int n4) {
    int i = blockIdx.x * blockDim.x + threadIdx.x;
    if (i >= n4) return;
    const int z = blockIdx.z;
    const float* src = (z == 0) ? w0 : (z == 1) ? w1 : (z == 2) ? w2 : w3;
    float4 v = ((const float4*)src)[i];
    const size_t off = (size_t)z * n4 * 2;
    dst[off + 2 * i]     = __halves2half2(__float2half_rn(v.x), __float2half_rn(v.y));
    dst[off + 2 * i + 1] = __halves2half2(__float2half_rn(v.z), __float2half_rn(v.w));
}

// ---------------------------------------------------------------------------
// fp16 2-term GEMM core (round-11 winner, unchanged). CTA 128x128, BK=64,
// 8 warps (2Mx4N, warp 64x32), 2-stage, 108 KB -> 2 CTAs/SM.
// ---------------------------------------------------------------------------
static constexpr int GBM = 128, GBN = 128, GBK = 64;
static constexpr int LDSE = 72;
static constexpr int ARRB = 128 * 144;
static constexpr int STB  = 3 * ARRB;
static constexpr int GSMEM = 2 * STB;
static constexpr int GTH = 256;

struct GemmCoreF16 {
    __device__ static __forceinline__ void run(
        uint32_t sBase, float (&acc)[4][4][4],
        const __half* gAh, const __half* gAl, const __half* gW,
        int tid, int wm, int wn, int lr, int lc)
    {
        const int cc = tid & 7;
        const int rb = tid >> 3;
        const int NIT = ATTN_ / GBK;

        auto load_stage = [&](uint32_t st, int k0) {
#pragma unroll
            for (int bb = 0; bb < 4; bb++) {
                const int r = bb * 32 + rb;
                const uint32_t so = r * 144 + cc * 16;
                const size_t go = (size_t)r * ATTN_ + k0 + cc * 8;
                CP_ASYNC16(st + so,            gAh + go);
                CP_ASYNC16(st + ARRB + so,     gAl + go);
                CP_ASYNC16(st + 2 * ARRB + so, gW + go);
            }
            CP_COMMIT();
        };

        load_stage(sBase, 0);

        for (int kt = 0; kt < NIT; kt++) {
            if (kt + 1 < NIT) {
                load_stage(sBase + ((kt + 1) & 1) * STB, (kt + 1) * GBK);
                CP_WAIT(1);
            } else {
                CP_WAIT(0);
            }
            __syncthreads();

            const uint32_t st  = sBase + (kt & 1) * STB;
            const uint32_t sAh = st;
            const uint32_t sAl = st + ARRB;
            const uint32_t sW  = st + 2 * ARRB;

#pragma unroll
            for (int ks = 0; ks < 4; ks++) {
                const int kc = ks * 16 + lc;
                uint32_t ah[4][4], al[4][4], wf[2][4];
#pragma unroll
                for (int mt = 0; mt < 4; mt++)
                    ldsm4(ah[mt], sAh + ((wm + mt * 16 + lr) * LDSE + kc) * 2);
#pragma unroll
                for (int mt = 0; mt < 4; mt++)
                    ldsm4(al[mt], sAl + ((wm + mt * 16 + lr) * LDSE + kc) * 2);
#pragma unroll
                for (int g = 0; g < 2; g++)
                    ldsm4(wf[g], sW + ((wn + g * 16 + lr) * LDSE + kc) * 2);

#pragma unroll
                for (int mt = 0; mt < 4; mt++)
#pragma unroll
                    for (int nt = 0; nt < 4; nt++) {
                        const uint32_t b0 = wf[nt >> 1][nt & 1];
                        const uint32_t b1 = wf[nt >> 1][(nt & 1) + 2];
                        mmah(acc[mt][nt], ah[mt], b0, b1);
                        mmah(acc[mt][nt], al[mt], b0, b1);
                    }
            }
            __syncthreads();
        }
    }
};

// ---------------------------------------------------------------------------
// Fused QKV projection GEMM. grid (48, 64). blockIdx.x>>4 : 0=Q,1=K,2=V.
// Q out: fp16 hi/lo (2 planes). K,V out: single fp16 plane.
// ---------------------------------------------------------------------------
__global__ void __launch_bounds__(GTH, 2) qkv_gemm(
    const __half* __restrict__ Xh, const __half* __restrict__ Xl,
    const __half* __restrict__ W,
    const float* __restrict__ bq, const float* __restrict__ bk, const float* __restrict__ bv,
    __half* __restrict__ QH, __half* __restrict__ QL,
    __half* __restrict__ KK, __half* __restrict__ VV,
    const float* __restrict__ cosT, const float* __restrict__ sinT)
{
    extern __shared__ char dsm[];
    const uint32_t sBase = smem_u32(dsm);

    const int tid  = threadIdx.x;
    const int wid  = tid >> 5;
    const int lane = tid & 31;
    const int wm   = (wid >> 2) * 64;
    const int wn   = (wid & 3) * 32;
    const int bm   = blockIdx.y * GBM;
    const int qkv  = blockIdx.x >> 4;
    const int bnl  = (blockIdx.x & 15) * GBN;
    const int bng  = blockIdx.x * GBN;

    float acc[4][4][4];
#pragma unroll
    for (int mt = 0; mt < 4; mt++)
#pragma unroll
        for (int nt = 0; nt < 4; nt++)
#pragma unroll
            for (int e = 0; e < 4; e++) acc[mt][nt][e] = 0.f;

    GemmCoreF16::run(sBase, acc,
                     Xh + (size_t)bm * ATTN_, Xl + (size_t)bm * ATTN_,
                     W + (size_t)bng * ATTN_,
                     tid, wm, wn, lane & 15, (lane >> 4) << 3);

    const float* bias = (qkv == 0) ? bq : (qkv == 1) ? bk : bv;
    const bool rope  = (qkv != 2);
    const bool scale = (qkv == 0);
    const float qscale = 0.08838834764831843f;

    const int rr = lane >> 2;
    const int nn = (lane & 3) * 2;
#pragma unroll
    for (int mt = 0; mt < 4; mt++) {
#pragma unroll
        for (int half_ = 0; half_ < 2; half_++) {
            const int m = bm + wm + mt * 16 + rr + half_ * 8;
            const int pos = m & (T_ - 1);
#pragma unroll
            for (int nt = 0; nt < 4; nt++) {
                const int n0 = bnl + wn + nt * 8 + nn;
                float v0 = acc[mt][nt][half_ * 2 + 0] + __ldg(&bias[n0]);
                float v1 = acc[mt][nt][half_ * 2 + 1] + __ldg(&bias[n0 + 1]);
                if (rope) {
                    const int pi = (n0 & (D_ - 1)) >> 1;
                    const float cv = __ldg(&cosT[pos * 64 + pi]);
                    const float sv = __ldg(&sinT[pos * 64 + pi]);
                    const float t1 = v0, t2 = v1;
                    v0 = t1 * cv - t2 * sv;
                    v1 = t1 * sv + t2 * cv;
                }
                if (scale) { v0 *= qscale; v1 *= qscale; }
                const size_t off = (size_t)m * ATTN_ + n0;
                if (qkv == 0) {
                    const __half h0 = __float2half_rn(v0), h1 = __float2half_rn(v1);
                    *(__half2*)(QH + off) = __halves2half2(h0, h1);
                    *(__half2*)(QL + off) = __halves2half2(
                        __float2half_rn(v0 - __half2float(h0)),
                        __float2half_rn(v1 - __half2float(h1)));
                } else {
                    __half* C = (qkv == 1) ? KK : VV;
                    *(__half2*)(C + off) = __halves2half2(__float2half_rn(v0),
                                                          __float2half_rn(v1));
                }
            }
        }
    }
}

// ---------------------------------------------------------------------------
// Output projection GEMM: fp32 out + bias. grid (16, 64).
// ---------------------------------------------------------------------------
__global__ void __launch_bounds__(GTH, 2) out_gemm(
    const __half* __restrict__ Ah, const __half* __restrict__ Al,
    const __half* __restrict__ W,
    const float* __restrict__ bias, float* __restrict__ Cf)
{
    extern __shared__ char dsm[];
    const uint32_t sBase = smem_u32(dsm);

    const int tid  = threadIdx.x;
    const int wid  = tid >> 5;
    const int lane = tid & 31;
    const int wm   = (wid >> 2) * 64;
    const int wn   = (wid & 3) * 32;
    const int bm   = blockIdx.y * GBM;
    const int bn   = blockIdx.x * GBN;

    float acc[4][4][4];
#pragma unroll
    for (int mt = 0; mt < 4; mt++)
#pragma unroll
        for (int nt = 0; nt < 4; nt++)
#pragma unroll
            for (int e = 0; e < 4; e++) acc[mt][nt][e] = 0.f;

    GemmCoreF16::run(sBase, acc,
                     Ah + (size_t)bm * ATTN_, Al + (size_t)bm * ATTN_,
                     W + (size_t)bn * ATTN_,
                     tid, wm, wn, lane & 15, (lane >> 4) << 3);

    const int rr = lane >> 2;
    const int nn = (lane & 3) * 2;
#pragma unroll
    for (int mt = 0; mt < 4; mt++) {
#pragma unroll
        for (int half_ = 0; half_ < 2; half_++) {
            const int m = bm + wm + mt * 16 + rr + half_ * 8;
#pragma unroll
            for (int nt = 0; nt < 4; nt++) {
                const int n0 = bn + wn + nt * 8 + nn;
                const float v0 = acc[mt][nt][half_ * 2 + 0] + __ldg(&bias[n0]);
                const float v1 = acc[mt][nt][half_ * 2 + 1] + __ldg(&bias[n0 + 1]);
                *(float2*)(Cf + (size_t)m * ATTN_ + n0) = make_float2(v0, v1);
            }
        }
    }
}

// ---------------------------------------------------------------------------
// Tensor-core causal flash attention, fp16 2-term:
// S = (Qh+Ql) K (K single plane), O += (Ph+Pl) V (V single plane).
// CTA: 128 q-rows x D=128, 8 warps x 16 rows, KV tiles of 64, 2-stage cp.async.
// ---------------------------------------------------------------------------
static constexpr int FLD = 136;
static constexpr int FQB = 128 * FLD * 2;   // 34816
static constexpr int FKB = 64 * FLD * 2;    // 17408
static constexpr int FSTG = 2 * FKB;        // K + V single planes
static constexpr int FSMEM = 2 * FQB + 2 * FSTG;   // 139264

__global__ void __launch_bounds__(256, 1) flash_mma(
    const __half* __restrict__ Qh, const __half* __restrict__ Ql,
    const __half* __restrict__ K, const __half* __restrict__ V,
    __half* __restrict__ Yh, __half* __restrict__ Yl)
{
    extern __shared__ char fsm[];
    const uint32_t sb  = smem_u32(fsm);
    const uint32_t sQH = sb;
    const uint32_t sQL = sb + FQB;
    const uint32_t sKV = sb + 2 * FQB;

    const int qt = blockIdx.x, h = blockIdx.y, b = blockIdx.z;
    const int tid = threadIdx.x, wid = tid >> 5, lane = tid & 31;
    const int wm = wid * 16;
    const int lr = lane & 15;
    const int lcg = (lane >> 4) << 3;

    const int ccf = tid & 15;
    const int r0f = tid >> 4;

    {
        const __half* qh_g = Qh + ((size_t)(b * T_ + qt * 128)) * ATTN_ + h * D_;
        const __half* ql_g = Ql + ((size_t)(b * T_ + qt * 128)) * ATTN_ + h * D_;
#pragma unroll
        for (int bb = 0; bb < 8; bb++) {
            const int r = bb * 16 + r0f;
            const uint32_t so = r * (FLD * 2) + ccf * 16;
            const size_t go = (size_t)r * ATTN_ + ccf * 8;
            CP_ASYNC16(sQH + so, qh_g + go);
            CP_ASYNC16(sQL + so, ql_g + go);
        }
        CP_COMMIT();
    }

    const int nkv = 2 * qt + 2;

    auto issue_kv = [&](int j) {
        const uint32_t st = sKV + (j & 1) * FSTG;
        const size_t base = ((size_t)(b * T_ + j * 64)) * ATTN_ + h * D_;
#pragma unroll
        for (int bb = 0; bb < 4; bb++) {
            const int r = bb * 16 + r0f;
            const uint32_t so = r * (FLD * 2) + ccf * 16;
            const size_t go = base + (size_t)r * ATTN_ + ccf * 8;
            CP_ASYNC16(st + so, K + go);
            CP_ASYNC16(st + FKB + so, V + go);
        }
        CP_COMMIT();
    };

    issue_kv(0);

    float Oacc[16][4];
#pragma unroll
    for (int nt = 0; nt < 16; nt++)
#pragma unroll
        for (int e = 0; e < 4; e++) Oacc[nt][e] = 0.f;
    float m0 = -1e30f, m1 = -1e30f, l0 = 0.f, l1 = 0.f;

    const int grow0 = qt * 128 + wm + (lane >> 2);
    const int grow1 = grow0 + 8;

    for (int j = 0; j < nkv; j++) {
        if (j + 1 < nkv) {
            issue_kv(j + 1);
            CP_WAIT(1);
        } else {
            CP_WAIT(0);
        }
        __syncthreads();

        const uint32_t st  = sKV + (j & 1) * FSTG;
        const uint32_t cK = st;
        const uint32_t cV = st + FKB;

        // ---- S = Q K^T (2-term fp16) ----
        float sc[8][4];
#pragma unroll
        for (int nt = 0; nt < 8; nt++)
#pragma unroll
            for (int e = 0; e < 4; e++) sc[nt][e] = 0.f;

#pragma unroll 2
        for (int ks = 0; ks < 8; ks++) {
            const int kc = ks * 16 + lcg;
            uint32_t aQh[4], aQl[4], kf[4][4];
            ldsm4(aQh, sQH + ((wm + lr) * FLD + kc) * 2);
            ldsm4(aQl, sQL + ((wm + lr) * FLD + kc) * 2);
#pragma unroll
            for (int g = 0; g < 4; g++)
                ldsm4(kf[g], cK + ((g * 16 + lr) * FLD + kc) * 2);
#pragma unroll
            for (int nt = 0; nt < 8; nt++) {
                const uint32_t b0 = kf[nt >> 1][nt & 1], b1 = kf[nt >> 1][(nt & 1) + 2];
                mmah(sc[nt], aQh, b0, b1);
                mmah(sc[nt], aQl, b0, b1);
            }
        }

        // ---- masking + online softmax ----
        if (j >= 2 * qt) {
            const int c0 = j * 64 + ((lane & 3) << 1);
#pragma unroll
            for (int nt = 0; nt < 8; nt++) {
                const int gc = c0 + nt * 8;
                if (gc > grow0)     sc[nt][0] = -1e30f;
                if (gc + 1 > grow0) sc[nt][1] = -1e30f;
                if (gc > grow1)     sc[nt][2] = -1e30f;
                if (gc + 1 > grow1) sc[nt][3] = -1e30f;
            }
        }
        float mx0 = -1e30f, mx1 = -1e30f;
#pragma unroll
        for (int nt = 0; nt < 8; nt++) {
            mx0 = fmaxf(mx0, fmaxf(sc[nt][0], sc[nt][1]));
            mx1 = fmaxf(mx1, fmaxf(sc[nt][2], sc[nt][3]));
        }
        mx0 = fmaxf(mx0, __shfl_xor_sync(0xffffffffu, mx0, 1));
        mx0 = fmaxf(mx0, __shfl_xor_sync(0xffffffffu, mx0, 2));
        mx1 = fmaxf(mx1, __shfl_xor_sync(0xffffffffu, mx1, 1));
        mx1 = fmaxf(mx1, __shfl_xor_sync(0xffffffffu, mx1, 2));
        const float mn0 = fmaxf(m0, mx0), mn1 = fmaxf(m1, mx1);
        const float al0 = __expf(m0 - mn0), al1 = __expf(m1 - mn1);
        float ls0 = 0.f, ls1 = 0.f;
#pragma unroll
        for (int nt = 0; nt < 8; nt++) {
            sc[nt][0] = __expf(sc[nt][0] - mn0);
            sc[nt][1] = __expf(sc[nt][1] - mn0);
            sc[nt][2] = __expf(sc[nt][2] - mn1);
            sc[nt][3] = __expf(sc[nt][3] - mn1);
            ls0 += sc[nt][0] + sc[nt][1];
            ls1 += sc[nt][2] + sc[nt][3];
        }
        ls0 += __shfl_xor_sync(0xffffffffu, ls0, 1);
        ls0 += __shfl_xor_sync(0xffffffffu, ls0, 2);
        ls1 += __shfl_xor_sync(0xffffffffu, ls1, 1);
        ls1 += __shfl_xor_sync(0xffffffffu, ls1, 2);
        l0 = l0 * al0 + ls0; m0 = mn0;
        l1 = l1 * al1 + ls1; m1 = mn1;
#pragma unroll
        for (int nt = 0; nt < 16; nt++) {
            Oacc[nt][0] *= al0; Oacc[nt][1] *= al0;
            Oacc[nt][2] *= al1; Oacc[nt][3] *= al1;
        }

        // ---- O += (Ph+Pl) V (V single plane) ----
#pragma unroll
        for (int ks = 0; ks < 4; ks++) {
            uint32_t aPh[4], aPl[4];
            {
                const float p0 = sc[2 * ks][0],     p1 = sc[2 * ks][1];
                const float p2 = sc[2 * ks][2],     p3 = sc[2 * ks][3];
                const float p4 = sc[2 * ks + 1][0], p5 = sc[2 * ks + 1][1];
                const float p6 = sc[2 * ks + 1][2], p7 = sc[2 * ks + 1][3];
                aPh[0] = packh2(p0, p1);
                aPh[1] = packh2(p2, p3);
                aPh[2] = packh2(p4, p5);
                aPh[3] = packh2(p6, p7);
                aPl[0] = packh2(p0 - __half2float(__float2half_rn(p0)),
                                p1 - __half2float(__float2half_rn(p1)));
                aPl[1] = packh2(p2 - __half2float(__float2half_rn(p2)),
                                p3 - __half2float(__float2half_rn(p3)));
                aPl[2] = packh2(p4 - __half2float(__float2half_rn(p4)),
                                p5 - __half2float(__float2half_rn(p5)));
                aPl[3] = packh2(p6 - __half2float(__float2half_rn(p6)),
                                p7 - __half2float(__float2half_rn(p7)));
            }
#pragma unroll
            for (int ng = 0; ng < 8; ng++) {
                uint32_t bv[4];
                const uint32_t va = ((ks * 16 + lr) * FLD + ng * 16 + lcg) * 2;
                ldsm4t(bv, cV + va);
                mmah(Oacc[2 * ng], aPh, bv[0], bv[1]);
                mmah(Oacc[2 * ng], aPl, bv[0], bv[1]);
                mmah(Oacc[2 * ng + 1], aPh, bv[2], bv[3]);
                mmah(Oacc[2 * ng + 1], aPl, bv[2], bv[3]);
            }
        }
        __syncthreads();
    }

    // ---- finalize: /l, fp16 hi/lo split output ----
    const float inv0 = 1.0f / l0, inv1 = 1.0f / l1;
    const size_t rb0 = ((size_t)(b * T_) + grow0) * ATTN_ + h * D_;
    const size_t rb1 = ((size_t)(b * T_) + grow1) * ATTN_ + h * D_;
    const int nn = (lane & 3) << 1;
#pragma unroll
    for (int nt = 0; nt < 16; nt++) {
        const int col = nt * 8 + nn;
        {
            const float v0 = Oacc[nt][0] * inv0, v1 = Oacc[nt][1] * inv0;
            const __half h0 = __float2half_rn(v0), h1 = __float2half_rn(v1);
            *(__half2*)(Yh + rb0 + col) = __halves2half2(h0, h1);
            *(__half2*)(Yl + rb0 + col) = __halves2half2(
                __float2half_rn(v0 - __half2float(h0)),
                __float2half_rn(v1 - __half2float(h1)));
        }
        {
            const float v0 = Oacc[nt][2] * inv1, v1 = Oacc[nt][3] * inv1;
            const __half h0 = __float2half_rn(v0), h1 = __float2half_rn(v1);
            *(__half2*)(Yh + rb1 + col) = __halves2half2(h0, h1);
            *(__half2*)(Yl + rb1 + col) = __halves2half2(
                __float2half_rn(v0 - __half2float(h0)),
                __float2half_rn(v1 - __half2float(h1)));
        }
    }
}

// ---------------------------------------------------------------------------
// Host side. Order: 0 rope, 1 split_x, 2 conv_w, 3 qkv, 4 flash, 5 out.
// ---------------------------------------------------------------------------
extern "C" void kernel_launch(void* const* d_in, const int* in_sizes, int n_in,
                              void* d_out, int out_size)
{
    const float* x    = (const float*)d_in[0];
    const float* wq_w = (const float*)d_in[3];
    const float* wq_b = (const float*)d_in[4];
    const float* wk_w = (const float*)d_in[5];
    const float* wk_b = (const float*)d_in[6];
    const float* wv_w = (const float*)d_in[7];
    const float* wv_b = (const float*)d_in[8];
    const float* wo_w = (const float*)d_in[9];
    const float* wo_b = (const float*)d_in[10];
    float* out = (float*)d_out;

    float *cosp, *sinp;
    __half *xh, *xl, *wp, *qh, *ql, *kp, *vp, *yh, *yl;
    cudaGetSymbolAddress((void**)&cosp, g_cosT);
    cudaGetSymbolAddress((void**)&sinp, g_sinT);
    cudaGetSymbolAddress((void**)&xh, g_xh);
    cudaGetSymbolAddress((void**)&xl, g_xl);
    cudaGetSymbolAddress((void**)&wp, g_w);
    cudaGetSymbolAddress((void**)&qh, g_qh);
    cudaGetSymbolAddress((void**)&ql, g_ql);
    cudaGetSymbolAddress((void**)&kp, g_k);
    cudaGetSymbolAddress((void**)&vp, g_v);
    cudaGetSymbolAddress((void**)&yh, g_yh);
    cudaGetSymbolAddress((void**)&yl, g_yl);

    const size_t WSZ = (size_t)ATTN_ * ATTN_;

    rope_table_kernel<<<T_, 64>>>(cosp, sinp);
    const int n4x = BT_ * ATTN_ / 4;
    split_x_kernel<<<n4x / 256, 256>>>((const float4*)x, (__half2*)xh, (__half2*)xl, n4x);
    const int n4w = ATTN_ * ATTN_ / 4;
    conv_w_kernel<<<dim3(n4w / 256, 1, 4), 256>>>(wq_w, wk_w, wv_w, wo_w,
                                                  (__half2*)wp, n4w);

    cudaFuncSetAttribute(qkv_gemm, cudaFuncAttributeMaxDynamicSharedMemorySize, GSMEM);
    cudaFuncSetAttribute(out_gemm, cudaFuncAttributeMaxDynamicSharedMemorySize, GSMEM);
    cudaFuncSetAttribute(flash_mma, cudaFuncAttributeMaxDynamicSharedMemorySize, FSMEM);

    qkv_gemm<<<dim3(48, BT_ / GBM), GTH, GSMEM>>>(xh, xl, wp,
                                                  wq_b, wk_b, wv_b,
                                                  qh, ql, kp, vp,
                                                  cosp, sinp);
    flash_mma<<<dim3(T_ / 128, H_, B_), 256, FSMEM>>>(qh, ql, kp, vp, yh, yl);

    out_gemm<<<dim3(ATTN_ / GBN, BT_ / GBM), GTH, GSMEM>>>(yh, yl, wp + 3 * WSZ,
                                                           wo_b, out);
}

// round 13
// speedup vs baseline: 3.5977x; 1.1431x over previous
#include <cuda_runtime.h>
#include <cuda_fp16.h>
#include <math.h>
#include <stdint.h>

#define B_    4
#define T_    2048
#define H_    16
#define D_    128
#define ATTN_ 2048
#define BT_   (B_*T_)

// ---------------------------------------------------------------------------
// Scratch, all fp16. x single plane, W single plane (concat 0=wq 1=wk 2=wv 3=wo),
// Q hi/lo (flash precision), K/V single, y single.
// ---------------------------------------------------------------------------
__device__ __half g_x[(size_t)BT_ * ATTN_];
__device__ __half g_w[(size_t)4 * ATTN_ * ATTN_];
__device__ __half g_qh[(size_t)BT_ * ATTN_];
__device__ __half g_ql[(size_t)BT_ * ATTN_];
__device__ __half g_k[(size_t)BT_ * ATTN_];
__device__ __half g_v[(size_t)BT_ * ATTN_];
__device__ __half g_y[(size_t)BT_ * ATTN_];
__device__ float g_cosT[T_ * 64];
__device__ float g_sinT[T_ * 64];

// ---------------------------------------------------------------------------
// PTX helpers
// ---------------------------------------------------------------------------
__device__ __forceinline__ uint32_t smem_u32(const void* p) {
    uint32_t a;
    asm("{ .reg .u64 t; cvta.to.shared.u64 t, %1; cvt.u32.u64 %0, t; }" : "=r"(a) : "l"(p));
    return a;
}

#define CP_ASYNC16(dst, src) \
    asm volatile("cp.async.cg.shared.global [%0], [%1], 16;" :: "r"(dst), "l"(src))
#define CP_COMMIT() asm volatile("cp.async.commit_group;" ::: "memory")
#define CP_WAIT(n)  asm volatile("cp.async.wait_group %0;" :: "n"(n) : "memory")

__device__ __forceinline__ void ldsm4(uint32_t* r, uint32_t addr) {
    asm volatile("ldmatrix.sync.aligned.m8n8.x4.shared.b16 {%0,%1,%2,%3}, [%4];"
                 : "=r"(r[0]), "=r"(r[1]), "=r"(r[2]), "=r"(r[3]) : "r"(addr));
}
__device__ __forceinline__ void ldsm4t(uint32_t* r, uint32_t addr) {
    asm volatile("ldmatrix.sync.aligned.m8n8.x4.trans.shared.b16 {%0,%1,%2,%3}, [%4];"
                 : "=r"(r[0]), "=r"(r[1]), "=r"(r[2]), "=r"(r[3]) : "r"(addr));
}

__device__ __forceinline__ void mmah(float* c, const uint32_t* a,
                                     uint32_t b0, uint32_t b1) {
    asm volatile(
        "mma.sync.aligned.m16n8k16.row.col.f32.f16.f16.f32 "
        "{%0,%1,%2,%3}, {%4,%5,%6,%7}, {%8,%9}, {%0,%1,%2,%3};"
        : "+f"(c[0]), "+f"(c[1]), "+f"(c[2]), "+f"(c[3])
        : "r"(a[0]), "r"(a[1]), "r"(a[2]), "r"(a[3]), "r"(b0), "r"(b1));
}

__device__ __forceinline__ uint32_t packh2(float a, float b) {
    __half2 t = __halves2half2(__float2half_rn(a), __float2half_rn(b));
    return *(uint32_t*)&t;
}

// ---------------------------------------------------------------------------
// Elementwise kernels
// ---------------------------------------------------------------------------
__global__ void rope_table_kernel(float* __restrict__ cosT, float* __restrict__ sinT) {
    const int t = blockIdx.x;
    const int i = threadIdx.x;
    const float kFreq = 0.07195578415606394f;  // ln(10000)/128
    const float inv = expf((float)(2 * i) * -kFreq);
    const float ang = (float)t * inv;
    float s, c;
    sincosf(ang, &s, &c);
    cosT[t * 64 + i] = c;
    sinT[t * 64 + i] = s;
}

__global__ void conv_x_kernel(const float4* __restrict__ src,
                              __half2* __restrict__ dst, int n4) {
    int i = blockIdx.x * blockDim.x + threadIdx.x;
    if (i >= n4) return;
    float4 v = src[i];
    dst[2 * i]     = __halves2half2(__float2half_rn(v.x), __float2half_rn(v.y));
    dst[2 * i + 1] = __halves2half2(__float2half_rn(v.z), __float2half_rn(v.w));
}

__global__ void conv_w_kernel(const float* __restrict__ w0, const float* __restrict__ w1,
                              const float* __restrict__ w2, const float* __restrict__ w3,
                              __half2* __restrict__ dst, int n4) {
    int i = blockIdx.x * blockDim.x + threadIdx.x;
    if (i >= n4) return;
    const int z = blockIdx.z;
    const float* src = (z == 0) ? w0 : (z == 1) ? w1 : (z == 2) ? w2 : w3;
    float4 v = ((const float4*)src)[i];
    const size_t off = (size_t)z * n4 * 2;
    dst[off + 2 * i]     = __halves2half2(__float2half_rn(v.x), __float2half_rn(v.y));
    dst[off + 2 * i + 1] = __halves2half2(__float2half_rn(v.z), __float2half_rn(v.w));
}

// ---------------------------------------------------------------------------
// fp16 1-term GEMM core. CTA 128x128, BK=64, 8 warps (2Mx4N, warp 64x32),
// 2-stage cp.async. Arrays per stage: A, W (each 128 x 144B) = 36 KB;
// total 72 KB -> 3 CTAs/SM.
// ---------------------------------------------------------------------------
static constexpr int GBM = 128, GBN = 128, GBK = 64;
static constexpr int LDSE = 72;
static constexpr int ARRB = 128 * 144;          // 18432 B
static constexpr int STB  = 2 * ARRB;           // 36864 B
static constexpr int GSMEM = 2 * STB;           // 73728 B
static constexpr int GTH = 256;

struct GemmCoreF16 {
    __device__ static __forceinline__ void run(
        uint32_t sBase, float (&acc)[4][4][4],
        const __half* gA, const __half* gW,
        int tid, int wm, int wn, int lr, int lc)
    {
        const int cc = tid & 7;
        const int rb = tid >> 3;
        const int NIT = ATTN_ / GBK;

        auto load_stage = [&](uint32_t st, int k0) {
#pragma unroll
            for (int bb = 0; bb < 4; bb++) {
                const int r = bb * 32 + rb;
                const uint32_t so = r * 144 + cc * 16;
                const size_t go = (size_t)r * ATTN_ + k0 + cc * 8;
                CP_ASYNC16(st + so,        gA + go);
                CP_ASYNC16(st + ARRB + so, gW + go);
            }
            CP_COMMIT();
        };

        load_stage(sBase, 0);

        for (int kt = 0; kt < NIT; kt++) {
            if (kt + 1 < NIT) {
                load_stage(sBase + ((kt + 1) & 1) * STB, (kt + 1) * GBK);
                CP_WAIT(1);
            } else {
                CP_WAIT(0);
            }
            __syncthreads();

            const uint32_t st = sBase + (kt & 1) * STB;
            const uint32_t sA = st;
            const uint32_t sW = st + ARRB;

#pragma unroll
            for (int ks = 0; ks < 4; ks++) {
                const int kc = ks * 16 + lc;
                uint32_t af[4][4], wf[2][4];
#pragma unroll
                for (int mt = 0; mt < 4; mt++)
                    ldsm4(af[mt], sA + ((wm + mt * 16 + lr) * LDSE + kc) * 2);
#pragma unroll
                for (int g = 0; g < 2; g++)
                    ldsm4(wf[g], sW + ((wn + g * 16 + lr) * LDSE + kc) * 2);

#pragma unroll
                for (int mt = 0; mt < 4; mt++)
#pragma unroll
                    for (int nt = 0; nt < 4; nt++)
                        mmah(acc[mt][nt], af[mt], wf[nt >> 1][nt & 1], wf[nt >> 1][(nt & 1) + 2]);
            }
            __syncthreads();
        }
    }
};

// ---------------------------------------------------------------------------
// Fused QKV projection GEMM. grid (48, 64). blockIdx.x>>4 : 0=Q,1=K,2=V.
// Q out: fp16 hi/lo planes. K,V out: single fp16 plane.
// ---------------------------------------------------------------------------
__global__ void __launch_bounds__(GTH, 3) qkv_gemm(
    const __half* __restrict__ X, const __half* __restrict__ W,
    const float* __restrict__ bq, const float* __restrict__ bk, const float* __restrict__ bv,
    __half* __restrict__ QH, __half* __restrict__ QL,
    __half* __restrict__ KK, __half* __restrict__ VV,
    const float* __restrict__ cosT, const float* __restrict__ sinT)
{
    extern __shared__ char dsm[];
    const uint32_t sBase = smem_u32(dsm);

    const int tid  = threadIdx.x;
    const int wid  = tid >> 5;
    const int lane = tid & 31;
    const int wm   = (wid >> 2) * 64;
    const int wn   = (wid & 3) * 32;
    const int bm   = blockIdx.y * GBM;
    const int qkv  = blockIdx.x >> 4;
    const int bnl  = (blockIdx.x & 15) * GBN;
    const int bng  = blockIdx.x * GBN;

    float acc[4][4][4];
#pragma unroll
    for (int mt = 0; mt < 4; mt++)
#pragma unroll
        for (int nt = 0; nt < 4; nt++)
#pragma unroll
            for (int e = 0; e < 4; e++) acc[mt][nt][e] = 0.f;

    GemmCoreF16::run(sBase, acc,
                     X + (size_t)bm * ATTN_, W + (size_t)bng * ATTN_,
                     tid, wm, wn, lane & 15, (lane >> 4) << 3);

    const float* bias = (qkv == 0) ? bq : (qkv == 1) ? bk : bv;
    const bool rope  = (qkv != 2);
    const bool scale = (qkv == 0);
    const float qscale = 0.08838834764831843f;

    const int rr = lane >> 2;
    const int nn = (lane & 3) * 2;
#pragma unroll
    for (int mt = 0; mt < 4; mt++) {
#pragma unroll
        for (int half_ = 0; half_ < 2; half_++) {
            const int m = bm + wm + mt * 16 + rr + half_ * 8;
            const int pos = m & (T_ - 1);
#pragma unroll
            for (int nt = 0; nt < 4; nt++) {
                const int n0 = bnl + wn + nt * 8 + nn;
                float v0 = acc[mt][nt][half_ * 2 + 0] + __ldg(&bias[n0]);
                float v1 = acc[mt][nt][half_ * 2 + 1] + __ldg(&bias[n0 + 1]);
                if (rope) {
                    const int pi = (n0 & (D_ - 1)) >> 1;
                    const float cv = __ldg(&cosT[pos * 64 + pi]);
                    const float sv = __ldg(&sinT[pos * 64 + pi]);
                    const float t1 = v0, t2 = v1;
                    v0 = t1 * cv - t2 * sv;
                    v1 = t1 * sv + t2 * cv;
                }
                if (scale) { v0 *= qscale; v1 *= qscale; }
                const size_t off = (size_t)m * ATTN_ + n0;
                if (qkv == 0) {
                    const __half h0 = __float2half_rn(v0), h1 = __float2half_rn(v1);
                    *(__half2*)(QH + off) = __halves2half2(h0, h1);
                    *(__half2*)(QL + off) = __halves2half2(
                        __float2half_rn(v0 - __half2float(h0)),
                        __float2half_rn(v1 - __half2float(h1)));
                } else {
                    __half* C = (qkv == 1) ? KK : VV;
                    *(__half2*)(C + off) = __halves2half2(__float2half_rn(v0),
                                                          __float2half_rn(v1));
                }
            }
        }
    }
}

// ---------------------------------------------------------------------------
// Output projection GEMM: fp32 out + bias. grid (16, 64). Single-plane y.
// ---------------------------------------------------------------------------
__global__ void __launch_bounds__(GTH, 3) out_gemm(
    const __half* __restrict__ A, const __half* __restrict__ W,
    const float* __restrict__ bias, float* __restrict__ Cf)
{
    extern __shared__ char dsm[];
    const uint32_t sBase = smem_u32(dsm);

    const int tid  = threadIdx.x;
    const int wid  = tid >> 5;
    const int lane = tid & 31;
    const int wm   = (wid >> 2) * 64;
    const int wn   = (wid & 3) * 32;
    const int bm   = blockIdx.y * GBM;
    const int bn   = blockIdx.x * GBN;

    float acc[4][4][4];
#pragma unroll
    for (int mt = 0; mt < 4; mt++)
#pragma unroll
        for (int nt = 0; nt < 4; nt++)
#pragma unroll
            for (int e = 0; e < 4; e++) acc[mt][nt][e] = 0.f;

    GemmCoreF16::run(sBase, acc,
                     A + (size_t)bm * ATTN_, W + (size_t)bn * ATTN_,
                     tid, wm, wn, lane & 15, (lane >> 4) << 3);

    const int rr = lane >> 2;
    const int nn = (lane & 3) * 2;
#pragma unroll
    for (int mt = 0; mt < 4; mt++) {
#pragma unroll
        for (int half_ = 0; half_ < 2; half_++) {
            const int m = bm + wm + mt * 16 + rr + half_ * 8;
#pragma unroll
            for (int nt = 0; nt < 4; nt++) {
                const int n0 = bn + wn + nt * 8 + nn;
                const float v0 = acc[mt][nt][half_ * 2 + 0] + __ldg(&bias[n0]);
                const float v1 = acc[mt][nt][half_ * 2 + 1] + __ldg(&bias[n0 + 1]);
                *(float2*)(Cf + (size_t)m * ATTN_ + n0) = make_float2(v0, v1);
            }
        }
    }
}

// ---------------------------------------------------------------------------
// Tensor-core causal flash attention, fp16 2-term (round-12 winner):
// S = (Qh+Ql) K, O += (Ph+Pl) V. Writes y single-plane fp16.
// ---------------------------------------------------------------------------
static constexpr int FLD = 136;
static constexpr int FQB = 128 * FLD * 2;
static constexpr int FKB = 64 * FLD * 2;
static constexpr int FSTG = 2 * FKB;
static constexpr int FSMEM = 2 * FQB + 2 * FSTG;

__global__ void __launch_bounds__(256, 1) flash_mma(
    const __half* __restrict__ Qh, const __half* __restrict__ Ql,
    const __half* __restrict__ K, const __half* __restrict__ V,
    __half* __restrict__ Y)
{
    extern __shared__ char fsm[];
    const uint32_t sb  = smem_u32(fsm);
    const uint32_t sQH = sb;
    const uint32_t sQL = sb + FQB;
    const uint32_t sKV = sb + 2 * FQB;

    const int qt = blockIdx.x, h = blockIdx.y, b = blockIdx.z;
    const int tid = threadIdx.x, wid = tid >> 5, lane = tid & 31;
    const int wm = wid * 16;
    const int lr = lane & 15;
    const int lcg = (lane >> 4) << 3;

    const int ccf = tid & 15;
    const int r0f = tid >> 4;

    {
        const __half* qh_g = Qh + ((size_t)(b * T_ + qt * 128)) * ATTN_ + h * D_;
        const __half* ql_g = Ql + ((size_t)(b * T_ + qt * 128)) * ATTN_ + h * D_;
#pragma unroll
        for (int bb = 0; bb < 8; bb++) {
            const int r = bb * 16 + r0f;
            const uint32_t so = r * (FLD * 2) + ccf * 16;
            const size_t go = (size_t)r * ATTN_ + ccf * 8;
            CP_ASYNC16(sQH + so, qh_g + go);
            CP_ASYNC16(sQL + so, ql_g + go);
        }
        CP_COMMIT();
    }

    const int nkv = 2 * qt + 2;

    auto issue_kv = [&](int j) {
        const uint32_t st = sKV + (j & 1) * FSTG;
        const size_t base = ((size_t)(b * T_ + j * 64)) * ATTN_ + h * D_;
#pragma unroll
        for (int bb = 0; bb < 4; bb++) {
            const int r = bb * 16 + r0f;
            const uint32_t so = r * (FLD * 2) + ccf * 16;
            const size_t go = base + (size_t)r * ATTN_ + ccf * 8;
            CP_ASYNC16(st + so, K + go);
            CP_ASYNC16(st + FKB + so, V + go);
        }
        CP_COMMIT();
    };

    issue_kv(0);

    float Oacc[16][4];
#pragma unroll
    for (int nt = 0; nt < 16; nt++)
#pragma unroll
        for (int e = 0; e < 4; e++) Oacc[nt][e] = 0.f;
    float m0 = -1e30f, m1 = -1e30f, l0 = 0.f, l1 = 0.f;

    const int grow0 = qt * 128 + wm + (lane >> 2);
    const int grow1 = grow0 + 8;

    for (int j = 0; j < nkv; j++) {
        if (j + 1 < nkv) {
            issue_kv(j + 1);
            CP_WAIT(1);
        } else {
            CP_WAIT(0);
        }
        __syncthreads();

        const uint32_t st = sKV + (j & 1) * FSTG;
        const uint32_t cK = st;
        const uint32_t cV = st + FKB;

        float sc[8][4];
#pragma unroll
        for (int nt = 0; nt < 8; nt++)
#pragma unroll
            for (int e = 0; e < 4; e++) sc[nt][e] = 0.f;

#pragma unroll 2
        for (int ks = 0; ks < 8; ks++) {
            const int kc = ks * 16 + lcg;
            uint32_t aQh[4], aQl[4], kf[4][4];
            ldsm4(aQh, sQH + ((wm + lr) * FLD + kc) * 2);
            ldsm4(aQl, sQL + ((wm + lr) * FLD + kc) * 2);
#pragma unroll
            for (int g = 0; g < 4; g++)
                ldsm4(kf[g], cK + ((g * 16 + lr) * FLD + kc) * 2);
#pragma unroll
            for (int nt = 0; nt < 8; nt++) {
                const uint32_t b0 = kf[nt >> 1][nt & 1], b1 = kf[nt >> 1][(nt & 1) + 2];
                mmah(sc[nt], aQh, b0, b1);
                mmah(sc[nt], aQl, b0, b1);
            }
        }

        if (j >= 2 * qt) {
            const int c0 = j * 64 + ((lane & 3) << 1);
#pragma unroll
            for (int nt = 0; nt < 8; nt++) {
                const int gc = c0 + nt * 8;
                if (gc > grow0)     sc[nt][0] = -1e30f;
                if (gc + 1 > grow0) sc[nt][1] = -1e30f;
                if (gc > grow1)     sc[nt][2] = -1e30f;
                if (gc + 1 > grow1) sc[nt][3] = -1e30f;
            }
        }
        float mx0 = -1e30f, mx1 = -1e30f;
#pragma unroll
        for (int nt = 0; nt < 8; nt++) {
            mx0 = fmaxf(mx0, fmaxf(sc[nt][0], sc[nt][1]));
            mx1 = fmaxf(mx1, fmaxf(sc[nt][2], sc[nt][3]));
        }
        mx0 = fmaxf(mx0, __shfl_xor_sync(0xffffffffu, mx0, 1));
        mx0 = fmaxf(mx0, __shfl_xor_sync(0xffffffffu, mx0, 2));
        mx1 = fmaxf(mx1, __shfl_xor_sync(0xffffffffu, mx1, 1));
        mx1 = fmaxf(mx1, __shfl_xor_sync(0xffffffffu, mx1, 2));
        const float mn0 = fmaxf(m0, mx0), mn1 = fmaxf(m1, mx1);
        const float al0 = __expf(m0 - mn0), al1 = __expf(m1 - mn1);
        float ls0 = 0.f, ls1 = 0.f;
#pragma unroll
        for (int nt = 0; nt < 8; nt++) {
            sc[nt][0] = __expf(sc[nt][0] - mn0);
            sc[nt][1] = __expf(sc[nt][1] - mn0);
            sc[nt][2] = __expf(sc[nt][2] - mn1);
            sc[nt][3] = __expf(sc[nt][3] - mn1);
            ls0 += sc[nt][0] + sc[nt][1];
            ls1 += sc[nt][2] + sc[nt][3];
        }
        ls0 += __shfl_xor_sync(0xffffffffu, ls0, 1);
        ls0 += __shfl_xor_sync(0xffffffffu, ls0, 2);
        ls1 += __shfl_xor_sync(0xffffffffu, ls1, 1);
        ls1 += __shfl_xor_sync(0xffffffffu, ls1, 2);
        l0 = l0 * al0 + ls0; m0 = mn0;
        l1 = l1 * al1 + ls1; m1 = mn1;
#pragma unroll
        for (int nt = 0; nt < 16; nt++) {
            Oacc[nt][0] *= al0; Oacc[nt][1] *= al0;
            Oacc[nt][2] *= al1; Oacc[nt][3] *= al1;
        }

#pragma unroll
        for (int ks = 0; ks < 4; ks++) {
            uint32_t aPh[4], aPl[4];
            {
                const float p0 = sc[2 * ks][0],     p1 = sc[2 * ks][1];
                const float p2 = sc[2 * ks][2],     p3 = sc[2 * ks][3];
                const float p4 = sc[2 * ks + 1][0], p5 = sc[2 * ks + 1][1];
                const float p6 = sc[2 * ks + 1][2], p7 = sc[2 * ks + 1][3];
                aPh[0] = packh2(p0, p1);
                aPh[1] = packh2(p2, p3);
                aPh[2] = packh2(p4, p5);
                aPh[3] = packh2(p6, p7);
                aPl[0] = packh2(p0 - __half2float(__float2half_rn(p0)),
                                p1 - __half2float(__float2half_rn(p1)));
                aPl[1] = packh2(p2 - __half2float(__float2half_rn(p2)),
                                p3 - __half2float(__float2half_rn(p3)));
                aPl[2] = packh2(p4 - __half2float(__float2half_rn(p4)),
                                p5 - __half2float(__float2half_rn(p5)));
                aPl[3] = packh2(p6 - __half2float(__float2half_rn(p6)),
                                p7 - __half2float(__float2half_rn(p7)));
            }
#pragma unroll
            for (int ng = 0; ng < 8; ng++) {
                uint32_t bv[4];
                const uint32_t va = ((ks * 16 + lr) * FLD + ng * 16 + lcg) * 2;
                ldsm4t(bv, cV + va);
                mmah(Oacc[2 * ng], aPh, bv[0], bv[1]);
                mmah(Oacc[2 * ng], aPl, bv[0], bv[1]);
                mmah(Oacc[2 * ng + 1], aPh, bv[2], bv[3]);
                mmah(Oacc[2 * ng + 1], aPl, bv[2], bv[3]);
            }
        }
        __syncthreads();
    }

    const float inv0 = 1.0f / l0, inv1 = 1.0f / l1;
    const size_t rb0 = ((size_t)(b * T_) + grow0) * ATTN_ + h * D_;
    const size_t rb1 = ((size_t)(b * T_) + grow1) * ATTN_ + h * D_;
    const int nn = (lane & 3) << 1;
#pragma unroll
    for (int nt = 0; nt < 16; nt++) {
        const int col = nt * 8 + nn;
        *(__half2*)(Y + rb0 + col) = __halves2half2(
            __float2half_rn(Oacc[nt][0] * inv0), __float2half_rn(Oacc[nt][1] * inv0));
        *(__half2*)(Y + rb1 + col) = __halves2half2(
            __float2half_rn(Oacc[nt][2] * inv1), __float2half_rn(Oacc[nt][3] * inv1));
    }
}

// ---------------------------------------------------------------------------
// Host side. Order: 0 rope, 1 conv_x, 2 conv_w, 3 qkv, 4 flash, 5 out.
// ---------------------------------------------------------------------------
extern "C" void kernel_launch(void* const* d_in, const int* in_sizes, int n_in,
                              void* d_out, int out_size)
{
    const float* x    = (const float*)d_in[0];
    const float* wq_w = (const float*)d_in[3];
    const float* wq_b = (const float*)d_in[4];
    const float* wk_w = (const float*)d_in[5];
    const float* wk_b = (const float*)d_in[6];
    const float* wv_w = (const float*)d_in[7];
    const float* wv_b = (const float*)d_in[8];
    const float* wo_w = (const float*)d_in[9];
    const float* wo_b = (const float*)d_in[10];
    float* out = (float*)d_out;

    float *cosp, *sinp;
    __half *xp, *wp, *qh, *ql, *kp, *vp, *yp;
    cudaGetSymbolAddress((void**)&cosp, g_cosT);
    cudaGetSymbolAddress((void**)&sinp, g_sinT);
    cudaGetSymbolAddress((void**)&xp, g_x);
    cudaGetSymbolAddress((void**)&wp, g_w);
    cudaGetSymbolAddress((void**)&qh, g_qh);
    cudaGetSymbolAddress((void**)&ql, g_ql);
    cudaGetSymbolAddress((void**)&kp, g_k);
    cudaGetSymbolAddress((void**)&vp, g_v);
    cudaGetSymbolAddress((void**)&yp, g_y);

    const size_t WSZ = (size_t)ATTN_ * ATTN_;

    rope_table_kernel<<<T_, 64>>>(cosp, sinp);
    const int n4x = BT_ * ATTN_ / 4;
    conv_x_kernel<<<n4x / 256, 256>>>((const float4*)x, (__half2*)xp, n4x);
    const int n4w = ATTN_ * ATTN_ / 4;
    conv_w_kernel<<<dim3(n4w / 256, 1, 4), 256>>>(wq_w, wk_w, wv_w, wo_w,
                                                  (__half2*)wp, n4w);

    cudaFuncSetAttribute(qkv_gemm, cudaFuncAttributeMaxDynamicSharedMemorySize, GSMEM);
    cudaFuncSetAttribute(out_gemm, cudaFuncAttributeMaxDynamicSharedMemorySize, GSMEM);
    cudaFuncSetAttribute(flash_mma, cudaFuncAttributeMaxDynamicSharedMemorySize, FSMEM);

    qkv_gemm<<<dim3(48, BT_ / GBM), GTH, GSMEM>>>(xp, wp,
                                                  wq_b, wk_b, wv_b,
                                                  qh, ql, kp, vp,
                                                  cosp, sinp);
    flash_mma<<<dim3(T_ / 128, H_, B_), 256, FSMEM>>>(qh, ql, kp, vp, yp);

    out_gemm<<<dim3(ATTN_ / GBN, BT_ / GBM), GTH, GSMEM>>>(yp, wp + 3 * WSZ,
                                                           wo_b, out);
}

// round 14
// speedup vs baseline: 4.4570x; 1.2388x over previous
#include <cuda_runtime.h>
#include <cuda_fp16.h>
#include <math.h>
#include <stdint.h>

#define B_    4
#define T_    2048
#define H_    16
#define D_    128
#define ATTN_ 2048
#define BT_   (B_*T_)

// ---------------------------------------------------------------------------
// Scratch, all fp16. x single plane, W single plane (concat 0=wq 1=wk 2=wv 3=wo),
// Q hi/lo (flash precision), K/V single, y single.
// ---------------------------------------------------------------------------
__device__ __half g_x[(size_t)BT_ * ATTN_];
__device__ __half g_w[(size_t)4 * ATTN_ * ATTN_];
__device__ __half g_qh[(size_t)BT_ * ATTN_];
__device__ __half g_ql[(size_t)BT_ * ATTN_];
__device__ __half g_k[(size_t)BT_ * ATTN_];
__device__ __half g_v[(size_t)BT_ * ATTN_];
__device__ __half g_y[(size_t)BT_ * ATTN_];
__device__ float g_cosT[T_ * 64];
__device__ float g_sinT[T_ * 64];

// ---------------------------------------------------------------------------
// PTX helpers
// ---------------------------------------------------------------------------
__device__ __forceinline__ uint32_t smem_u32(const void* p) {
    uint32_t a;
    asm("{ .reg .u64 t; cvta.to.shared.u64 t, %1; cvt.u32.u64 %0, t; }" : "=r"(a) : "l"(p));
    return a;
}

#define CP_ASYNC16(dst, src) \
    asm volatile("cp.async.cg.shared.global [%0], [%1], 16;" :: "r"(dst), "l"(src))
#define CP_COMMIT() asm volatile("cp.async.commit_group;" ::: "memory")
#define CP_WAIT(n)  asm volatile("cp.async.wait_group %0;" :: "n"(n) : "memory")

__device__ __forceinline__ void ldsm4(uint32_t* r, uint32_t addr) {
    asm volatile("ldmatrix.sync.aligned.m8n8.x4.shared.b16 {%0,%1,%2,%3}, [%4];"
                 : "=r"(r[0]), "=r"(r[1]), "=r"(r[2]), "=r"(r[3]) : "r"(addr));
}
__device__ __forceinline__ void ldsm4t(uint32_t* r, uint32_t addr) {
    asm volatile("ldmatrix.sync.aligned.m8n8.x4.trans.shared.b16 {%0,%1,%2,%3}, [%4];"
                 : "=r"(r[0]), "=r"(r[1]), "=r"(r[2]), "=r"(r[3]) : "r"(addr));
}

__device__ __forceinline__ void mmah(float* c, const uint32_t* a,
                                     uint32_t b0, uint32_t b1) {
    asm volatile(
        "mma.sync.aligned.m16n8k16.row.col.f32.f16.f16.f32 "
        "{%0,%1,%2,%3}, {%4,%5,%6,%7}, {%8,%9}, {%0,%1,%2,%3};"
        : "+f"(c[0]), "+f"(c[1]), "+f"(c[2]), "+f"(c[3])
        : "r"(a[0]), "r"(a[1]), "r"(a[2]), "r"(a[3]), "r"(b0), "r"(b1));
}

__device__ __forceinline__ uint32_t packh2(float a, float b) {
    __half2 t = __halves2half2(__float2half_rn(a), __float2half_rn(b));
    return *(uint32_t*)&t;
}

// ---------------------------------------------------------------------------
// Elementwise kernels
// ---------------------------------------------------------------------------
__global__ void rope_table_kernel(float* __restrict__ cosT, float* __restrict__ sinT) {
    const int t = blockIdx.x;
    const int i = threadIdx.x;
    const float kFreq = 0.07195578415606394f;  // ln(10000)/128
    const float inv = expf((float)(2 * i) * -kFreq);
    const float ang = (float)t * inv;
    float s, c;
    sincosf(ang, &s, &c);
    cosT[t * 64 + i] = c;
    sinT[t * 64 + i] = s;
}

__global__ void conv_x_kernel(const float4* __restrict__ src,
                              __half2* __restrict__ dst, int n4) {
    int i = blockIdx.x * blockDim.x + threadIdx.x;
    if (i >= n4) return;
    float4 v = src[i];
    dst[2 * i]     = __halves2half2(__float2half_rn(v.x), __float2half_rn(v.y));
    dst[2 * i + 1] = __halves2half2(__float2half_rn(v.z), __float2half_rn(v.w));
}

__global__ void conv_w_kernel(const float* __restrict__ w0, const float* __restrict__ w1,
                              const float* __restrict__ w2, const float* __restrict__ w3,
                              __half2* __restrict__ dst, int n4) {
    int i = blockIdx.x * blockDim.x + threadIdx.x;
    if (i >= n4) return;
    const int z = blockIdx.z;
    const float* src = (z == 0) ? w0 : (z == 1) ? w1 : (z == 2) ? w2 : w3;
    float4 v = ((const float4*)src)[i];
    const size_t off = (size_t)z * n4 * 2;
    dst[off + 2 * i]     = __halves2half2(__float2half_rn(v.x), __float2half_rn(v.y));
    dst[off + 2 * i + 1] = __halves2half2(__float2half_rn(v.z), __float2half_rn(v.w));
}

// ---------------------------------------------------------------------------
// fp16 1-term GEMM core v2: CTA 128x256, 8 warps (2Mx4N), warp tile 64x64.
// BK=64, 2-stage cp.async. smem: A 18 KB + W 36 KB per stage -> 108 KB total.
// 4 mma per ldsm (vs 2.67 at 64x32).
// ---------------------------------------------------------------------------
static constexpr int GBM = 128, GBN = 256, GBK = 64;
static constexpr int LDSE = 72;
static constexpr int A_B  = 128 * 144;          // 18432 B
static constexpr int W_B  = 256 * 144;          // 36864 B
static constexpr int STB  = A_B + W_B;          // 55296 B
static constexpr int GSMEM = 2 * STB;           // 110592 B
static constexpr int GTH = 256;

struct GemmCoreF16 {
    __device__ static __forceinline__ void run(
        uint32_t sBase, float (&acc)[4][8][4],
        const __half* gA, const __half* gW,
        int tid, int wm, int wn, int lr, int lc)
    {
        const int cc = tid & 7;        // 16B chunk within 128B row
        const int rb = tid >> 3;       // 0..31
        const int NIT = ATTN_ / GBK;   // 32

        auto load_stage = [&](uint32_t st, int k0) {
#pragma unroll
            for (int bb = 0; bb < 4; bb++) {
                const int r = bb * 32 + rb;
                const uint32_t so = r * 144 + cc * 16;
                const size_t go = (size_t)r * ATTN_ + k0 + cc * 8;
                CP_ASYNC16(st + so, gA + go);
            }
#pragma unroll
            for (int bb = 0; bb < 8; bb++) {
                const int r = bb * 32 + rb;
                const uint32_t so = r * 144 + cc * 16;
                const size_t go = (size_t)r * ATTN_ + k0 + cc * 8;
                CP_ASYNC16(st + A_B + so, gW + go);
            }
            CP_COMMIT();
        };

        load_stage(sBase, 0);

        for (int kt = 0; kt < NIT; kt++) {
            if (kt + 1 < NIT) {
                load_stage(sBase + ((kt + 1) & 1) * STB, (kt + 1) * GBK);
                CP_WAIT(1);
            } else {
                CP_WAIT(0);
            }
            __syncthreads();

            const uint32_t st = sBase + (kt & 1) * STB;
            const uint32_t sA = st;
            const uint32_t sW = st + A_B;

#pragma unroll
            for (int ks = 0; ks < 4; ks++) {
                const int kc = ks * 16 + lc;
                uint32_t af[4][4], wf[4][4];
#pragma unroll
                for (int mt = 0; mt < 4; mt++)
                    ldsm4(af[mt], sA + ((wm + mt * 16 + lr) * LDSE + kc) * 2);
#pragma unroll
                for (int g = 0; g < 4; g++)
                    ldsm4(wf[g], sW + ((wn + g * 16 + lr) * LDSE + kc) * 2);

#pragma unroll
                for (int mt = 0; mt < 4; mt++)
#pragma unroll
                    for (int nt = 0; nt < 8; nt++)
                        mmah(acc[mt][nt], af[mt], wf[nt >> 1][nt & 1], wf[nt >> 1][(nt & 1) + 2]);
            }
            __syncthreads();
        }
    }
};

// ---------------------------------------------------------------------------
// Fused QKV projection GEMM. grid (24, 64). blockIdx.x>>3 : 0=Q,1=K,2=V.
// Q out: fp16 hi/lo planes. K,V out: single fp16 plane.
// ---------------------------------------------------------------------------
__global__ void __launch_bounds__(GTH, 1) qkv_gemm(
    const __half* __restrict__ X, const __half* __restrict__ W,
    const float* __restrict__ bq, const float* __restrict__ bk, const float* __restrict__ bv,
    __half* __restrict__ QH, __half* __restrict__ QL,
    __half* __restrict__ KK, __half* __restrict__ VV,
    const float* __restrict__ cosT, const float* __restrict__ sinT)
{
    extern __shared__ char dsm[];
    const uint32_t sBase = smem_u32(dsm);

    const int tid  = threadIdx.x;
    const int wid  = tid >> 5;
    const int lane = tid & 31;
    const int wm   = (wid >> 2) * 64;
    const int wn   = (wid & 3) * 64;
    const int bm   = blockIdx.y * GBM;
    const int qkv  = blockIdx.x >> 3;
    const int bnl  = (blockIdx.x & 7) * GBN;
    const int bng  = blockIdx.x * GBN;

    float acc[4][8][4];
#pragma unroll
    for (int mt = 0; mt < 4; mt++)
#pragma unroll
        for (int nt = 0; nt < 8; nt++)
#pragma unroll
            for (int e = 0; e < 4; e++) acc[mt][nt][e] = 0.f;

    GemmCoreF16::run(sBase, acc,
                     X + (size_t)bm * ATTN_, W + (size_t)bng * ATTN_,
                     tid, wm, wn, lane & 15, (lane >> 4) << 3);

    const float* bias = (qkv == 0) ? bq : (qkv == 1) ? bk : bv;
    const bool rope  = (qkv != 2);
    const bool scale = (qkv == 0);
    const float qscale = 0.08838834764831843f;

    const int rr = lane >> 2;
    const int nn = (lane & 3) * 2;
#pragma unroll
    for (int mt = 0; mt < 4; mt++) {
#pragma unroll
        for (int half_ = 0; half_ < 2; half_++) {
            const int m = bm + wm + mt * 16 + rr + half_ * 8;
            const int pos = m & (T_ - 1);
#pragma unroll
            for (int nt = 0; nt < 8; nt++) {
                const int n0 = bnl + wn + nt * 8 + nn;
                float v0 = acc[mt][nt][half_ * 2 + 0] + __ldg(&bias[n0]);
                float v1 = acc[mt][nt][half_ * 2 + 1] + __ldg(&bias[n0 + 1]);
                if (rope) {
                    const int pi = (n0 & (D_ - 1)) >> 1;
                    const float cv = __ldg(&cosT[pos * 64 + pi]);
                    const float sv = __ldg(&sinT[pos * 64 + pi]);
                    const float t1 = v0, t2 = v1;
                    v0 = t1 * cv - t2 * sv;
                    v1 = t1 * sv + t2 * cv;
                }
                if (scale) { v0 *= qscale; v1 *= qscale; }
                const size_t off = (size_t)m * ATTN_ + n0;
                if (qkv == 0) {
                    const __half h0 = __float2half_rn(v0), h1 = __float2half_rn(v1);
                    *(__half2*)(QH + off) = __halves2half2(h0, h1);
                    *(__half2*)(QL + off) = __halves2half2(
                        __float2half_rn(v0 - __half2float(h0)),
                        __float2half_rn(v1 - __half2float(h1)));
                } else {
                    __half* C = (qkv == 1) ? KK : VV;
                    *(__half2*)(C + off) = __halves2half2(__float2half_rn(v0),
                                                          __float2half_rn(v1));
                }
            }
        }
    }
}

// ---------------------------------------------------------------------------
// Output projection GEMM: fp32 out + bias. grid (8, 64).
// ---------------------------------------------------------------------------
__global__ void __launch_bounds__(GTH, 1) out_gemm(
    const __half* __restrict__ A, const __half* __restrict__ W,
    const float* __restrict__ bias, float* __restrict__ Cf)
{
    extern __shared__ char dsm[];
    const uint32_t sBase = smem_u32(dsm);

    const int tid  = threadIdx.x;
    const int wid  = tid >> 5;
    const int lane = tid & 31;
    const int wm   = (wid >> 2) * 64;
    const int wn   = (wid & 3) * 64;
    const int bm   = blockIdx.y * GBM;
    const int bn   = blockIdx.x * GBN;

    float acc[4][8][4];
#pragma unroll
    for (int mt = 0; mt < 4; mt++)
#pragma unroll
        for (int nt = 0; nt < 8; nt++)
#pragma unroll
            for (int e = 0; e < 4; e++) acc[mt][nt][e] = 0.f;

    GemmCoreF16::run(sBase, acc,
                     A + (size_t)bm * ATTN_, W + (size_t)bn * ATTN_,
                     tid, wm, wn, lane & 15, (lane >> 4) << 3);

    const int rr = lane >> 2;
    const int nn = (lane & 3) * 2;
#pragma unroll
    for (int mt = 0; mt < 4; mt++) {
#pragma unroll
        for (int half_ = 0; half_ < 2; half_++) {
            const int m = bm + wm + mt * 16 + rr + half_ * 8;
#pragma unroll
            for (int nt = 0; nt < 8; nt++) {
                const int n0 = bn + wn + nt * 8 + nn;
                const float v0 = acc[mt][nt][half_ * 2 + 0] + __ldg(&bias[n0]);
                const float v1 = acc[mt][nt][half_ * 2 + 1] + __ldg(&bias[n0 + 1]);
                *(float2*)(Cf + (size_t)m * ATTN_ + n0) = make_float2(v0, v1);
            }
        }
    }
}

// ---------------------------------------------------------------------------
// Tensor-core causal flash attention, fp16 2-term (round-12/13 winner, unchanged).
// ---------------------------------------------------------------------------
static constexpr int FLD = 136;
static constexpr int FQB = 128 * FLD * 2;
static constexpr int FKB = 64 * FLD * 2;
static constexpr int FSTG = 2 * FKB;
static constexpr int FSMEM = 2 * FQB + 2 * FSTG;

__global__ void __launch_bounds__(256, 1) flash_mma(
    const __half* __restrict__ Qh, const __half* __restrict__ Ql,
    const __half* __restrict__ K, const __half* __restrict__ V,
    __half* __restrict__ Y)
{
    extern __shared__ char fsm[];
    const uint32_t sb  = smem_u32(fsm);
    const uint32_t sQH = sb;
    const uint32_t sQL = sb + FQB;
    const uint32_t sKV = sb + 2 * FQB;

    const int qt = blockIdx.x, h = blockIdx.y, b = blockIdx.z;
    const int tid = threadIdx.x, wid = tid >> 5, lane = tid & 31;
    const int wm = wid * 16;
    const int lr = lane & 15;
    const int lcg = (lane >> 4) << 3;

    const int ccf = tid & 15;
    const int r0f = tid >> 4;

    {
        const __half* qh_g = Qh + ((size_t)(b * T_ + qt * 128)) * ATTN_ + h * D_;
        const __half* ql_g = Ql + ((size_t)(b * T_ + qt * 128)) * ATTN_ + h * D_;
#pragma unroll
        for (int bb = 0; bb < 8; bb++) {
            const int r = bb * 16 + r0f;
            const uint32_t so = r * (FLD * 2) + ccf * 16;
            const size_t go = (size_t)r * ATTN_ + ccf * 8;
            CP_ASYNC16(sQH + so, qh_g + go);
            CP_ASYNC16(sQL + so, ql_g + go);
        }
        CP_COMMIT();
    }

    const int nkv = 2 * qt + 2;

    auto issue_kv = [&](int j) {
        const uint32_t st = sKV + (j & 1) * FSTG;
        const size_t base = ((size_t)(b * T_ + j * 64)) * ATTN_ + h * D_;
#pragma unroll
        for (int bb = 0; bb < 4; bb++) {
            const int r = bb * 16 + r0f;
            const uint32_t so = r * (FLD * 2) + ccf * 16;
            const size_t go = base + (size_t)r * ATTN_ + ccf * 8;
            CP_ASYNC16(st + so, K + go);
            CP_ASYNC16(st + FKB + so, V + go);
        }
        CP_COMMIT();
    };

    issue_kv(0);

    float Oacc[16][4];
#pragma unroll
    for (int nt = 0; nt < 16; nt++)
#pragma unroll
        for (int e = 0; e < 4; e++) Oacc[nt][e] = 0.f;
    float m0 = -1e30f, m1 = -1e30f, l0 = 0.f, l1 = 0.f;

    const int grow0 = qt * 128 + wm + (lane >> 2);
    const int grow1 = grow0 + 8;

    for (int j = 0; j < nkv; j++) {
        if (j + 1 < nkv) {
            issue_kv(j + 1);
            CP_WAIT(1);
        } else {
            CP_WAIT(0);
        }
        __syncthreads();

        const uint32_t st = sKV + (j & 1) * FSTG;
        const uint32_t cK = st;
        const uint32_t cV = st + FKB;

        float sc[8][4];
#pragma unroll
        for (int nt = 0; nt < 8; nt++)
#pragma unroll
            for (int e = 0; e < 4; e++) sc[nt][e] = 0.f;

#pragma unroll 2
        for (int ks = 0; ks < 8; ks++) {
            const int kc = ks * 16 + lcg;
            uint32_t aQh[4], aQl[4], kf[4][4];
            ldsm4(aQh, sQH + ((wm + lr) * FLD + kc) * 2);
            ldsm4(aQl, sQL + ((wm + lr) * FLD + kc) * 2);
#pragma unroll
            for (int g = 0; g < 4; g++)
                ldsm4(kf[g], cK + ((g * 16 + lr) * FLD + kc) * 2);
#pragma unroll
            for (int nt = 0; nt < 8; nt++) {
                const uint32_t b0 = kf[nt >> 1][nt & 1], b1 = kf[nt >> 1][(nt & 1) + 2];
                mmah(sc[nt], aQh, b0, b1);
                mmah(sc[nt], aQl, b0, b1);
            }
        }

        if (j >= 2 * qt) {
            const int c0 = j * 64 + ((lane & 3) << 1);
#pragma unroll
            for (int nt = 0; nt < 8; nt++) {
                const int gc = c0 + nt * 8;
                if (gc > grow0)     sc[nt][0] = -1e30f;
                if (gc + 1 > grow0) sc[nt][1] = -1e30f;
                if (gc > grow1)     sc[nt][2] = -1e30f;
                if (gc + 1 > grow1) sc[nt][3] = -1e30f;
            }
        }
        float mx0 = -1e30f, mx1 = -1e30f;
#pragma unroll
        for (int nt = 0; nt < 8; nt++) {
            mx0 = fmaxf(mx0, fmaxf(sc[nt][0], sc[nt][1]));
            mx1 = fmaxf(mx1, fmaxf(sc[nt][2], sc[nt][3]));
        }
        mx0 = fmaxf(mx0, __shfl_xor_sync(0xffffffffu, mx0, 1));
        mx0 = fmaxf(mx0, __shfl_xor_sync(0xffffffffu, mx0, 2));
        mx1 = fmaxf(mx1, __shfl_xor_sync(0xffffffffu, mx1, 1));
        mx1 = fmaxf(mx1, __shfl_xor_sync(0xffffffffu, mx1, 2));
        const float mn0 = fmaxf(m0, mx0), mn1 = fmaxf(m1, mx1);
        const float al0 = __expf(m0 - mn0), al1 = __expf(m1 - mn1);
        float ls0 = 0.f, ls1 = 0.f;
#pragma unroll
        for (int nt = 0; nt < 8; nt++) {
            sc[nt][0] = __expf(sc[nt][0] - mn0);
            sc[nt][1] = __expf(sc[nt][1] - mn0);
            sc[nt][2] = __expf(sc[nt][2] - mn1);
            sc[nt][3] = __expf(sc[nt][3] - mn1);
            ls0 += sc[nt][0] + sc[nt][1];
            ls1 += sc[nt][2] + sc[nt][3];
        }
        ls0 += __shfl_xor_sync(0xffffffffu, ls0, 1);
        ls0 += __shfl_xor_sync(0xffffffffu, ls0, 2);
        ls1 += __shfl_xor_sync(0xffffffffu, ls1, 1);
        ls1 += __shfl_xor_sync(0xffffffffu, ls1, 2);
        l0 = l0 * al0 + ls0; m0 = mn0;
        l1 = l1 * al1 + ls1; m1 = mn1;
#pragma unroll
        for (int nt = 0; nt < 16; nt++) {
            Oacc[nt][0] *= al0; Oacc[nt][1] *= al0;
            Oacc[nt][2] *= al1; Oacc[nt][3] *= al1;
        }

#pragma unroll
        for (int ks = 0; ks < 4; ks++) {
            uint32_t aPh[4], aPl[4];
            {
                const float p0 = sc[2 * ks][0],     p1 = sc[2 * ks][1];
                const float p2 = sc[2 * ks][2],     p3 = sc[2 * ks][3];
                const float p4 = sc[2 * ks + 1][0], p5 = sc[2 * ks + 1][1];
                const float p6 = sc[2 * ks + 1][2], p7 = sc[2 * ks + 1][3];
                aPh[0] = packh2(p0, p1);
                aPh[1] = packh2(p2, p3);
                aPh[2] = packh2(p4, p5);
                aPh[3] = packh2(p6, p7);
                aPl[0] = packh2(p0 - __half2float(__float2half_rn(p0)),
                                p1 - __half2float(__float2half_rn(p1)));
                aPl[1] = packh2(p2 - __half2float(__float2half_rn(p2)),
                                p3 - __half2float(__float2half_rn(p3)));
                aPl[2] = packh2(p4 - __half2float(__float2half_rn(p4)),
                                p5 - __half2float(__float2half_rn(p5)));
                aPl[3] = packh2(p6 - __half2float(__float2half_rn(p6)),
                                p7 - __half2float(__float2half_rn(p7)));
            }
#pragma unroll
            for (int ng = 0; ng < 8; ng++) {
                uint32_t bv[4];
                const uint32_t va = ((ks * 16 + lr) * FLD + ng * 16 + lcg) * 2;
                ldsm4t(bv, cV + va);
                mmah(Oacc[2 * ng], aPh, bv[0], bv[1]);
                mmah(Oacc[2 * ng], aPl, bv[0], bv[1]);
                mmah(Oacc[2 * ng + 1], aPh, bv[2], bv[3]);
                mmah(Oacc[2 * ng + 1], aPl, bv[2], bv[3]);
            }
        }
        __syncthreads();
    }

    const float inv0 = 1.0f / l0, inv1 = 1.0f / l1;
    const size_t rb0 = ((size_t)(b * T_) + grow0) * ATTN_ + h * D_;
    const size_t rb1 = ((size_t)(b * T_) + grow1) * ATTN_ + h * D_;
    const int nn = (lane & 3) << 1;
#pragma unroll
    for (int nt = 0; nt < 16; nt++) {
        const int col = nt * 8 + nn;
        *(__half2*)(Y + rb0 + col) = __halves2half2(
            __float2half_rn(Oacc[nt][0] * inv0), __float2half_rn(Oacc[nt][1] * inv0));
        *(__half2*)(Y + rb1 + col) = __halves2half2(
            __float2half_rn(Oacc[nt][2] * inv1), __float2half_rn(Oacc[nt][3] * inv1));
    }
}

// ---------------------------------------------------------------------------
// Host side. Order: 0 rope, 1 conv_x, 2 conv_w, 3 qkv, 4 flash, 5 out.
// ---------------------------------------------------------------------------
extern "C" void kernel_launch(void* const* d_in, const int* in_sizes, int n_in,
                              void* d_out, int out_size)
{
    const float* x    = (const float*)d_in[0];
    const float* wq_w = (const float*)d_in[3];
    const float* wq_b = (const float*)d_in[4];
    const float* wk_w = (const float*)d_in[5];
    const float* wk_b = (const float*)d_in[6];
    const float* wv_w = (const float*)d_in[7];
    const float* wv_b = (const float*)d_in[8];
    const float* wo_w = (const float*)d_in[9];
    const float* wo_b = (const float*)d_in[10];
    float* out = (float*)d_out;

    float *cosp, *sinp;
    __half *xp, *wp, *qh, *ql, *kp, *vp, *yp;
    cudaGetSymbolAddress((void**)&cosp, g_cosT);
    cudaGetSymbolAddress((void**)&sinp, g_sinT);
    cudaGetSymbolAddress((void**)&xp, g_x);
    cudaGetSymbolAddress((void**)&wp, g_w);
    cudaGetSymbolAddress((void**)&qh, g_qh);
    cudaGetSymbolAddress((void**)&ql, g_ql);
    cudaGetSymbolAddress((void**)&kp, g_k);
    cudaGetSymbolAddress((void**)&vp, g_v);
    cudaGetSymbolAddress((void**)&yp, g_y);

    const size_t WSZ = (size_t)ATTN_ * ATTN_;

    rope_table_kernel<<<T_, 64>>>(cosp, sinp);
    const int n4x = BT_ * ATTN_ / 4;
    conv_x_kernel<<<n4x / 256, 256>>>((const float4*)x, (__half2*)xp, n4x);
    const int n4w = ATTN_ * ATTN_ / 4;
    conv_w_kernel<<<dim3(n4w / 256, 1, 4), 256>>>(wq_w, wk_w, wv_w, wo_w,
                                                  (__half2*)wp, n4w);

    cudaFuncSetAttribute(qkv_gemm, cudaFuncAttributeMaxDynamicSharedMemorySize, GSMEM);
    cudaFuncSetAttribute(out_gemm, cudaFuncAttributeMaxDynamicSharedMemorySize, GSMEM);
    cudaFuncSetAttribute(flash_mma, cudaFuncAttributeMaxDynamicSharedMemorySize, FSMEM);

    qkv_gemm<<<dim3(24, BT_ / GBM), GTH, GSMEM>>>(xp, wp,
                                                  wq_b, wk_b, wv_b,
                                                  qh, ql, kp, vp,
                                                  cosp, sinp);
    flash_mma<<<dim3(T_ / 128, H_, B_), 256, FSMEM>>>(qh, ql, kp, vp, yp);

    out_gemm<<<dim3(ATTN_ / GBN, BT_ / GBM), GTH, GSMEM>>>(yp, wp + 3 * WSZ,
                                                           wo_b, out);
}

// round 15
// speedup vs baseline: 4.8627x; 1.0910x over previous
#include <cuda_runtime.h>
#include <cuda_fp16.h>
#include <math.h>
#include <stdint.h>

#define B_    4
#define T_    2048
#define H_    16
#define D_    128
#define ATTN_ 2048
#define BT_   (B_*T_)

// ---------------------------------------------------------------------------
// Scratch, all fp16 single-plane except P (in-register hi/lo):
// x, W (concat 0=wq 1=wk 2=wv 3=wo), Q, K, V, y.
// ---------------------------------------------------------------------------
__device__ __half g_x[(size_t)BT_ * ATTN_];
__device__ __half g_w[(size_t)4 * ATTN_ * ATTN_];
__device__ __half g_q[(size_t)BT_ * ATTN_];
__device__ __half g_k[(size_t)BT_ * ATTN_];
__device__ __half g_v[(size_t)BT_ * ATTN_];
__device__ __half g_y[(size_t)BT_ * ATTN_];
__device__ float g_cosT[T_ * 64];
__device__ float g_sinT[T_ * 64];

// ---------------------------------------------------------------------------
// PTX helpers
// ---------------------------------------------------------------------------
__device__ __forceinline__ uint32_t smem_u32(const void* p) {
    uint32_t a;
    asm("{ .reg .u64 t; cvta.to.shared.u64 t, %1; cvt.u32.u64 %0, t; }" : "=r"(a) : "l"(p));
    return a;
}

#define CP_ASYNC16(dst, src) \
    asm volatile("cp.async.cg.shared.global [%0], [%1], 16;" :: "r"(dst), "l"(src))
#define CP_COMMIT() asm volatile("cp.async.commit_group;" ::: "memory")
#define CP_WAIT(n)  asm volatile("cp.async.wait_group %0;" :: "n"(n) : "memory")

__device__ __forceinline__ void ldsm4(uint32_t* r, uint32_t addr) {
    asm volatile("ldmatrix.sync.aligned.m8n8.x4.shared.b16 {%0,%1,%2,%3}, [%4];"
                 : "=r"(r[0]), "=r"(r[1]), "=r"(r[2]), "=r"(r[3]) : "r"(addr));
}
__device__ __forceinline__ void ldsm4t(uint32_t* r, uint32_t addr) {
    asm volatile("ldmatrix.sync.aligned.m8n8.x4.trans.shared.b16 {%0,%1,%2,%3}, [%4];"
                 : "=r"(r[0]), "=r"(r[1]), "=r"(r[2]), "=r"(r[3]) : "r"(addr));
}

__device__ __forceinline__ void mmah(float* c, const uint32_t* a,
                                     uint32_t b0, uint32_t b1) {
    asm volatile(
        "mma.sync.aligned.m16n8k16.row.col.f32.f16.f16.f32 "
        "{%0,%1,%2,%3}, {%4,%5,%6,%7}, {%8,%9}, {%0,%1,%2,%3};"
        : "+f"(c[0]), "+f"(c[1]), "+f"(c[2]), "+f"(c[3])
        : "r"(a[0]), "r"(a[1]), "r"(a[2]), "r"(a[3]), "r"(b0), "r"(b1));
}

__device__ __forceinline__ uint32_t packh2(float a, float b) {
    __half2 t = __halves2half2(__float2half_rn(a), __float2half_rn(b));
    return *(uint32_t*)&t;
}

// ---------------------------------------------------------------------------
// Elementwise kernels
// ---------------------------------------------------------------------------
__global__ void rope_table_kernel(float* __restrict__ cosT, float* __restrict__ sinT) {
    const int t = blockIdx.x;
    const int i = threadIdx.x;
    const float kFreq = 0.07195578415606394f;  // ln(10000)/128
    const float inv = expf((float)(2 * i) * -kFreq);
    const float ang = (float)t * inv;
    float s, c;
    sincosf(ang, &s, &c);
    cosT[t * 64 + i] = c;
    sinT[t * 64 + i] = s;
}

__global__ void conv_x_kernel(const float4* __restrict__ src,
                              __half2* __restrict__ dst, int n4) {
    int i = blockIdx.x * blockDim.x + threadIdx.x;
    if (i >= n4) return;
    float4 v = src[i];
    dst[2 * i]     = __halves2half2(__float2half_rn(v.x), __float2half_rn(v.y));
    dst[2 * i + 1] = __halves2half2(__float2half_rn(v.z), __float2half_rn(v.w));
}

__global__ void conv_w_kernel(const float* __restrict__ w0, const float* __restrict__ w1,
                              const float* __restrict__ w2, const float* __restrict__ w3,
                              __half2* __restrict__ dst, int n4) {
    int i = blockIdx.x * blockDim.x + threadIdx.x;
    if (i >= n4) return;
    const int z = blockIdx.z;
    const float* src = (z == 0) ? w0 : (z == 1) ? w1 : (z == 2) ? w2 : w3;
    float4 v = ((const float4*)src)[i];
    const size_t off = (size_t)z * n4 * 2;
    dst[off + 2 * i]     = __halves2half2(__float2half_rn(v.x), __float2half_rn(v.y));
    dst[off + 2 * i + 1] = __halves2half2(__float2half_rn(v.z), __float2half_rn(v.w));
}

// ---------------------------------------------------------------------------
// fp16 1-term GEMM core v3: CTA 128x256, warp tile 64x64, BK=64, 3-stage.
// smem 3 x 55296 = 165888 B.
// ---------------------------------------------------------------------------
static constexpr int GBM = 128, GBN = 256, GBK = 64;
static constexpr int LDSE = 72;
static constexpr int A_B  = 128 * 144;          // 18432 B
static constexpr int W_B  = 256 * 144;          // 36864 B
static constexpr int STB  = A_B + W_B;          // 55296 B
static constexpr int GSMEM = 3 * STB;           // 165888 B
static constexpr int GTH = 256;

struct GemmCoreF16 {
    __device__ static __forceinline__ void run(
        uint32_t sBase, float (&acc)[4][8][4],
        const __half* gA, const __half* gW,
        int tid, int wm, int wn, int lr, int lc)
    {
        const int cc = tid & 7;
        const int rb = tid >> 3;
        const int NIT = ATTN_ / GBK;   // 32

        auto load_stage = [&](uint32_t st, int k0) {
#pragma unroll
            for (int bb = 0; bb < 4; bb++) {
                const int r = bb * 32 + rb;
                const uint32_t so = r * 144 + cc * 16;
                const size_t go = (size_t)r * ATTN_ + k0 + cc * 8;
                CP_ASYNC16(st + so, gA + go);
            }
#pragma unroll
            for (int bb = 0; bb < 8; bb++) {
                const int r = bb * 32 + rb;
                const uint32_t so = r * 144 + cc * 16;
                const size_t go = (size_t)r * ATTN_ + k0 + cc * 8;
                CP_ASYNC16(st + A_B + so, gW + go);
            }
            CP_COMMIT();
        };

        load_stage(sBase, 0);
        load_stage(sBase + STB, GBK);

        int s = 0;                     // stage index = kt % 3
        for (int kt = 0; kt < NIT; kt++) {
            if (kt + 2 < NIT) {
                int s2 = s + 2; if (s2 >= 3) s2 -= 3;
                load_stage(sBase + s2 * STB, (kt + 2) * GBK);
                CP_WAIT(2);
            } else if (kt + 1 < NIT) {
                CP_WAIT(1);
            } else {
                CP_WAIT(0);
            }
            __syncthreads();

            const uint32_t st = sBase + s * STB;
            const uint32_t sA = st;
            const uint32_t sW = st + A_B;

#pragma unroll
            for (int ks = 0; ks < 4; ks++) {
                const int kc = ks * 16 + lc;
                uint32_t af[4][4], wf[4][4];
#pragma unroll
                for (int mt = 0; mt < 4; mt++)
                    ldsm4(af[mt], sA + ((wm + mt * 16 + lr) * LDSE + kc) * 2);
#pragma unroll
                for (int g = 0; g < 4; g++)
                    ldsm4(wf[g], sW + ((wn + g * 16 + lr) * LDSE + kc) * 2);

#pragma unroll
                for (int mt = 0; mt < 4; mt++)
#pragma unroll
                    for (int nt = 0; nt < 8; nt++)
                        mmah(acc[mt][nt], af[mt], wf[nt >> 1][nt & 1], wf[nt >> 1][(nt & 1) + 2]);
            }
            __syncthreads();
            if (++s == 3) s = 0;
        }
    }
};

// ---------------------------------------------------------------------------
// Fused QKV projection GEMM. grid (24, 64). blockIdx.x>>3 : 0=Q,1=K,2=V.
// All outputs single fp16 plane.
// ---------------------------------------------------------------------------
__global__ void __launch_bounds__(GTH, 1) qkv_gemm(
    const __half* __restrict__ X, const __half* __restrict__ W,
    const float* __restrict__ bq, const float* __restrict__ bk, const float* __restrict__ bv,
    __half* __restrict__ QQ, __half* __restrict__ KK, __half* __restrict__ VV,
    const float* __restrict__ cosT, const float* __restrict__ sinT)
{
    extern __shared__ char dsm[];
    const uint32_t sBase = smem_u32(dsm);

    const int tid  = threadIdx.x;
    const int wid  = tid >> 5;
    const int lane = tid & 31;
    const int wm   = (wid >> 2) * 64;
    const int wn   = (wid & 3) * 64;
    const int bm   = blockIdx.y * GBM;
    const int qkv  = blockIdx.x >> 3;
    const int bnl  = (blockIdx.x & 7) * GBN;
    const int bng  = blockIdx.x * GBN;

    float acc[4][8][4];
#pragma unroll
    for (int mt = 0; mt < 4; mt++)
#pragma unroll
        for (int nt = 0; nt < 8; nt++)
#pragma unroll
            for (int e = 0; e < 4; e++) acc[mt][nt][e] = 0.f;

    GemmCoreF16::run(sBase, acc,
                     X + (size_t)bm * ATTN_, W + (size_t)bng * ATTN_,
                     tid, wm, wn, lane & 15, (lane >> 4) << 3);

    const float* bias = (qkv == 0) ? bq : (qkv == 1) ? bk : bv;
    __half* C = (qkv == 0) ? QQ : (qkv == 1) ? KK : VV;
    const bool rope  = (qkv != 2);
    const bool scale = (qkv == 0);
    const float qscale = 0.08838834764831843f;

    const int rr = lane >> 2;
    const int nn = (lane & 3) * 2;
#pragma unroll
    for (int mt = 0; mt < 4; mt++) {
#pragma unroll
        for (int half_ = 0; half_ < 2; half_++) {
            const int m = bm + wm + mt * 16 + rr + half_ * 8;
            const int pos = m & (T_ - 1);
#pragma unroll
            for (int nt = 0; nt < 8; nt++) {
                const int n0 = bnl + wn + nt * 8 + nn;
                float v0 = acc[mt][nt][half_ * 2 + 0] + __ldg(&bias[n0]);
                float v1 = acc[mt][nt][half_ * 2 + 1] + __ldg(&bias[n0 + 1]);
                if (rope) {
                    const int pi = (n0 & (D_ - 1)) >> 1;
                    const float cv = __ldg(&cosT[pos * 64 + pi]);
                    const float sv = __ldg(&sinT[pos * 64 + pi]);
                    const float t1 = v0, t2 = v1;
                    v0 = t1 * cv - t2 * sv;
                    v1 = t1 * sv + t2 * cv;
                }
                if (scale) { v0 *= qscale; v1 *= qscale; }
                *(__half2*)(C + (size_t)m * ATTN_ + n0) =
                    __halves2half2(__float2half_rn(v0), __float2half_rn(v1));
            }
        }
    }
}

// ---------------------------------------------------------------------------
// Output projection GEMM: fp32 out + bias. grid (8, 64).
// ---------------------------------------------------------------------------
__global__ void __launch_bounds__(GTH, 1) out_gemm(
    const __half* __restrict__ A, const __half* __restrict__ W,
    const float* __restrict__ bias, float* __restrict__ Cf)
{
    extern __shared__ char dsm[];
    const uint32_t sBase = smem_u32(dsm);

    const int tid  = threadIdx.x;
    const int wid  = tid >> 5;
    const int lane = tid & 31;
    const int wm   = (wid >> 2) * 64;
    const int wn   = (wid & 3) * 64;
    const int bm   = blockIdx.y * GBM;
    const int bn   = blockIdx.x * GBN;

    float acc[4][8][4];
#pragma unroll
    for (int mt = 0; mt < 4; mt++)
#pragma unroll
        for (int nt = 0; nt < 8; nt++)
#pragma unroll
            for (int e = 0; e < 4; e++) acc[mt][nt][e] = 0.f;

    GemmCoreF16::run(sBase, acc,
                     A + (size_t)bm * ATTN_, W + (size_t)bn * ATTN_,
                     tid, wm, wn, lane & 15, (lane >> 4) << 3);

    const int rr = lane >> 2;
    const int nn = (lane & 3) * 2;
#pragma unroll
    for (int mt = 0; mt < 4; mt++) {
#pragma unroll
        for (int half_ = 0; half_ < 2; half_++) {
            const int m = bm + wm + mt * 16 + rr + half_ * 8;
#pragma unroll
            for (int nt = 0; nt < 8; nt++) {
                const int n0 = bn + wn + nt * 8 + nn;
                const float v0 = acc[mt][nt][half_ * 2 + 0] + __ldg(&bias[n0]);
                const float v1 = acc[mt][nt][half_ * 2 + 1] + __ldg(&bias[n0 + 1]);
                *(float2*)(Cf + (size_t)m * ATTN_ + n0) = make_float2(v0, v1);
            }
        }
    }
}

// ---------------------------------------------------------------------------
// Flash attention v3: Q single plane (1-term S), P hi/lo (2-term PV), V single.
// CTA 128 q-rows x D=128, 8 warps x 16 rows, KV tiles 64, 2-stage cp.async.
// smem = Q 34816 + 2 x 34816 = 104448 B -> 2 CTAs/SM.
// ---------------------------------------------------------------------------
static constexpr int FLD = 136;
static constexpr int FQB = 128 * FLD * 2;   // 34816
static constexpr int FKB = 64 * FLD * 2;    // 17408
static constexpr int FSTG = 2 * FKB;        // 34816 (K + V)
static constexpr int FSMEM = FQB + 2 * FSTG;  // 104448

__global__ void __launch_bounds__(256, 2) flash_mma(
    const __half* __restrict__ Q, const __half* __restrict__ K,
    const __half* __restrict__ V, __half* __restrict__ Y)
{
    extern __shared__ char fsm[];
    const uint32_t sb  = smem_u32(fsm);
    const uint32_t sQ  = sb;
    const uint32_t sKV = sb + FQB;

    const int qt = blockIdx.x, h = blockIdx.y, b = blockIdx.z;
    const int tid = threadIdx.x, wid = tid >> 5, lane = tid & 31;
    const int wm = wid * 16;
    const int lr = lane & 15;
    const int lcg = (lane >> 4) << 3;

    const int ccf = tid & 15;
    const int r0f = tid >> 4;

    {
        const __half* q_g = Q + ((size_t)(b * T_ + qt * 128)) * ATTN_ + h * D_;
#pragma unroll
        for (int bb = 0; bb < 8; bb++) {
            const int r = bb * 16 + r0f;
            const uint32_t so = r * (FLD * 2) + ccf * 16;
            const size_t go = (size_t)r * ATTN_ + ccf * 8;
            CP_ASYNC16(sQ + so, q_g + go);
        }
        CP_COMMIT();
    }

    const int nkv = 2 * qt + 2;

    auto issue_kv = [&](int j) {
        const uint32_t st = sKV + (j & 1) * FSTG;
        const size_t base = ((size_t)(b * T_ + j * 64)) * ATTN_ + h * D_;
#pragma unroll
        for (int bb = 0; bb < 4; bb++) {
            const int r = bb * 16 + r0f;
            const uint32_t so = r * (FLD * 2) + ccf * 16;
            const size_t go = base + (size_t)r * ATTN_ + ccf * 8;
            CP_ASYNC16(st + so, K + go);
            CP_ASYNC16(st + FKB + so, V + go);
        }
        CP_COMMIT();
    };

    issue_kv(0);

    float Oacc[16][4];
#pragma unroll
    for (int nt = 0; nt < 16; nt++)
#pragma unroll
        for (int e = 0; e < 4; e++) Oacc[nt][e] = 0.f;
    float m0 = -1e30f, m1 = -1e30f, l0 = 0.f, l1 = 0.f;

    const int grow0 = qt * 128 + wm + (lane >> 2);
    const int grow1 = grow0 + 8;

    for (int j = 0; j < nkv; j++) {
        if (j + 1 < nkv) {
            issue_kv(j + 1);
            CP_WAIT(1);
        } else {
            CP_WAIT(0);
        }
        __syncthreads();

        const uint32_t st = sKV + (j & 1) * FSTG;
        const uint32_t cK = st;
        const uint32_t cV = st + FKB;

        // ---- S = Q K^T (1-term fp16) ----
        float sc[8][4];
#pragma unroll
        for (int nt = 0; nt < 8; nt++)
#pragma unroll
            for (int e = 0; e < 4; e++) sc[nt][e] = 0.f;

#pragma unroll 2
        for (int ks = 0; ks < 8; ks++) {
            const int kc = ks * 16 + lcg;
            uint32_t aQ[4], kf[4][4];
            ldsm4(aQ, sQ + ((wm + lr) * FLD + kc) * 2);
#pragma unroll
            for (int g = 0; g < 4; g++)
                ldsm4(kf[g], cK + ((g * 16 + lr) * FLD + kc) * 2);
#pragma unroll
            for (int nt = 0; nt < 8; nt++)
                mmah(sc[nt], aQ, kf[nt >> 1][nt & 1], kf[nt >> 1][(nt & 1) + 2]);
        }

        if (j >= 2 * qt) {
            const int c0 = j * 64 + ((lane & 3) << 1);
#pragma unroll
            for (int nt = 0; nt < 8; nt++) {
                const int gc = c0 + nt * 8;
                if (gc > grow0)     sc[nt][0] = -1e30f;
                if (gc + 1 > grow0) sc[nt][1] = -1e30f;
                if (gc > grow1)     sc[nt][2] = -1e30f;
                if (gc + 1 > grow1) sc[nt][3] = -1e30f;
            }
        }
        float mx0 = -1e30f, mx1 = -1e30f;
#pragma unroll
        for (int nt = 0; nt < 8; nt++) {
            mx0 = fmaxf(mx0, fmaxf(sc[nt][0], sc[nt][1]));
            mx1 = fmaxf(mx1, fmaxf(sc[nt][2], sc[nt][3]));
        }
        mx0 = fmaxf(mx0, __shfl_xor_sync(0xffffffffu, mx0, 1));
        mx0 = fmaxf(mx0, __shfl_xor_sync(0xffffffffu, mx0, 2));
        mx1 = fmaxf(mx1, __shfl_xor_sync(0xffffffffu, mx1, 1));
        mx1 = fmaxf(mx1, __shfl_xor_sync(0xffffffffu, mx1, 2));
        const float mn0 = fmaxf(m0, mx0), mn1 = fmaxf(m1, mx1);
        const float al0 = __expf(m0 - mn0), al1 = __expf(m1 - mn1);
        float ls0 = 0.f, ls1 = 0.f;
#pragma unroll
        for (int nt = 0; nt < 8; nt++) {
            sc[nt][0] = __expf(sc[nt][0] - mn0);
            sc[nt][1] = __expf(sc[nt][1] - mn0);
            sc[nt][2] = __expf(sc[nt][2] - mn1);
            sc[nt][3] = __expf(sc[nt][3] - mn1);
            ls0 += sc[nt][0] + sc[nt][1];
            ls1 += sc[nt][2] + sc[nt][3];
        }
        ls0 += __shfl_xor_sync(0xffffffffu, ls0, 1);
        ls0 += __shfl_xor_sync(0xffffffffu, ls0, 2);
        ls1 += __shfl_xor_sync(0xffffffffu, ls1, 1);
        ls1 += __shfl_xor_sync(0xffffffffu, ls1, 2);
        l0 = l0 * al0 + ls0; m0 = mn0;
        l1 = l1 * al1 + ls1; m1 = mn1;
#pragma unroll
        for (int nt = 0; nt < 16; nt++) {
            Oacc[nt][0] *= al0; Oacc[nt][1] *= al0;
            Oacc[nt][2] *= al1; Oacc[nt][3] *= al1;
        }

        // ---- O += (Ph+Pl) V ----
#pragma unroll
        for (int ks = 0; ks < 4; ks++) {
            uint32_t aPh[4], aPl[4];
            {
                const float p0 = sc[2 * ks][0],     p1 = sc[2 * ks][1];
                const float p2 = sc[2 * ks][2],     p3 = sc[2 * ks][3];
                const float p4 = sc[2 * ks + 1][0], p5 = sc[2 * ks + 1][1];
                const float p6 = sc[2 * ks + 1][2], p7 = sc[2 * ks + 1][3];
                aPh[0] = packh2(p0, p1);
                aPh[1] = packh2(p2, p3);
                aPh[2] = packh2(p4, p5);
                aPh[3] = packh2(p6, p7);
                aPl[0] = packh2(p0 - __half2float(__float2half_rn(p0)),
                                p1 - __half2float(__float2half_rn(p1)));
                aPl[1] = packh2(p2 - __half2float(__float2half_rn(p2)),
                                p3 - __half2float(__float2half_rn(p3)));
                aPl[2] = packh2(p4 - __half2float(__float2half_rn(p4)),
                                p5 - __half2float(__float2half_rn(p5)));
                aPl[3] = packh2(p6 - __half2float(__float2half_rn(p6)),
                                p7 - __half2float(__float2half_rn(p7)));
            }
#pragma unroll
            for (int ng = 0; ng < 8; ng++) {
                uint32_t bv[4];
                const uint32_t va = ((ks * 16 + lr) * FLD + ng * 16 + lcg) * 2;
                ldsm4t(bv, cV + va);
                mmah(Oacc[2 * ng], aPh, bv[0], bv[1]);
                mmah(Oacc[2 * ng], aPl, bv[0], bv[1]);
                mmah(Oacc[2 * ng + 1], aPh, bv[2], bv[3]);
                mmah(Oacc[2 * ng + 1], aPl, bv[2], bv[3]);
            }
        }
        __syncthreads();
    }

    const float inv0 = 1.0f / l0, inv1 = 1.0f / l1;
    const size_t rb0 = ((size_t)(b * T_) + grow0) * ATTN_ + h * D_;
    const size_t rb1 = ((size_t)(b * T_) + grow1) * ATTN_ + h * D_;
    const int nn = (lane & 3) << 1;
#pragma unroll
    for (int nt = 0; nt < 16; nt++) {
        const int col = nt * 8 + nn;
        *(__half2*)(Y + rb0 + col) = __halves2half2(
            __float2half_rn(Oacc[nt][0] * inv0), __float2half_rn(Oacc[nt][1] * inv0));
        *(__half2*)(Y + rb1 + col) = __halves2half2(
            __float2half_rn(Oacc[nt][2] * inv1), __float2half_rn(Oacc[nt][3] * inv1));
    }
}

// ---------------------------------------------------------------------------
// Host side. Order: 0 rope, 1 conv_x, 2 conv_w, 3 qkv, 4 flash, 5 out.
// ---------------------------------------------------------------------------
extern "C" void kernel_launch(void* const* d_in, const int* in_sizes, int n_in,
                              void* d_out, int out_size)
{
    const float* x    = (const float*)d_in[0];
    const float* wq_w = (const float*)d_in[3];
    const float* wq_b = (const float*)d_in[4];
    const float* wk_w = (const float*)d_in[5];
    const float* wk_b = (const float*)d_in[6];
    const float* wv_w = (const float*)d_in[7];
    const float* wv_b = (const float*)d_in[8];
    const float* wo_w = (const float*)d_in[9];
    const float* wo_b = (const float*)d_in[10];
    float* out = (float*)d_out;

    float *cosp, *sinp;
    __half *xp, *wp, *qp, *kp, *vp, *yp;
    cudaGetSymbolAddress((void**)&cosp, g_cosT);
    cudaGetSymbolAddress((void**)&sinp, g_sinT);
    cudaGetSymbolAddress((void**)&xp, g_x);
    cudaGetSymbolAddress((void**)&wp, g_w);
    cudaGetSymbolAddress((void**)&qp, g_q);
    cudaGetSymbolAddress((void**)&kp, g_k);
    cudaGetSymbolAddress((void**)&vp, g_v);
    cudaGetSymbolAddress((void**)&yp, g_y);

    const size_t WSZ = (size_t)ATTN_ * ATTN_;

    rope_table_kernel<<<T_, 64>>>(cosp, sinp);
    const int n4x = BT_ * ATTN_ / 4;
    conv_x_kernel<<<n4x / 256, 256>>>((const float4*)x, (__half2*)xp, n4x);
    const int n4w = ATTN_ * ATTN_ / 4;
    conv_w_kernel<<<dim3(n4w / 256, 1, 4), 256>>>(wq_w, wk_w, wv_w, wo_w,
                                                  (__half2*)wp, n4w);

    cudaFuncSetAttribute(qkv_gemm, cudaFuncAttributeMaxDynamicSharedMemorySize, GSMEM);
    cudaFuncSetAttribute(out_gemm, cudaFuncAttributeMaxDynamicSharedMemorySize, GSMEM);
    cudaFuncSetAttribute(flash_mma, cudaFuncAttributeMaxDynamicSharedMemorySize, FSMEM);

    qkv_gemm<<<dim3(24, BT_ / GBM), GTH, GSMEM>>>(xp, wp,
                                                  wq_b, wk_b, wv_b,
                                                  qp, kp, vp,
                                                  cosp, sinp);
    flash_mma<<<dim3(T_ / 128, H_, B_), 256, FSMEM>>>(qp, kp, vp, yp);

    out_gemm<<<dim3(ATTN_ / GBN, BT_ / GBM), GTH, GSMEM>>>(yp, wp + 3 * WSZ,
                                                           wo_b, out);
}

// round 16
// speedup vs baseline: 4.8915x; 1.0059x over previous
#include <cuda_runtime.h>
#include <cuda_fp16.h>
#include <math.h>
#include <stdint.h>

#define B_    4
#define T_    2048
#define H_    16
#define D_    128
#define ATTN_ 2048
#define BT_   (B_*T_)

// ---------------------------------------------------------------------------
// Scratch, all fp16 single-plane except P (in-register hi/lo):
// x, W (concat 0=wq 1=wk 2=wv 3=wo), Q, K, V, y.
// ---------------------------------------------------------------------------
__device__ __half g_x[(size_t)BT_ * ATTN_];
__device__ __half g_w[(size_t)4 * ATTN_ * ATTN_];
__device__ __half g_q[(size_t)BT_ * ATTN_];
__device__ __half g_k[(size_t)BT_ * ATTN_];
__device__ __half g_v[(size_t)BT_ * ATTN_];
__device__ __half g_y[(size_t)BT_ * ATTN_];
__device__ float g_cosT[T_ * 64];
__device__ float g_sinT[T_ * 64];

// ---------------------------------------------------------------------------
// PTX helpers
// ---------------------------------------------------------------------------
__device__ __forceinline__ uint32_t smem_u32(const void* p) {
    uint32_t a;
    asm("{ .reg .u64 t; cvta.to.shared.u64 t, %1; cvt.u32.u64 %0, t; }" : "=r"(a) : "l"(p));
    return a;
}

#define CP_ASYNC16(dst, src) \
    asm volatile("cp.async.cg.shared.global [%0], [%1], 16;" :: "r"(dst), "l"(src))
#define CP_COMMIT() asm volatile("cp.async.commit_group;" ::: "memory")
#define CP_WAIT(n)  asm volatile("cp.async.wait_group %0;" :: "n"(n) : "memory")

__device__ __forceinline__ void ldsm4(uint32_t* r, uint32_t addr) {
    asm volatile("ldmatrix.sync.aligned.m8n8.x4.shared.b16 {%0,%1,%2,%3}, [%4];"
                 : "=r"(r[0]), "=r"(r[1]), "=r"(r[2]), "=r"(r[3]) : "r"(addr));
}
__device__ __forceinline__ void ldsm4t(uint32_t* r, uint32_t addr) {
    asm volatile("ldmatrix.sync.aligned.m8n8.x4.trans.shared.b16 {%0,%1,%2,%3}, [%4];"
                 : "=r"(r[0]), "=r"(r[1]), "=r"(r[2]), "=r"(r[3]) : "r"(addr));
}

__device__ __forceinline__ void mmah(float* c, const uint32_t* a,
                                     uint32_t b0, uint32_t b1) {
    asm volatile(
        "mma.sync.aligned.m16n8k16.row.col.f32.f16.f16.f32 "
        "{%0,%1,%2,%3}, {%4,%5,%6,%7}, {%8,%9}, {%0,%1,%2,%3};"
        : "+f"(c[0]), "+f"(c[1]), "+f"(c[2]), "+f"(c[3])
        : "r"(a[0]), "r"(a[1]), "r"(a[2]), "r"(a[3]), "r"(b0), "r"(b1));
}

__device__ __forceinline__ uint32_t packh2(float a, float b) {
    __half2 t = __halves2half2(__float2half_rn(a), __float2half_rn(b));
    return *(uint32_t*)&t;
}

// ---------------------------------------------------------------------------
// Elementwise kernels
// ---------------------------------------------------------------------------
__global__ void rope_table_kernel(float* __restrict__ cosT, float* __restrict__ sinT) {
    const int t = blockIdx.x;
    const int i = threadIdx.x;
    const float kFreq = 0.07195578415606394f;  // ln(10000)/128
    const float inv = expf((float)(2 * i) * -kFreq);
    const float ang = (float)t * inv;
    float s, c;
    sincosf(ang, &s, &c);
    cosT[t * 64 + i] = c;
    sinT[t * 64 + i] = s;
}

__global__ void conv_x_kernel(const float4* __restrict__ src,
                              __half2* __restrict__ dst, int n4) {
    int i = blockIdx.x * blockDim.x + threadIdx.x;
    if (i >= n4) return;
    float4 v = src[i];
    dst[2 * i]     = __halves2half2(__float2half_rn(v.x), __float2half_rn(v.y));
    dst[2 * i + 1] = __halves2half2(__float2half_rn(v.z), __float2half_rn(v.w));
}

__global__ void conv_w_kernel(const float* __restrict__ w0, const float* __restrict__ w1,
                              const float* __restrict__ w2, const float* __restrict__ w3,
                              __half2* __restrict__ dst, int n4) {
    int i = blockIdx.x * blockDim.x + threadIdx.x;
    if (i >= n4) return;
    const int z = blockIdx.z;
    const float* src = (z == 0) ? w0 : (z == 1) ? w1 : (z == 2) ? w2 : w3;
    float4 v = ((const float4*)src)[i];
    const size_t off = (size_t)z * n4 * 2;
    dst[off + 2 * i]     = __halves2half2(__float2half_rn(v.x), __float2half_rn(v.y));
    dst[off + 2 * i + 1] = __halves2half2(__float2half_rn(v.z), __float2half_rn(v.w));
}

// ---------------------------------------------------------------------------
// fp16 1-term GEMM core v4: CTA 128x256, warp tile 64x64, BK=128, 2-stage.
// smem: A 128x272B + W 256x272B = 104448 B/stage; 208896 B total.
// 16 barrier windows (was 32), 8 ks-steps each.
// ---------------------------------------------------------------------------
static constexpr int GBM = 128, GBN = 256, GBK = 128;
static constexpr int LDSE = 136;                // pitch in b16 elems = 272 B
static constexpr int A_B  = 128 * 272;          // 34816 B
static constexpr int W_B  = 256 * 272;          // 69632 B
static constexpr int STB  = A_B + W_B;          // 104448 B
static constexpr int GSMEM = 2 * STB;           // 208896 B
static constexpr int GTH = 256;

struct GemmCoreF16 {
    __device__ static __forceinline__ void run(
        uint32_t sBase, float (&acc)[4][8][4],
        const __half* gA, const __half* gW,
        int tid, int wm, int wn, int lr, int lc)
    {
        const int cc = tid & 15;       // 16B chunk within 256B row
        const int rb = tid >> 4;       // 0..15
        const int NIT = ATTN_ / GBK;   // 16

        auto load_stage = [&](uint32_t st, int k0) {
#pragma unroll
            for (int bb = 0; bb < 8; bb++) {
                const int r = bb * 16 + rb;
                const uint32_t so = r * 272 + cc * 16;
                const size_t go = (size_t)r * ATTN_ + k0 + cc * 8;
                CP_ASYNC16(st + so, gA + go);
            }
#pragma unroll
            for (int bb = 0; bb < 16; bb++) {
                const int r = bb * 16 + rb;
                const uint32_t so = r * 272 + cc * 16;
                const size_t go = (size_t)r * ATTN_ + k0 + cc * 8;
                CP_ASYNC16(st + A_B + so, gW + go);
            }
            CP_COMMIT();
        };

        load_stage(sBase, 0);

        for (int kt = 0; kt < NIT; kt++) {
            if (kt + 1 < NIT) {
                load_stage(sBase + ((kt + 1) & 1) * STB, (kt + 1) * GBK);
                CP_WAIT(1);
            } else {
                CP_WAIT(0);
            }
            __syncthreads();

            const uint32_t st = sBase + (kt & 1) * STB;
            const uint32_t sA = st;
            const uint32_t sW = st + A_B;

#pragma unroll
            for (int ks = 0; ks < 8; ks++) {
                const int kc = ks * 16 + lc;
                uint32_t af[4][4], wf[4][4];
#pragma unroll
                for (int mt = 0; mt < 4; mt++)
                    ldsm4(af[mt], sA + ((wm + mt * 16 + lr) * LDSE + kc) * 2);
#pragma unroll
                for (int g = 0; g < 4; g++)
                    ldsm4(wf[g], sW + ((wn + g * 16 + lr) * LDSE + kc) * 2);

#pragma unroll
                for (int mt = 0; mt < 4; mt++)
#pragma unroll
                    for (int nt = 0; nt < 8; nt++)
                        mmah(acc[mt][nt], af[mt], wf[nt >> 1][nt & 1], wf[nt >> 1][(nt & 1) + 2]);
            }
            __syncthreads();
        }
    }
};

// ---------------------------------------------------------------------------
// Fused QKV projection GEMM. grid (24, 64). blockIdx.x>>3 : 0=Q,1=K,2=V.
// All outputs single fp16 plane.
// ---------------------------------------------------------------------------
__global__ void __launch_bounds__(GTH, 1) qkv_gemm(
    const __half* __restrict__ X, const __half* __restrict__ W,
    const float* __restrict__ bq, const float* __restrict__ bk, const float* __restrict__ bv,
    __half* __restrict__ QQ, __half* __restrict__ KK, __half* __restrict__ VV,
    const float* __restrict__ cosT, const float* __restrict__ sinT)
{
    extern __shared__ char dsm[];
    const uint32_t sBase = smem_u32(dsm);

    const int tid  = threadIdx.x;
    const int wid  = tid >> 5;
    const int lane = tid & 31;
    const int wm   = (wid >> 2) * 64;
    const int wn   = (wid & 3) * 64;
    const int bm   = blockIdx.y * GBM;
    const int qkv  = blockIdx.x >> 3;
    const int bnl  = (blockIdx.x & 7) * GBN;
    const int bng  = blockIdx.x * GBN;

    float acc[4][8][4];
#pragma unroll
    for (int mt = 0; mt < 4; mt++)
#pragma unroll
        for (int nt = 0; nt < 8; nt++)
#pragma unroll
            for (int e = 0; e < 4; e++) acc[mt][nt][e] = 0.f;

    GemmCoreF16::run(sBase, acc,
                     X + (size_t)bm * ATTN_, W + (size_t)bng * ATTN_,
                     tid, wm, wn, lane & 15, (lane >> 4) << 3);

    const float* bias = (qkv == 0) ? bq : (qkv == 1) ? bk : bv;
    __half* C = (qkv == 0) ? QQ : (qkv == 1) ? KK : VV;
    const bool rope  = (qkv != 2);
    const bool scale = (qkv == 0);
    const float qscale = 0.08838834764831843f;

    const int rr = lane >> 2;
    const int nn = (lane & 3) * 2;
#pragma unroll
    for (int mt = 0; mt < 4; mt++) {
#pragma unroll
        for (int half_ = 0; half_ < 2; half_++) {
            const int m = bm + wm + mt * 16 + rr + half_ * 8;
            const int pos = m & (T_ - 1);
#pragma unroll
            for (int nt = 0; nt < 8; nt++) {
                const int n0 = bnl + wn + nt * 8 + nn;
                float v0 = acc[mt][nt][half_ * 2 + 0] + __ldg(&bias[n0]);
                float v1 = acc[mt][nt][half_ * 2 + 1] + __ldg(&bias[n0 + 1]);
                if (rope) {
                    const int pi = (n0 & (D_ - 1)) >> 1;
                    const float cv = __ldg(&cosT[pos * 64 + pi]);
                    const float sv = __ldg(&sinT[pos * 64 + pi]);
                    const float t1 = v0, t2 = v1;
                    v0 = t1 * cv - t2 * sv;
                    v1 = t1 * sv + t2 * cv;
                }
                if (scale) { v0 *= qscale; v1 *= qscale; }
                *(__half2*)(C + (size_t)m * ATTN_ + n0) =
                    __halves2half2(__float2half_rn(v0), __float2half_rn(v1));
            }
        }
    }
}

// ---------------------------------------------------------------------------
// Output projection GEMM: fp32 out + bias. grid (8, 64).
// ---------------------------------------------------------------------------
__global__ void __launch_bounds__(GTH, 1) out_gemm(
    const __half* __restrict__ A, const __half* __restrict__ W,
    const float* __restrict__ bias, float* __restrict__ Cf)
{
    extern __shared__ char dsm[];
    const uint32_t sBase = smem_u32(dsm);

    const int tid  = threadIdx.x;
    const int wid  = tid >> 5;
    const int lane = tid & 31;
    const int wm   = (wid >> 2) * 64;
    const int wn   = (wid & 3) * 64;
    const int bm   = blockIdx.y * GBM;
    const int bn   = blockIdx.x * GBN;

    float acc[4][8][4];
#pragma unroll
    for (int mt = 0; mt < 4; mt++)
#pragma unroll
        for (int nt = 0; nt < 8; nt++)
#pragma unroll
            for (int e = 0; e < 4; e++) acc[mt][nt][e] = 0.f;

    GemmCoreF16::run(sBase, acc,
                     A + (size_t)bm * ATTN_, W + (size_t)bn * ATTN_,
                     tid, wm, wn, lane & 15, (lane >> 4) << 3);

    const int rr = lane >> 2;
    const int nn = (lane & 3) * 2;
#pragma unroll
    for (int mt = 0; mt < 4; mt++) {
#pragma unroll
        for (int half_ = 0; half_ < 2; half_++) {
            const int m = bm + wm + mt * 16 + rr + half_ * 8;
#pragma unroll
            for (int nt = 0; nt < 8; nt++) {
                const int n0 = bn + wn + nt * 8 + nn;
                const float v0 = acc[mt][nt][half_ * 2 + 0] + __ldg(&bias[n0]);
                const float v1 = acc[mt][nt][half_ * 2 + 1] + __ldg(&bias[n0 + 1]);
                *(float2*)(Cf + (size_t)m * ATTN_ + n0) = make_float2(v0, v1);
            }
        }
    }
}

// ---------------------------------------------------------------------------
// Flash attention v3 (round-15 winner, unchanged): Q single (1-term S),
// P hi/lo (2-term PV), V single. 2 CTAs/SM.
// ---------------------------------------------------------------------------
static constexpr int FLD = 136;
static constexpr int FQB = 128 * FLD * 2;   // 34816
static constexpr int FKB = 64 * FLD * 2;    // 17408
static constexpr int FSTG = 2 * FKB;        // 34816 (K + V)
static constexpr int FSMEM = FQB + 2 * FSTG;  // 104448

__global__ void __launch_bounds__(256, 2) flash_mma(
    const __half* __restrict__ Q, const __half* __restrict__ K,
    const __half* __restrict__ V, __half* __restrict__ Y)
{
    extern __shared__ char fsm[];
    const uint32_t sb  = smem_u32(fsm);
    const uint32_t sQ  = sb;
    const uint32_t sKV = sb + FQB;

    const int qt = blockIdx.x, h = blockIdx.y, b = blockIdx.z;
    const int tid = threadIdx.x, wid = tid >> 5, lane = tid & 31;
    const int wm = wid * 16;
    const int lr = lane & 15;
    const int lcg = (lane >> 4) << 3;

    const int ccf = tid & 15;
    const int r0f = tid >> 4;

    {
        const __half* q_g = Q + ((size_t)(b * T_ + qt * 128)) * ATTN_ + h * D_;
#pragma unroll
        for (int bb = 0; bb < 8; bb++) {
            const int r = bb * 16 + r0f;
            const uint32_t so = r * (FLD * 2) + ccf * 16;
            const size_t go = (size_t)r * ATTN_ + ccf * 8;
            CP_ASYNC16(sQ + so, q_g + go);
        }
        CP_COMMIT();
    }

    const int nkv = 2 * qt + 2;

    auto issue_kv = [&](int j) {
        const uint32_t st = sKV + (j & 1) * FSTG;
        const size_t base = ((size_t)(b * T_ + j * 64)) * ATTN_ + h * D_;
#pragma unroll
        for (int bb = 0; bb < 4; bb++) {
            const int r = bb * 16 + r0f;
            const uint32_t so = r * (FLD * 2) + ccf * 16;
            const size_t go = base + (size_t)r * ATTN_ + ccf * 8;
            CP_ASYNC16(st + so, K + go);
            CP_ASYNC16(st + FKB + so, V + go);
        }
        CP_COMMIT();
    };

    issue_kv(0);

    float Oacc[16][4];
#pragma unroll
    for (int nt = 0; nt < 16; nt++)
#pragma unroll
        for (int e = 0; e < 4; e++) Oacc[nt][e] = 0.f;
    float m0 = -1e30f, m1 = -1e30f, l0 = 0.f, l1 = 0.f;

    const int grow0 = qt * 128 + wm + (lane >> 2);
    const int grow1 = grow0 + 8;

    for (int j = 0; j < nkv; j++) {
        if (j + 1 < nkv) {
            issue_kv(j + 1);
            CP_WAIT(1);
        } else {
            CP_WAIT(0);
        }
        __syncthreads();

        const uint32_t st = sKV + (j & 1) * FSTG;
        const uint32_t cK = st;
        const uint32_t cV = st + FKB;

        float sc[8][4];
#pragma unroll
        for (int nt = 0; nt < 8; nt++)
#pragma unroll
            for (int e = 0; e < 4; e++) sc[nt][e] = 0.f;

#pragma unroll 2
        for (int ks = 0; ks < 8; ks++) {
            const int kc = ks * 16 + lcg;
            uint32_t aQ[4], kf[4][4];
            ldsm4(aQ, sQ + ((wm + lr) * FLD + kc) * 2);
#pragma unroll
            for (int g = 0; g < 4; g++)
                ldsm4(kf[g], cK + ((g * 16 + lr) * FLD + kc) * 2);
#pragma unroll
            for (int nt = 0; nt < 8; nt++)
                mmah(sc[nt], aQ, kf[nt >> 1][nt & 1], kf[nt >> 1][(nt & 1) + 2]);
        }

        if (j >= 2 * qt) {
            const int c0 = j * 64 + ((lane & 3) << 1);
#pragma unroll
            for (int nt = 0; nt < 8; nt++) {
                const int gc = c0 + nt * 8;
                if (gc > grow0)     sc[nt][0] = -1e30f;
                if (gc + 1 > grow0) sc[nt][1] = -1e30f;
                if (gc > grow1)     sc[nt][2] = -1e30f;
                if (gc + 1 > grow1) sc[nt][3] = -1e30f;
            }
        }
        float mx0 = -1e30f, mx1 = -1e30f;
#pragma unroll
        for (int nt = 0; nt < 8; nt++) {
            mx0 = fmaxf(mx0, fmaxf(sc[nt][0], sc[nt][1]));
            mx1 = fmaxf(mx1, fmaxf(sc[nt][2], sc[nt][3]));
        }
        mx0 = fmaxf(mx0, __shfl_xor_sync(0xffffffffu, mx0, 1));
        mx0 = fmaxf(mx0, __shfl_xor_sync(0xffffffffu, mx0, 2));
        mx1 = fmaxf(mx1, __shfl_xor_sync(0xffffffffu, mx1, 1));
        mx1 = fmaxf(mx1, __shfl_xor_sync(0xffffffffu, mx1, 2));
        const float mn0 = fmaxf(m0, mx0), mn1 = fmaxf(m1, mx1);
        const float al0 = __expf(m0 - mn0), al1 = __expf(m1 - mn1);
        float ls0 = 0.f, ls1 = 0.f;
#pragma unroll
        for (int nt = 0; nt < 8; nt++) {
            sc[nt][0] = __expf(sc[nt][0] - mn0);
            sc[nt][1] = __expf(sc[nt][1] - mn0);
            sc[nt][2] = __expf(sc[nt][2] - mn1);
            sc[nt][3] = __expf(sc[nt][3] - mn1);
            ls0 += sc[nt][0] + sc[nt][1];
            ls1 += sc[nt][2] + sc[nt][3];
        }
        ls0 += __shfl_xor_sync(0xffffffffu, ls0, 1);
        ls0 += __shfl_xor_sync(0xffffffffu, ls0, 2);
        ls1 += __shfl_xor_sync(0xffffffffu, ls1, 1);
        ls1 += __shfl_xor_sync(0xffffffffu, ls1, 2);
        l0 = l0 * al0 + ls0; m0 = mn0;
        l1 = l1 * al1 + ls1; m1 = mn1;
#pragma unroll
        for (int nt = 0; nt < 16; nt++) {
            Oacc[nt][0] *= al0; Oacc[nt][1] *= al0;
            Oacc[nt][2] *= al1; Oacc[nt][3] *= al1;
        }

#pragma unroll
        for (int ks = 0; ks < 4; ks++) {
            uint32_t aPh[4], aPl[4];
            {
                const float p0 = sc[2 * ks][0],     p1 = sc[2 * ks][1];
                const float p2 = sc[2 * ks][2],     p3 = sc[2 * ks][3];
                const float p4 = sc[2 * ks + 1][0], p5 = sc[2 * ks + 1][1];
                const float p6 = sc[2 * ks + 1][2], p7 = sc[2 * ks + 1][3];
                aPh[0] = packh2(p0, p1);
                aPh[1] = packh2(p2, p3);
                aPh[2] = packh2(p4, p5);
                aPh[3] = packh2(p6, p7);
                aPl[0] = packh2(p0 - __half2float(__float2half_rn(p0)),
                                p1 - __half2float(__float2half_rn(p1)));
                aPl[1] = packh2(p2 - __half2float(__float2half_rn(p2)),
                                p3 - __half2float(__float2half_rn(p3)));
                aPl[2] = packh2(p4 - __half2float(__float2half_rn(p4)),
                                p5 - __half2float(__float2half_rn(p5)));
                aPl[3] = packh2(p6 - __half2float(__float2half_rn(p6)),
                                p7 - __half2float(__float2half_rn(p7)));
            }
#pragma unroll
            for (int ng = 0; ng < 8; ng++) {
                uint32_t bv[4];
                const uint32_t va = ((ks * 16 + lr) * FLD + ng * 16 + lcg) * 2;
                ldsm4t(bv, cV + va);
                mmah(Oacc[2 * ng], aPh, bv[0], bv[1]);
                mmah(Oacc[2 * ng], aPl, bv[0], bv[1]);
                mmah(Oacc[2 * ng + 1], aPh, bv[2], bv[3]);
                mmah(Oacc[2 * ng + 1], aPl, bv[2], bv[3]);
            }
        }
        __syncthreads();
    }

    const float inv0 = 1.0f / l0, inv1 = 1.0f / l1;
    const size_t rb0 = ((size_t)(b * T_) + grow0) * ATTN_ + h * D_;
    const size_t rb1 = ((size_t)(b * T_) + grow1) * ATTN_ + h * D_;
    const int nn = (lane & 3) << 1;
#pragma unroll
    for (int nt = 0; nt < 16; nt++) {
        const int col = nt * 8 + nn;
        *(__half2*)(Y + rb0 + col) = __halves2half2(
            __float2half_rn(Oacc[nt][0] * inv0), __float2half_rn(Oacc[nt][1] * inv0));
        *(__half2*)(Y + rb1 + col) = __halves2half2(
            __float2half_rn(Oacc[nt][2] * inv1), __float2half_rn(Oacc[nt][3] * inv1));
    }
}

// ---------------------------------------------------------------------------
// Host side. Order: 0 rope, 1 conv_x, 2 conv_w, 3 qkv, 4 flash, 5 out.
// ---------------------------------------------------------------------------
extern "C" void kernel_launch(void* const* d_in, const int* in_sizes, int n_in,
                              void* d_out, int out_size)
{
    const float* x    = (const float*)d_in[0];
    const float* wq_w = (const float*)d_in[3];
    const float* wq_b = (const float*)d_in[4];
    const float* wk_w = (const float*)d_in[5];
    const float* wk_b = (const float*)d_in[6];
    const float* wv_w = (const float*)d_in[7];
    const float* wv_b = (const float*)d_in[8];
    const float* wo_w = (const float*)d_in[9];
    const float* wo_b = (const float*)d_in[10];
    float* out = (float*)d_out;

    float *cosp, *sinp;
    __half *xp, *wp, *qp, *kp, *vp, *yp;
    cudaGetSymbolAddress((void**)&cosp, g_cosT);
    cudaGetSymbolAddress((void**)&sinp, g_sinT);
    cudaGetSymbolAddress((void**)&xp, g_x);
    cudaGetSymbolAddress((void**)&wp, g_w);
    cudaGetSymbolAddress((void**)&qp, g_q);
    cudaGetSymbolAddress((void**)&kp, g_k);
    cudaGetSymbolAddress((void**)&vp, g_v);
    cudaGetSymbolAddress((void**)&yp, g_y);

    const size_t WSZ = (size_t)ATTN_ * ATTN_;

    rope_table_kernel<<<T_, 64>>>(cosp, sinp);
    const int n4x = BT_ * ATTN_ / 4;
    conv_x_kernel<<<n4x / 256, 256>>>((const float4*)x, (__half2*)xp, n4x);
    const int n4w = ATTN_ * ATTN_ / 4;
    conv_w_kernel<<<dim3(n4w / 256, 1, 4), 256>>>(wq_w, wk_w, wv_w, wo_w,
                                                  (__half2*)wp, n4w);

    cudaFuncSetAttribute(qkv_gemm, cudaFuncAttributeMaxDynamicSharedMemorySize, GSMEM);
    cudaFuncSetAttribute(out_gemm, cudaFuncAttributeMaxDynamicSharedMemorySize, GSMEM);
    cudaFuncSetAttribute(flash_mma, cudaFuncAttributeMaxDynamicSharedMemorySize, FSMEM);

    qkv_gemm<<<dim3(24, BT_ / GBM), GTH, GSMEM>>>(xp, wp,
                                                  wq_b, wk_b, wv_b,
                                                  qp, kp, vp,
                                                  cosp, sinp);
    flash_mma<<<dim3(T_ / 128, H_, B_), 256, FSMEM>>>(qp, kp, vp, yp);

    out_gemm<<<dim3(ATTN_ / GBN, BT_ / GBM), GTH, GSMEM>>>(yp, wp + 3 * WSZ,
                                                           wo_b, out);
}

// round 17
// speedup vs baseline: 5.2390x; 1.0710x over previous
#include <cuda_runtime.h>
#include <cuda_fp16.h>
#include <math.h>
#include <stdint.h>

#define B_    4
#define T_    2048
#define H_    16
#define D_    128
#define ATTN_ 2048
#define BT_   (B_*T_)

// ---------------------------------------------------------------------------
// Scratch, all fp16 single-plane: x, W (concat 0=wq 1=wk 2=wv 3=wo), Q, K, V, y.
// ---------------------------------------------------------------------------
__device__ __half g_x[(size_t)BT_ * ATTN_];
__device__ __half g_w[(size_t)4 * ATTN_ * ATTN_];
__device__ __half g_q[(size_t)BT_ * ATTN_];
__device__ __half g_k[(size_t)BT_ * ATTN_];
__device__ __half g_v[(size_t)BT_ * ATTN_];
__device__ __half g_y[(size_t)BT_ * ATTN_];
__device__ float g_cosT[T_ * 64];
__device__ float g_sinT[T_ * 64];

// ---------------------------------------------------------------------------
// PTX helpers
// ---------------------------------------------------------------------------
__device__ __forceinline__ uint32_t smem_u32(const void* p) {
    uint32_t a;
    asm("{ .reg .u64 t; cvta.to.shared.u64 t, %1; cvt.u32.u64 %0, t; }" : "=r"(a) : "l"(p));
    return a;
}

#define CP_ASYNC16(dst, src) \
    asm volatile("cp.async.cg.shared.global [%0], [%1], 16;" :: "r"(dst), "l"(src))
#define CP_COMMIT() asm volatile("cp.async.commit_group;" ::: "memory")
#define CP_WAIT(n)  asm volatile("cp.async.wait_group %0;" :: "n"(n) : "memory")

__device__ __forceinline__ void ldsm4(uint32_t* r, uint32_t addr) {
    asm volatile("ldmatrix.sync.aligned.m8n8.x4.shared.b16 {%0,%1,%2,%3}, [%4];"
                 : "=r"(r[0]), "=r"(r[1]), "=r"(r[2]), "=r"(r[3]) : "r"(addr));
}
__device__ __forceinline__ void ldsm4t(uint32_t* r, uint32_t addr) {
    asm volatile("ldmatrix.sync.aligned.m8n8.x4.trans.shared.b16 {%0,%1,%2,%3}, [%4];"
                 : "=r"(r[0]), "=r"(r[1]), "=r"(r[2]), "=r"(r[3]) : "r"(addr));
}

__device__ __forceinline__ void mmah(float* c, const uint32_t* a,
                                     uint32_t b0, uint32_t b1) {
    asm volatile(
        "mma.sync.aligned.m16n8k16.row.col.f32.f16.f16.f32 "
        "{%0,%1,%2,%3}, {%4,%5,%6,%7}, {%8,%9}, {%0,%1,%2,%3};"
        : "+f"(c[0]), "+f"(c[1]), "+f"(c[2]), "+f"(c[3])
        : "r"(a[0]), "r"(a[1]), "r"(a[2]), "r"(a[3]), "r"(b0), "r"(b1));
}

__device__ __forceinline__ uint32_t packh2(float a, float b) {
    __half2 t = __halves2half2(__float2half_rn(a), __float2half_rn(b));
    return *(uint32_t*)&t;
}

// ---------------------------------------------------------------------------
// Elementwise kernels
// ---------------------------------------------------------------------------
__global__ void rope_table_kernel(float* __restrict__ cosT, float* __restrict__ sinT) {
    const int t = blockIdx.x;
    const int i = threadIdx.x;
    const float kFreq = 0.07195578415606394f;  // ln(10000)/128
    const float inv = expf((float)(2 * i) * -kFreq);
    const float ang = (float)t * inv;
    float s, c;
    sincosf(ang, &s, &c);
    cosT[t * 64 + i] = c;
    sinT[t * 64 + i] = s;
}

__global__ void conv_x_kernel(const float4* __restrict__ src,
                              __half2* __restrict__ dst, int n4) {
    int i = blockIdx.x * blockDim.x + threadIdx.x;
    if (i >= n4) return;
    float4 v = src[i];
    dst[2 * i]     = __halves2half2(__float2half_rn(v.x), __float2half_rn(v.y));
    dst[2 * i + 1] = __halves2half2(__float2half_rn(v.z), __float2half_rn(v.w));
}

__global__ void conv_w_kernel(const float* __restrict__ w0, const float* __restrict__ w1,
                              const float* __restrict__ w2, const float* __restrict__ w3,
                              __half2* __restrict__ dst, int n4) {
    int i = blockIdx.x * blockDim.x + threadIdx.x;
    if (i >= n4) return;
    const int z = blockIdx.z;
    const float* src = (z == 0) ? w0 : (z == 1) ? w1 : (z == 2) ? w2 : w3;
    float4 v = ((const float4*)src)[i];
    const size_t off = (size_t)z * n4 * 2;
    dst[off + 2 * i]     = __halves2half2(__float2half_rn(v.x), __float2half_rn(v.y));
    dst[off + 2 * i + 1] = __halves2half2(__float2half_rn(v.z), __float2half_rn(v.w));
}

// ---------------------------------------------------------------------------
// fp16 1-term GEMM core (round-16 config, at plateau): CTA 128x256,
// warp tile 64x64, BK=128, 2-stage.
// ---------------------------------------------------------------------------
static constexpr int GBM = 128, GBN = 256, GBK = 128;
static constexpr int LDSE = 136;
static constexpr int A_B  = 128 * 272;
static constexpr int W_B  = 256 * 272;
static constexpr int STB  = A_B + W_B;
static constexpr int GSMEM = 2 * STB;
static constexpr int GTH = 256;

struct GemmCoreF16 {
    __device__ static __forceinline__ void run(
        uint32_t sBase, float (&acc)[4][8][4],
        const __half* gA, const __half* gW,
        int tid, int wm, int wn, int lr, int lc)
    {
        const int cc = tid & 15;
        const int rb = tid >> 4;
        const int NIT = ATTN_ / GBK;   // 16

        auto load_stage = [&](uint32_t st, int k0) {
#pragma unroll
            for (int bb = 0; bb < 8; bb++) {
                const int r = bb * 16 + rb;
                const uint32_t so = r * 272 + cc * 16;
                const size_t go = (size_t)r * ATTN_ + k0 + cc * 8;
                CP_ASYNC16(st + so, gA + go);
            }
#pragma unroll
            for (int bb = 0; bb < 16; bb++) {
                const int r = bb * 16 + rb;
                const uint32_t so = r * 272 + cc * 16;
                const size_t go = (size_t)r * ATTN_ + k0 + cc * 8;
                CP_ASYNC16(st + A_B + so, gW + go);
            }
            CP_COMMIT();
        };

        load_stage(sBase, 0);

        for (int kt = 0; kt < NIT; kt++) {
            if (kt + 1 < NIT) {
                load_stage(sBase + ((kt + 1) & 1) * STB, (kt + 1) * GBK);
                CP_WAIT(1);
            } else {
                CP_WAIT(0);
            }
            __syncthreads();

            const uint32_t st = sBase + (kt & 1) * STB;
            const uint32_t sA = st;
            const uint32_t sW = st + A_B;

#pragma unroll
            for (int ks = 0; ks < 8; ks++) {
                const int kc = ks * 16 + lc;
                uint32_t af[4][4], wf[4][4];
#pragma unroll
                for (int mt = 0; mt < 4; mt++)
                    ldsm4(af[mt], sA + ((wm + mt * 16 + lr) * LDSE + kc) * 2);
#pragma unroll
                for (int g = 0; g < 4; g++)
                    ldsm4(wf[g], sW + ((wn + g * 16 + lr) * LDSE + kc) * 2);

#pragma unroll
                for (int mt = 0; mt < 4; mt++)
#pragma unroll
                    for (int nt = 0; nt < 8; nt++)
                        mmah(acc[mt][nt], af[mt], wf[nt >> 1][nt & 1], wf[nt >> 1][(nt & 1) + 2]);
            }
            __syncthreads();
        }
    }
};

// ---------------------------------------------------------------------------
// Fused QKV projection GEMM. grid (24, 64). blockIdx.x>>3 : 0=Q,1=K,2=V.
// ---------------------------------------------------------------------------
__global__ void __launch_bounds__(GTH, 1) qkv_gemm(
    const __half* __restrict__ X, const __half* __restrict__ W,
    const float* __restrict__ bq, const float* __restrict__ bk, const float* __restrict__ bv,
    __half* __restrict__ QQ, __half* __restrict__ KK, __half* __restrict__ VV,
    const float* __restrict__ cosT, const float* __restrict__ sinT)
{
    extern __shared__ char dsm[];
    const uint32_t sBase = smem_u32(dsm);

    const int tid  = threadIdx.x;
    const int wid  = tid >> 5;
    const int lane = tid & 31;
    const int wm   = (wid >> 2) * 64;
    const int wn   = (wid & 3) * 64;
    const int bm   = blockIdx.y * GBM;
    const int qkv  = blockIdx.x >> 3;
    const int bnl  = (blockIdx.x & 7) * GBN;
    const int bng  = blockIdx.x * GBN;

    float acc[4][8][4];
#pragma unroll
    for (int mt = 0; mt < 4; mt++)
#pragma unroll
        for (int nt = 0; nt < 8; nt++)
#pragma unroll
            for (int e = 0; e < 4; e++) acc[mt][nt][e] = 0.f;

    GemmCoreF16::run(sBase, acc,
                     X + (size_t)bm * ATTN_, W + (size_t)bng * ATTN_,
                     tid, wm, wn, lane & 15, (lane >> 4) << 3);

    const float* bias = (qkv == 0) ? bq : (qkv == 1) ? bk : bv;
    __half* C = (qkv == 0) ? QQ : (qkv == 1) ? KK : VV;
    const bool rope  = (qkv != 2);
    const bool scale = (qkv == 0);
    const float qscale = 0.08838834764831843f;

    const int rr = lane >> 2;
    const int nn = (lane & 3) * 2;
#pragma unroll
    for (int mt = 0; mt < 4; mt++) {
#pragma unroll
        for (int half_ = 0; half_ < 2; half_++) {
            const int m = bm + wm + mt * 16 + rr + half_ * 8;
            const int pos = m & (T_ - 1);
#pragma unroll
            for (int nt = 0; nt < 8; nt++) {
                const int n0 = bnl + wn + nt * 8 + nn;
                float v0 = acc[mt][nt][half_ * 2 + 0] + __ldg(&bias[n0]);
                float v1 = acc[mt][nt][half_ * 2 + 1] + __ldg(&bias[n0 + 1]);
                if (rope) {
                    const int pi = (n0 & (D_ - 1)) >> 1;
                    const float cv = __ldg(&cosT[pos * 64 + pi]);
                    const float sv = __ldg(&sinT[pos * 64 + pi]);
                    const float t1 = v0, t2 = v1;
                    v0 = t1 * cv - t2 * sv;
                    v1 = t1 * sv + t2 * cv;
                }
                if (scale) { v0 *= qscale; v1 *= qscale; }
                *(__half2*)(C + (size_t)m * ATTN_ + n0) =
                    __halves2half2(__float2half_rn(v0), __float2half_rn(v1));
            }
        }
    }
}

// ---------------------------------------------------------------------------
// Output projection GEMM: fp32 out + bias. grid (8, 64).
// ---------------------------------------------------------------------------
__global__ void __launch_bounds__(GTH, 1) out_gemm(
    const __half* __restrict__ A, const __half* __restrict__ W,
    const float* __restrict__ bias, float* __restrict__ Cf)
{
    extern __shared__ char dsm[];
    const uint32_t sBase = smem_u32(dsm);

    const int tid  = threadIdx.x;
    const int wid  = tid >> 5;
    const int lane = tid & 31;
    const int wm   = (wid >> 2) * 64;
    const int wn   = (wid & 3) * 64;
    const int bm   = blockIdx.y * GBM;
    const int bn   = blockIdx.x * GBN;

    float acc[4][8][4];
#pragma unroll
    for (int mt = 0; mt < 4; mt++)
#pragma unroll
        for (int nt = 0; nt < 8; nt++)
#pragma unroll
            for (int e = 0; e < 4; e++) acc[mt][nt][e] = 0.f;

    GemmCoreF16::run(sBase, acc,
                     A + (size_t)bm * ATTN_, W + (size_t)bn * ATTN_,
                     tid, wm, wn, lane & 15, (lane >> 4) << 3);

    const int rr = lane >> 2;
    const int nn = (lane & 3) * 2;
#pragma unroll
    for (int mt = 0; mt < 4; mt++) {
#pragma unroll
        for (int half_ = 0; half_ < 2; half_++) {
            const int m = bm + wm + mt * 16 + rr + half_ * 8;
#pragma unroll
            for (int nt = 0; nt < 8; nt++) {
                const int n0 = bn + wn + nt * 8 + nn;
                const float v0 = acc[mt][nt][half_ * 2 + 0] + __ldg(&bias[n0]);
                const float v1 = acc[mt][nt][half_ * 2 + 1] + __ldg(&bias[n0 + 1]);
                *(float2*)(Cf + (size_t)m * ATTN_ + n0) = make_float2(v0, v1);
            }
        }
    }
}

// ---------------------------------------------------------------------------
// Flash attention v4: Q single (1-term S), P single (1-term PV), V single.
// Longest-qt-first CTA ordering. 2 CTAs/SM.
// ---------------------------------------------------------------------------
static constexpr int FLD = 136;
static constexpr int FQB = 128 * FLD * 2;   // 34816
static constexpr int FKB = 64 * FLD * 2;    // 17408
static constexpr int FSTG = 2 * FKB;        // 34816 (K + V)
static constexpr int FSMEM = FQB + 2 * FSTG;  // 104448

__global__ void __launch_bounds__(256, 2) flash_mma(
    const __half* __restrict__ Q, const __half* __restrict__ K,
    const __half* __restrict__ V, __half* __restrict__ Y)
{
    extern __shared__ char fsm[];
    const uint32_t sb  = smem_u32(fsm);
    const uint32_t sQ  = sb;
    const uint32_t sKV = sb + FQB;

    // Longest-first: earliest CTAs take the largest causal extent.
    const int qt = (T_ / 128 - 1) - blockIdx.x;
    const int h = blockIdx.y, b = blockIdx.z;
    const int tid = threadIdx.x, wid = tid >> 5, lane = tid & 31;
    const int wm = wid * 16;
    const int lr = lane & 15;
    const int lcg = (lane >> 4) << 3;

    const int ccf = tid & 15;
    const int r0f = tid >> 4;

    {
        const __half* q_g = Q + ((size_t)(b * T_ + qt * 128)) * ATTN_ + h * D_;
#pragma unroll
        for (int bb = 0; bb < 8; bb++) {
            const int r = bb * 16 + r0f;
            const uint32_t so = r * (FLD * 2) + ccf * 16;
            const size_t go = (size_t)r * ATTN_ + ccf * 8;
            CP_ASYNC16(sQ + so, q_g + go);
        }
        CP_COMMIT();
    }

    const int nkv = 2 * qt + 2;

    auto issue_kv = [&](int j) {
        const uint32_t st = sKV + (j & 1) * FSTG;
        const size_t base = ((size_t)(b * T_ + j * 64)) * ATTN_ + h * D_;
#pragma unroll
        for (int bb = 0; bb < 4; bb++) {
            const int r = bb * 16 + r0f;
            const uint32_t so = r * (FLD * 2) + ccf * 16;
            const size_t go = base + (size_t)r * ATTN_ + ccf * 8;
            CP_ASYNC16(st + so, K + go);
            CP_ASYNC16(st + FKB + so, V + go);
        }
        CP_COMMIT();
    };

    issue_kv(0);

    float Oacc[16][4];
#pragma unroll
    for (int nt = 0; nt < 16; nt++)
#pragma unroll
        for (int e = 0; e < 4; e++) Oacc[nt][e] = 0.f;
    float m0 = -1e30f, m1 = -1e30f, l0 = 0.f, l1 = 0.f;

    const int grow0 = qt * 128 + wm + (lane >> 2);
    const int grow1 = grow0 + 8;

    for (int j = 0; j < nkv; j++) {
        if (j + 1 < nkv) {
            issue_kv(j + 1);
            CP_WAIT(1);
        } else {
            CP_WAIT(0);
        }
        __syncthreads();

        const uint32_t st = sKV + (j & 1) * FSTG;
        const uint32_t cK = st;
        const uint32_t cV = st + FKB;

        // ---- S = Q K^T (1-term) ----
        float sc[8][4];
#pragma unroll
        for (int nt = 0; nt < 8; nt++)
#pragma unroll
            for (int e = 0; e < 4; e++) sc[nt][e] = 0.f;

#pragma unroll 2
        for (int ks = 0; ks < 8; ks++) {
            const int kc = ks * 16 + lcg;
            uint32_t aQ[4], kf[4][4];
            ldsm4(aQ, sQ + ((wm + lr) * FLD + kc) * 2);
#pragma unroll
            for (int g = 0; g < 4; g++)
                ldsm4(kf[g], cK + ((g * 16 + lr) * FLD + kc) * 2);
#pragma unroll
            for (int nt = 0; nt < 8; nt++)
                mmah(sc[nt], aQ, kf[nt >> 1][nt & 1], kf[nt >> 1][(nt & 1) + 2]);
        }

        if (j >= 2 * qt) {
            const int c0 = j * 64 + ((lane & 3) << 1);
#pragma unroll
            for (int nt = 0; nt < 8; nt++) {
                const int gc = c0 + nt * 8;
                if (gc > grow0)     sc[nt][0] = -1e30f;
                if (gc + 1 > grow0) sc[nt][1] = -1e30f;
                if (gc > grow1)     sc[nt][2] = -1e30f;
                if (gc + 1 > grow1) sc[nt][3] = -1e30f;
            }
        }
        float mx0 = -1e30f, mx1 = -1e30f;
#pragma unroll
        for (int nt = 0; nt < 8; nt++) {
            mx0 = fmaxf(mx0, fmaxf(sc[nt][0], sc[nt][1]));
            mx1 = fmaxf(mx1, fmaxf(sc[nt][2], sc[nt][3]));
        }
        mx0 = fmaxf(mx0, __shfl_xor_sync(0xffffffffu, mx0, 1));
        mx0 = fmaxf(mx0, __shfl_xor_sync(0xffffffffu, mx0, 2));
        mx1 = fmaxf(mx1, __shfl_xor_sync(0xffffffffu, mx1, 1));
        mx1 = fmaxf(mx1, __shfl_xor_sync(0xffffffffu, mx1, 2));
        const float mn0 = fmaxf(m0, mx0), mn1 = fmaxf(m1, mx1);
        const float al0 = __expf(m0 - mn0), al1 = __expf(m1 - mn1);
        float ls0 = 0.f, ls1 = 0.f;
#pragma unroll
        for (int nt = 0; nt < 8; nt++) {
            sc[nt][0] = __expf(sc[nt][0] - mn0);
            sc[nt][1] = __expf(sc[nt][1] - mn0);
            sc[nt][2] = __expf(sc[nt][2] - mn1);
            sc[nt][3] = __expf(sc[nt][3] - mn1);
            ls0 += sc[nt][0] + sc[nt][1];
            ls1 += sc[nt][2] + sc[nt][3];
        }
        ls0 += __shfl_xor_sync(0xffffffffu, ls0, 1);
        ls0 += __shfl_xor_sync(0xffffffffu, ls0, 2);
        ls1 += __shfl_xor_sync(0xffffffffu, ls1, 1);
        ls1 += __shfl_xor_sync(0xffffffffu, ls1, 2);
        l0 = l0 * al0 + ls0; m0 = mn0;
        l1 = l1 * al1 + ls1; m1 = mn1;
#pragma unroll
        for (int nt = 0; nt < 16; nt++) {
            Oacc[nt][0] *= al0; Oacc[nt][1] *= al0;
            Oacc[nt][2] *= al1; Oacc[nt][3] *= al1;
        }

        // ---- O += P V (1-term) ----
#pragma unroll
        for (int ks = 0; ks < 4; ks++) {
            uint32_t aP[4];
            aP[0] = packh2(sc[2 * ks][0],     sc[2 * ks][1]);
            aP[1] = packh2(sc[2 * ks][2],     sc[2 * ks][3]);
            aP[2] = packh2(sc[2 * ks + 1][0], sc[2 * ks + 1][1]);
            aP[3] = packh2(sc[2 * ks + 1][2], sc[2 * ks + 1][3]);
#pragma unroll
            for (int ng = 0; ng < 8; ng++) {
                uint32_t bv[4];
                const uint32_t va = ((ks * 16 + lr) * FLD + ng * 16 + lcg) * 2;
                ldsm4t(bv, cV + va);
                mmah(Oacc[2 * ng],     aP, bv[0], bv[1]);
                mmah(Oacc[2 * ng + 1], aP, bv[2], bv[3]);
            }
        }
        __syncthreads();
    }

    const float inv0 = 1.0f / l0, inv1 = 1.0f / l1;
    const size_t rb0 = ((size_t)(b * T_) + grow0) * ATTN_ + h * D_;
    const size_t rb1 = ((size_t)(b * T_) + grow1) * ATTN_ + h * D_;
    const int nn = (lane & 3) << 1;
#pragma unroll
    for (int nt = 0; nt < 16; nt++) {
        const int col = nt * 8 + nn;
        *(__half2*)(Y + rb0 + col) = __halves2half2(
            __float2half_rn(Oacc[nt][0] * inv0), __float2half_rn(Oacc[nt][1] * inv0));
        *(__half2*)(Y + rb1 + col) = __halves2half2(
            __float2half_rn(Oacc[nt][2] * inv1), __float2half_rn(Oacc[nt][3] * inv1));
    }
}

// ---------------------------------------------------------------------------
// Host side. Order: 0 rope, 1 conv_x, 2 conv_w, 3 qkv, 4 flash, 5 out.
// ---------------------------------------------------------------------------
extern "C" void kernel_launch(void* const* d_in, const int* in_sizes, int n_in,
                              void* d_out, int out_size)
{
    const float* x    = (const float*)d_in[0];
    const float* wq_w = (const float*)d_in[3];
    const float* wq_b = (const float*)d_in[4];
    const float* wk_w = (const float*)d_in[5];
    const float* wk_b = (const float*)d_in[6];
    const float* wv_w = (const float*)d_in[7];
    const float* wv_b = (const float*)d_in[8];
    const float* wo_w = (const float*)d_in[9];
    const float* wo_b = (const float*)d_in[10];
    float* out = (float*)d_out;

    float *cosp, *sinp;
    __half *xp, *wp, *qp, *kp, *vp, *yp;
    cudaGetSymbolAddress((void**)&cosp, g_cosT);
    cudaGetSymbolAddress((void**)&sinp, g_sinT);
    cudaGetSymbolAddress((void**)&xp, g_x);
    cudaGetSymbolAddress((void**)&wp, g_w);
    cudaGetSymbolAddress((void**)&qp, g_q);
    cudaGetSymbolAddress((void**)&kp, g_k);
    cudaGetSymbolAddress((void**)&vp, g_v);
    cudaGetSymbolAddress((void**)&yp, g_y);

    const size_t WSZ = (size_t)ATTN_ * ATTN_;

    rope_table_kernel<<<T_, 64>>>(cosp, sinp);
    const int n4x = BT_ * ATTN_ / 4;
    conv_x_kernel<<<n4x / 256, 256>>>((const float4*)x, (__half2*)xp, n4x);
    const int n4w = ATTN_ * ATTN_ / 4;
    conv_w_kernel<<<dim3(n4w / 256, 1, 4), 256>>>(wq_w, wk_w, wv_w, wo_w,
                                                  (__half2*)wp, n4w);

    cudaFuncSetAttribute(qkv_gemm, cudaFuncAttributeMaxDynamicSharedMemorySize, GSMEM);
    cudaFuncSetAttribute(out_gemm, cudaFuncAttributeMaxDynamicSharedMemorySize, GSMEM);
    cudaFuncSetAttribute(flash_mma, cudaFuncAttributeMaxDynamicSharedMemorySize, FSMEM);

    qkv_gemm<<<dim3(24, BT_ / GBM), GTH, GSMEM>>>(xp, wp,
                                                  wq_b, wk_b, wv_b,
                                                  qp, kp, vp,
                                                  cosp, sinp);
    flash_mma<<<dim3(T_ / 128, H_, B_), 256, FSMEM>>>(qp, kp, vp, yp);

    out_gemm<<<dim3(ATTN_ / GBN, BT_ / GBM), GTH, GSMEM>>>(yp, wp + 3 * WSZ,
                                                           wo_b, out);
}